// round 1
// baseline (speedup 1.0000x reference)
#include <cuda_runtime.h>
#include <cuda_bf16.h>
#include <math_constants.h>

// Problem constants
#define BATCH 512
#define NTOK  343
#define CDIM  192
#define NHEAD 6
#define HD    32
#define NWIN  64
#define NN    (NTOK * NTOK)        // 117649
#define SCALE 0.17677669529663687f // 32^-0.5

// ---------------------------------------------------------------------------
// Scratch (device globals: allocation-free)
// ---------------------------------------------------------------------------
__device__ float g_q[BATCH * NHEAD * NTOK * HD];   // [b][h][n][d], pre-scaled
__device__ float g_k[BATCH * NHEAD * NTOK * HD];
__device__ float g_v[BATCH * NHEAD * NTOK * HD];
__device__ float g_o[BATCH * NTOK * CDIM];         // [b][n][h*32+d]
__device__ float g_bias[NHEAD * NN];               // [h][i][j]

// ---------------------------------------------------------------------------
// Kernel 1: expand relative-position bias table -> [h][i][j]
// ---------------------------------------------------------------------------
__global__ void bias_expand_kernel(const float* __restrict__ bt,
                                   const int* __restrict__ rpi)
{
    int ij = blockIdx.x * blockDim.x + threadIdx.x;
    if (ij >= NN) return;
    int t = rpi[ij];
    #pragma unroll
    for (int h = 0; h < NHEAD; h++)
        g_bias[h * NN + ij] = bt[t * NHEAD + h];
}

// ---------------------------------------------------------------------------
// Kernel 2/4: fp32 GEMM  C[M x Nc] = A[M x 192] * W[192 x Nc] (+bias)
//   MODE 0: A = x, Nc = 576, epilogue scatters into g_q/g_k/g_v (q scaled)
//   MODE 1: A = g_o, Nc = 192, epilogue writes d_out (+proj_b)
// Tiles: BM=128, BN=64, BK=16, 256 threads, 8x4 microtile.
// M = 175616 (divisible by 128); Nc divisible by 64; K=192 divisible by 16.
// ---------------------------------------------------------------------------
template <int MODE>
__global__ void __launch_bounds__(256)
gemm_kernel(const float* __restrict__ Ain,
            const float* __restrict__ W,
            const float* __restrict__ bias,
            float* __restrict__ Cout)
{
    constexpr int NC = (MODE == 0) ? 3 * CDIM : CDIM;
    constexpr int K  = CDIM;                 // 192
    constexpr int AP = 132;                  // padded As row pitch (floats)

    const float* A = (MODE == 0) ? Ain : g_o;

    __shared__ float As[16 * AP];            // As[k][r], r in [0,128)
    __shared__ float Ws[16 * 64];            // Ws[k][c]

    const int tid  = threadIdx.x;
    const int tx   = tid & 15;               // col group (x4)
    const int ty   = tid >> 4;               // row group (x8)
    const int c0   = blockIdx.x * 64;
    const int row0 = blockIdx.y * 128;

    float acc[8][4];
    #pragma unroll
    for (int i = 0; i < 8; i++)
        #pragma unroll
        for (int j = 0; j < 4; j++) acc[i][j] = 0.f;

    for (int k0 = 0; k0 < K; k0 += 16) {
        __syncthreads();
        // stage A transposed: As[k][r]
        #pragma unroll
        for (int f = 0; f < 2; f++) {
            int lin = f * 256 + tid;         // 0..511
            int kq  = lin & 3;
            int r   = lin >> 2;              // 0..127
            float4 a = *(const float4*)(A + (size_t)(row0 + r) * K + k0 + kq * 4);
            As[(kq * 4 + 0) * AP + r] = a.x;
            As[(kq * 4 + 1) * AP + r] = a.y;
            As[(kq * 4 + 2) * AP + r] = a.z;
            As[(kq * 4 + 3) * AP + r] = a.w;
        }
        // stage W: Ws[k][c]
        #pragma unroll
        for (int f = 0; f < 4; f++) {
            int lin = f * 256 + tid;         // 0..1023
            int c = lin & 63;
            int k = lin >> 6;
            Ws[k * 64 + c] = W[(size_t)(k0 + k) * NC + c0 + c];
        }
        __syncthreads();

        #pragma unroll
        for (int kk = 0; kk < 16; kk++) {
            float4 a0 = *(const float4*)&As[kk * AP + ty * 8];
            float4 a1 = *(const float4*)&As[kk * AP + ty * 8 + 4];
            float4 w  = *(const float4*)&Ws[kk * 64 + tx * 4];
            float ar[8] = {a0.x, a0.y, a0.z, a0.w, a1.x, a1.y, a1.z, a1.w};
            float wr[4] = {w.x, w.y, w.z, w.w};
            #pragma unroll
            for (int i = 0; i < 8; i++)
                #pragma unroll
                for (int j = 0; j < 4; j++)
                    acc[i][j] += ar[i] * wr[j];
        }
    }

    const int c = c0 + tx * 4;               // 4 consecutive cols, 16B aligned
    float4 bv;
    bv.x = bias[c + 0]; bv.y = bias[c + 1];
    bv.z = bias[c + 2]; bv.w = bias[c + 3];

    if (MODE == 0) {
        // c -> (s, h, d): c = s*192 + h*32 + d ; 4 cols never cross h boundary
        int s   = c / CDIM;
        int rem = c - s * CDIM;
        int hh  = rem >> 5;
        int dd  = rem & 31;
        float* dst = (s == 0) ? g_q : (s == 1) ? g_k : g_v;
        float sc = (s == 0) ? SCALE : 1.f;
        #pragma unroll
        for (int ii = 0; ii < 8; ii++) {
            int row = row0 + ty * 8 + ii;
            int bb  = row / NTOK;
            int nn  = row - bb * NTOK;
            float4 v;
            v.x = (acc[ii][0] + bv.x) * sc;
            v.y = (acc[ii][1] + bv.y) * sc;
            v.z = (acc[ii][2] + bv.z) * sc;
            v.w = (acc[ii][3] + bv.w) * sc;
            *(float4*)&dst[(size_t)((bb * NHEAD + hh) * NTOK + nn) * HD + dd] = v;
        }
    } else {
        #pragma unroll
        for (int ii = 0; ii < 8; ii++) {
            int row = row0 + ty * 8 + ii;
            float4 v;
            v.x = acc[ii][0] + bv.x;
            v.y = acc[ii][1] + bv.y;
            v.z = acc[ii][2] + bv.z;
            v.w = acc[ii][3] + bv.w;
            *(float4*)&Cout[(size_t)row * CDIM + c] = v;
        }
    }
}

// ---------------------------------------------------------------------------
// Kernel 3: attention. grid (NHEAD, BATCH, 2), 192 threads.
// Each block: one (h, b, row-half). K,V tiles in smem; bias+mask staged
// coalesced per 32-wide j tile; per-thread online softmax (flash style).
// ---------------------------------------------------------------------------
#define ATTN_THREADS 192
#define ROWS_PER_BLK 172
#define BM_PITCH     33
#define ATTN_SMEM_FLOATS (2 * NTOK * HD + ROWS_PER_BLK * BM_PITCH)
#define ATTN_SMEM_BYTES  (ATTN_SMEM_FLOATS * 4)

template <int JW>
__device__ __forceinline__ void attn_tile(const float* __restrict__ ks,
                                          const float* __restrict__ vs,
                                          const float* __restrict__ bmr,
                                          const float4 q4[8], float4 a4[8],
                                          float& mrun, float& lrun, int j0)
{
    float s[JW];
    #pragma unroll
    for (int jj = 0; jj < JW; jj++) {
        const float4* kr = (const float4*)(ks + (j0 + jj) * HD);
        float sum = bmr[jj];
        #pragma unroll
        for (int dd = 0; dd < 8; dd++) {
            float4 kv = kr[dd];
            sum += q4[dd].x * kv.x;
            sum += q4[dd].y * kv.y;
            sum += q4[dd].z * kv.z;
            sum += q4[dd].w * kv.w;
        }
        s[jj] = sum;
    }
    float tm = s[0];
    #pragma unroll
    for (int jj = 1; jj < JW; jj++) tm = fmaxf(tm, s[jj]);
    float mn   = fmaxf(mrun, tm);
    float corr = __expf(mrun - mn);
    lrun *= corr;
    #pragma unroll
    for (int dd = 0; dd < 8; dd++) {
        a4[dd].x *= corr; a4[dd].y *= corr;
        a4[dd].z *= corr; a4[dd].w *= corr;
    }
    float ls = 0.f;
    #pragma unroll
    for (int jj = 0; jj < JW; jj++) {
        float p = __expf(s[jj] - mn);
        ls += p;
        const float4* vr = (const float4*)(vs + (j0 + jj) * HD);
        #pragma unroll
        for (int dd = 0; dd < 8; dd++) {
            float4 vv = vr[dd];
            a4[dd].x += p * vv.x; a4[dd].y += p * vv.y;
            a4[dd].z += p * vv.z; a4[dd].w += p * vv.w;
        }
    }
    lrun += ls;
    mrun = mn;
}

__global__ void __launch_bounds__(ATTN_THREADS, 2)
attn_kernel(const float* __restrict__ mask)
{
    const int h = blockIdx.x;
    const int b = blockIdx.y;
    const int z = blockIdx.z;
    const int tid = threadIdx.x;
    const int w = b & (NWIN - 1);

    extern __shared__ float sm[];
    float* ks = sm;
    float* vs = sm + NTOK * HD;
    float* bm = sm + 2 * NTOK * HD;

    const float* kg = g_k + (size_t)(b * NHEAD + h) * NTOK * HD;
    const float* vg = g_v + (size_t)(b * NHEAD + h) * NTOK * HD;
    for (int t = tid; t < NTOK * HD / 4; t += ATTN_THREADS) {
        ((float4*)ks)[t] = ((const float4*)kg)[t];
        ((float4*)vs)[t] = ((const float4*)vg)[t];
    }

    const int i0   = z * ROWS_PER_BLK;                 // 0 or 172
    const int iend = (z == 0) ? ROWS_PER_BLK : NTOK;   // 172 or 343
    const int i    = i0 + tid;
    const bool act = i < iend;

    float4 q4[8];
    if (act) {
        const float4* qg = (const float4*)(g_q + (size_t)((b * NHEAD + h) * NTOK + i) * HD);
        #pragma unroll
        for (int dd = 0; dd < 8; dd++) q4[dd] = qg[dd];
    }
    float4 a4[8];
    #pragma unroll
    for (int dd = 0; dd < 8; dd++) a4[dd] = make_float4(0.f, 0.f, 0.f, 0.f);
    float mrun = -1e30f, lrun = 0.f;

    const float* brow = g_bias + (size_t)h * NN;
    const float* mrow = mask + (size_t)w * NN;
    const float* bmr  = bm + tid * BM_PITCH;

    for (int jt = 0; jt < 11; jt++) {
        const int j0 = jt * 32;
        __syncthreads();
        // stage bias+mask tile, coalesced (warp = one i-row, 32 consecutive j)
        for (int t = tid; t < ROWS_PER_BLK * 32; t += ATTN_THREADS) {
            int r  = t >> 5;
            int jj = t & 31;
            int ii = i0 + r;
            int j  = j0 + jj;
            if (ii < iend && j < NTOK)
                bm[r * BM_PITCH + jj] = brow[ii * NTOK + j] + mrow[ii * NTOK + j];
        }
        __syncthreads();
        if (!act) continue;
        if (jt < 10) attn_tile<32>(ks, vs, bmr, q4, a4, mrun, lrun, j0);
        else         attn_tile<23>(ks, vs, bmr, q4, a4, mrun, lrun, j0);
    }

    if (act) {
        float inv = 1.f / lrun;
        float4* og = (float4*)(g_o + (size_t)(b * NTOK + i) * CDIM + h * HD);
        #pragma unroll
        for (int dd = 0; dd < 8; dd++) {
            float4 o = a4[dd];
            o.x *= inv; o.y *= inv; o.z *= inv; o.w *= inv;
            og[dd] = o;
        }
    }
}

// ---------------------------------------------------------------------------
// Launch
// ---------------------------------------------------------------------------
extern "C" void kernel_launch(void* const* d_in, const int* in_sizes, int n_in,
                              void* d_out, int out_size)
{
    const float* x      = (const float*)d_in[0];
    const float* mask   = (const float*)d_in[1];
    const float* qkv_w  = (const float*)d_in[2];
    const float* qkv_b  = (const float*)d_in[3];
    const float* proj_w = (const float*)d_in[4];
    const float* proj_b = (const float*)d_in[5];
    const float* bt     = (const float*)d_in[6];
    const int*   rpi    = (const int*)d_in[7];
    float* out = (float*)d_out;

    cudaFuncSetAttribute(attn_kernel,
                         cudaFuncAttributeMaxDynamicSharedMemorySize,
                         ATTN_SMEM_BYTES);

    const int M = BATCH * NTOK;              // 175616

    bias_expand_kernel<<<(NN + 255) / 256, 256>>>(bt, rpi);
    gemm_kernel<0><<<dim3(3 * CDIM / 64, M / 128), 256>>>(x, qkv_w, qkv_b, nullptr);
    attn_kernel<<<dim3(NHEAD, BATCH, 2), ATTN_THREADS, ATTN_SMEM_BYTES>>>(mask);
    gemm_kernel<1><<<dim3(CDIM / 64, M / 128), 256>>>(nullptr, proj_w, proj_b, out);
}

// round 3
// speedup vs baseline: 1.2714x; 1.2714x over previous
#include <cuda_runtime.h>
#include <cuda_bf16.h>
#include <cstdint>

// Problem constants
#define BATCH 512
#define NTOK  343
#define NP    384                  // padded token count (6 * 64)
#define CDIM  192
#define NHEAD 6
#define HD    32
#define NWIN  64
#define NN    (NTOK * NTOK)        // 117649
#define SCALE 0.17677669529663687f // 32^-0.5

// ---------------------------------------------------------------------------
// Scratch (device globals: allocation-free, zero-initialized at module load;
// pad regions of g_vt are never written so they stay zero across replays)
// ---------------------------------------------------------------------------
__device__ float g_q[BATCH * NHEAD * NTOK * HD];   // [b][h][n][d] tf32-rounded, pre-scaled
__device__ float g_k[BATCH * NHEAD * NTOK * HD];   // [b][h][n][d] tf32-rounded
__device__ float g_vt[BATCH * NHEAD * HD * NP];    // [b][h][d][np] tf32-rounded, transposed
__device__ float g_o[BATCH * NTOK * CDIM];         // [b][n][h*32+d]
__device__ float g_bias[NHEAD * NN];               // [h][i][j]

__device__ __forceinline__ float tf32r(float x) {   // round-to-nearest tf32
    uint32_t b;
    asm("cvt.rna.tf32.f32 %0, %1;" : "=r"(b) : "f"(x));
    return __uint_as_float(b);
}
__device__ __forceinline__ uint32_t tf32bits(float x) {
    uint32_t b;
    asm("cvt.rna.tf32.f32 %0, %1;" : "=r"(b) : "f"(x));
    return b;
}

// Warp-level tf32 MMA (baseline PTX, works on plain sm_103 target)
__device__ __forceinline__ void mma_tf32(float c[4], const uint32_t a[4],
                                         uint32_t b0, uint32_t b1) {
    asm volatile(
        "mma.sync.aligned.m16n8k8.row.col.f32.tf32.tf32.f32 "
        "{%0,%1,%2,%3}, {%4,%5,%6,%7}, {%8,%9}, {%0,%1,%2,%3};"
        : "+f"(c[0]), "+f"(c[1]), "+f"(c[2]), "+f"(c[3])
        : "r"(a[0]), "r"(a[1]), "r"(a[2]), "r"(a[3]), "r"(b0), "r"(b1));
}

// ---------------------------------------------------------------------------
// Kernel 1: expand relative-position bias table -> [h][i][j]
// ---------------------------------------------------------------------------
__global__ void bias_expand_kernel(const float* __restrict__ bt,
                                   const int* __restrict__ rpi)
{
    int ij = blockIdx.x * blockDim.x + threadIdx.x;
    if (ij >= NN) return;
    int t = rpi[ij];
    #pragma unroll
    for (int h = 0; h < NHEAD; h++)
        g_bias[h * NN + ij] = bt[t * NHEAD + h];
}

// ---------------------------------------------------------------------------
// Kernel 2/4: fp32 GEMM  C[M x Nc] = A[M x 192] * W[192 x Nc] (+bias)
//   MODE 0: A = x, Nc = 576, epilogue scatters into g_q/g_k/g_vt (tf32-rounded)
//   MODE 1: A = g_o, Nc = 192, epilogue writes d_out (+proj_b)
// ---------------------------------------------------------------------------
template <int MODE>
__global__ void __launch_bounds__(256)
gemm_kernel(const float* __restrict__ Ain,
            const float* __restrict__ W,
            const float* __restrict__ bias,
            float* __restrict__ Cout)
{
    constexpr int NC = (MODE == 0) ? 3 * CDIM : CDIM;
    constexpr int K  = CDIM;
    constexpr int AP = 132;

    const float* A = (MODE == 0) ? Ain : g_o;

    __shared__ float As[16 * AP];
    __shared__ float Ws[16 * 64];

    const int tid  = threadIdx.x;
    const int tx   = tid & 15;
    const int ty   = tid >> 4;
    const int c0   = blockIdx.x * 64;
    const int row0 = blockIdx.y * 128;

    float acc[8][4];
    #pragma unroll
    for (int i = 0; i < 8; i++)
        #pragma unroll
        for (int j = 0; j < 4; j++) acc[i][j] = 0.f;

    for (int k0 = 0; k0 < K; k0 += 16) {
        __syncthreads();
        #pragma unroll
        for (int f = 0; f < 2; f++) {
            int lin = f * 256 + tid;
            int kq  = lin & 3;
            int r   = lin >> 2;
            float4 a = *(const float4*)(A + (size_t)(row0 + r) * K + k0 + kq * 4);
            As[(kq * 4 + 0) * AP + r] = a.x;
            As[(kq * 4 + 1) * AP + r] = a.y;
            As[(kq * 4 + 2) * AP + r] = a.z;
            As[(kq * 4 + 3) * AP + r] = a.w;
        }
        #pragma unroll
        for (int f = 0; f < 4; f++) {
            int lin = f * 256 + tid;
            int c = lin & 63;
            int k = lin >> 6;
            Ws[k * 64 + c] = W[(size_t)(k0 + k) * NC + c0 + c];
        }
        __syncthreads();

        #pragma unroll
        for (int kk = 0; kk < 16; kk++) {
            float4 a0 = *(const float4*)&As[kk * AP + ty * 8];
            float4 a1 = *(const float4*)&As[kk * AP + ty * 8 + 4];
            float4 w  = *(const float4*)&Ws[kk * 64 + tx * 4];
            float ar[8] = {a0.x, a0.y, a0.z, a0.w, a1.x, a1.y, a1.z, a1.w};
            float wr[4] = {w.x, w.y, w.z, w.w};
            #pragma unroll
            for (int i = 0; i < 8; i++)
                #pragma unroll
                for (int j = 0; j < 4; j++)
                    acc[i][j] += ar[i] * wr[j];
        }
    }

    const int c = c0 + tx * 4;
    float4 bv;
    bv.x = bias[c + 0]; bv.y = bias[c + 1];
    bv.z = bias[c + 2]; bv.w = bias[c + 3];

    if (MODE == 0) {
        int s   = c / CDIM;
        int rem = c - s * CDIM;
        int hh  = rem >> 5;
        int dd  = rem & 31;
        if (s == 2) {
            #pragma unroll
            for (int ii = 0; ii < 8; ii++) {
                int row = row0 + ty * 8 + ii;
                int bb  = row / NTOK;
                int nn  = row - bb * NTOK;
                float* vt = g_vt + (size_t)((bb * NHEAD + hh) * HD) * NP;
                vt[(dd + 0) * NP + nn] = tf32r(acc[ii][0] + bv.x);
                vt[(dd + 1) * NP + nn] = tf32r(acc[ii][1] + bv.y);
                vt[(dd + 2) * NP + nn] = tf32r(acc[ii][2] + bv.z);
                vt[(dd + 3) * NP + nn] = tf32r(acc[ii][3] + bv.w);
            }
        } else {
            float* dst = (s == 0) ? g_q : g_k;
            float sc = (s == 0) ? SCALE : 1.f;
            #pragma unroll
            for (int ii = 0; ii < 8; ii++) {
                int row = row0 + ty * 8 + ii;
                int bb  = row / NTOK;
                int nn  = row - bb * NTOK;
                float4 v;
                v.x = tf32r((acc[ii][0] + bv.x) * sc);
                v.y = tf32r((acc[ii][1] + bv.y) * sc);
                v.z = tf32r((acc[ii][2] + bv.z) * sc);
                v.w = tf32r((acc[ii][3] + bv.w) * sc);
                *(float4*)&dst[(size_t)((bb * NHEAD + hh) * NTOK + nn) * HD + dd] = v;
            }
        }
    } else {
        #pragma unroll
        for (int ii = 0; ii < 8; ii++) {
            int row = row0 + ty * 8 + ii;
            float4 v;
            v.x = acc[ii][0] + bv.x;
            v.y = acc[ii][1] + bv.y;
            v.z = acc[ii][2] + bv.z;
            v.w = acc[ii][3] + bv.w;
            *(float4*)&Cout[(size_t)row * CDIM + c] = v;
        }
    }
}

// ---------------------------------------------------------------------------
// Kernel 3: warp-mma tf32 attention.
// Grid (NHEAD, BATCH, 3 m-tiles of 128). 256 threads = 8 warps, each warp m16.
// Per 64-wide j-chunk: stage K[64x32](p36), VT[32x64](p68), bias+mask[128x64]
// (p68) in smem; S via mma into C-frags; softmax on frags (no max subtract);
// P -> warp-private smem (p68) -> A-frags; PV mma accumulates O frags.
// ---------------------------------------------------------------------------
#define KS_PITCH 36
#define VS_PITCH 68
#define BM_PITCH 68
#define P_PITCH  68
#define OFF_KS 0
#define OFF_VS (OFF_KS + 64 * KS_PITCH)          // 2304
#define OFF_BM (OFF_VS + 32 * VS_PITCH)          // 4480
#define OFF_P  (OFF_BM + 128 * BM_PITCH)         // 13184
#define ATTN_SMEM_FLOATS (OFF_P + 128 * P_PITCH) // 21888
#define ATTN_SMEM_BYTES  (ATTN_SMEM_FLOATS * 4)  // 87552

__global__ void __launch_bounds__(256)
attn_mma_kernel(const float* __restrict__ mask)
{
    const int h   = blockIdx.x;
    const int b   = blockIdx.y;
    const int mt  = blockIdx.z;
    const int wmk = b & (NWIN - 1);
    const int tid = threadIdx.x;
    const int w   = tid >> 5;
    const int lane = tid & 31;
    const int lq  = lane >> 2;     // 0..7
    const int lr  = lane & 3;      // 0..3

    extern __shared__ float sm[];
    float* Ks = sm + OFF_KS;
    float* Vs = sm + OFF_VS;
    float* BM = sm + OFF_BM;
    float* Pw = sm + OFF_P + w * 16 * P_PITCH;   // warp-private 16-row P tile

    const int i0 = mt * 128;
    const int m0 = i0 + w * 16;
    const size_t bh = (size_t)(b * NHEAD + h);

    // --- stage Q tile [128 x 32] into BM area (aliased; pitch 36), load frags
    const float4* qg = (const float4*)(g_q + bh * NTOK * HD);
    for (int idx = tid; idx < 128 * 8; idx += 256) {
        int r = idx >> 3, dq = idx & 7;
        int i = i0 + r;
        float4 v = (i < NTOK) ? qg[i * 8 + dq] : make_float4(0.f, 0.f, 0.f, 0.f);
        *(float4*)&BM[r * KS_PITCH + dq * 4] = v;
    }
    __syncthreads();
    uint32_t qf[4][4];
    {
        const int r0 = w * 16 + lq;
        #pragma unroll
        for (int ks = 0; ks < 4; ks++) {
            int c = ks * 8 + lr;
            qf[ks][0] = __float_as_uint(BM[r0 * KS_PITCH + c]);
            qf[ks][1] = __float_as_uint(BM[(r0 + 8) * KS_PITCH + c]);
            qf[ks][2] = __float_as_uint(BM[r0 * KS_PITCH + c + 4]);
            qf[ks][3] = __float_as_uint(BM[(r0 + 8) * KS_PITCH + c + 4]);
        }
    }
    __syncthreads();

    float o[4][4];
    #pragma unroll
    for (int nt = 0; nt < 4; nt++)
        #pragma unroll
        for (int r = 0; r < 4; r++) o[nt][r] = 0.f;
    float lsum0 = 0.f, lsum1 = 0.f;

    const float4* kg = (const float4*)(g_k + bh * NTOK * HD);
    const float*  vg = g_vt + bh * HD * NP;
    const float*  brow = g_bias + (size_t)h * NN;
    const float*  mrow = mask + (size_t)wmk * NN;

    for (int jc = 0; jc < 6; jc++) {
        const int j0 = jc * 64;
        __syncthreads();
        // stage K chunk [64 j x 32 d], pitch 36
        for (int idx = tid; idx < 64 * 8; idx += 256) {
            int jl = idx >> 3, dq = idx & 7;
            int j = j0 + jl;
            float4 v = (j < NTOK) ? kg[j * 8 + dq] : make_float4(0.f, 0.f, 0.f, 0.f);
            *(float4*)&Ks[jl * KS_PITCH + dq * 4] = v;
        }
        // stage VT chunk [32 d x 64 j], pitch 68 (pad cols are zero in g_vt)
        for (int idx = tid; idx < 32 * 16; idx += 256) {
            int d = idx >> 4, jq = idx & 15;
            float4 v = *(const float4*)(vg + (size_t)d * NP + j0 + jq * 4);
            *(float4*)&Vs[d * VS_PITCH + jq * 4] = v;
        }
        // stage combined bias+mask [128 i x 64 j], pitch 68
        for (int idx = tid; idx < 128 * 64; idx += 256) {
            int r = idx >> 6, c = idx & 63;
            int i = i0 + r, j = j0 + c;
            float v = 0.f;
            if (i < NTOK && j < NTOK)
                v = brow[(size_t)i * NTOK + j] + mrow[(size_t)i * NTOK + j];
            BM[r * BM_PITCH + c] = v;
        }
        __syncthreads();

        // S = Q * K^T for this warp's m16 x 64 chunk
        float s[8][4];
        #pragma unroll
        for (int nt = 0; nt < 8; nt++) {
            #pragma unroll
            for (int r = 0; r < 4; r++) s[nt][r] = 0.f;
            #pragma unroll
            for (int ks = 0; ks < 4; ks++) {
                int kc = ks * 8 + lr;
                uint32_t b0 = __float_as_uint(Ks[(nt * 8 + lq) * KS_PITCH + kc]);
                uint32_t b1 = __float_as_uint(Ks[(nt * 8 + lq) * KS_PITCH + kc + 4]);
                mma_tf32(s[nt], qf[ks], b0, b1);
            }
        }

        // softmax on fragments; write P (tf32) to warp-private smem
        const int rbm0 = w * 16 + lq;
        #pragma unroll
        for (int nt = 0; nt < 8; nt++) {
            int cl = nt * 8 + 2 * lr;          // chunk-local col
            int jgl = j0 + cl;                 // global col
            float2 bm0 = *(const float2*)&BM[rbm0 * BM_PITCH + cl];
            float2 bm1 = *(const float2*)&BM[(rbm0 + 8) * BM_PITCH + cl];
            bool v0 = jgl < NTOK, v1 = (jgl + 1) < NTOK;
            float p00 = v0 ? __expf(s[nt][0] + bm0.x) : 0.f;
            float p01 = v1 ? __expf(s[nt][1] + bm0.y) : 0.f;
            float p10 = v0 ? __expf(s[nt][2] + bm1.x) : 0.f;
            float p11 = v1 ? __expf(s[nt][3] + bm1.y) : 0.f;
            lsum0 += p00 + p01;
            lsum1 += p10 + p11;
            float2 w0, w1;
            w0.x = __uint_as_float(tf32bits(p00));
            w0.y = __uint_as_float(tf32bits(p01));
            w1.x = __uint_as_float(tf32bits(p10));
            w1.y = __uint_as_float(tf32bits(p11));
            *(float2*)&Pw[lq * P_PITCH + cl] = w0;
            *(float2*)&Pw[(lq + 8) * P_PITCH + cl] = w1;
        }
        __syncwarp();

        // O += P * V  (A = P frags from smem, B = VT frags from smem)
        #pragma unroll
        for (int ks = 0; ks < 8; ks++) {
            int kc = ks * 8 + lr;
            uint32_t a[4];
            a[0] = __float_as_uint(Pw[lq * P_PITCH + kc]);
            a[1] = __float_as_uint(Pw[(lq + 8) * P_PITCH + kc]);
            a[2] = __float_as_uint(Pw[lq * P_PITCH + kc + 4]);
            a[3] = __float_as_uint(Pw[(lq + 8) * P_PITCH + kc + 4]);
            #pragma unroll
            for (int nt = 0; nt < 4; nt++) {
                uint32_t b0 = __float_as_uint(Vs[(nt * 8 + lq) * VS_PITCH + kc]);
                uint32_t b1 = __float_as_uint(Vs[(nt * 8 + lq) * VS_PITCH + kc + 4]);
                mma_tf32(o[nt], a, b0, b1);
            }
        }
        __syncwarp();
    }

    // reduce row sums across the 4 lanes of each row group
    lsum0 += __shfl_xor_sync(0xffffffffu, lsum0, 1);
    lsum0 += __shfl_xor_sync(0xffffffffu, lsum0, 2);
    lsum1 += __shfl_xor_sync(0xffffffffu, lsum1, 1);
    lsum1 += __shfl_xor_sync(0xffffffffu, lsum1, 2);
    float inv0 = 1.f / lsum0;
    float inv1 = 1.f / lsum1;

    const int ir0 = m0 + lq;
    const int ir1 = ir0 + 8;
    if (ir0 < NTOK) {
        float* base = g_o + ((size_t)b * NTOK + ir0) * CDIM + h * HD;
        #pragma unroll
        for (int nt = 0; nt < 4; nt++) {
            float2 v; v.x = o[nt][0] * inv0; v.y = o[nt][1] * inv0;
            *(float2*)(base + nt * 8 + 2 * lr) = v;
        }
    }
    if (ir1 < NTOK) {
        float* base = g_o + ((size_t)b * NTOK + ir1) * CDIM + h * HD;
        #pragma unroll
        for (int nt = 0; nt < 4; nt++) {
            float2 v; v.x = o[nt][2] * inv1; v.y = o[nt][3] * inv1;
            *(float2*)(base + nt * 8 + 2 * lr) = v;
        }
    }
}

// ---------------------------------------------------------------------------
// Launch
// ---------------------------------------------------------------------------
extern "C" void kernel_launch(void* const* d_in, const int* in_sizes, int n_in,
                              void* d_out, int out_size)
{
    const float* x      = (const float*)d_in[0];
    const float* mask   = (const float*)d_in[1];
    const float* qkv_w  = (const float*)d_in[2];
    const float* qkv_b  = (const float*)d_in[3];
    const float* proj_w = (const float*)d_in[4];
    const float* proj_b = (const float*)d_in[5];
    const float* bt     = (const float*)d_in[6];
    const int*   rpi    = (const int*)d_in[7];
    float* out = (float*)d_out;

    cudaFuncSetAttribute(attn_mma_kernel,
                         cudaFuncAttributeMaxDynamicSharedMemorySize,
                         ATTN_SMEM_BYTES);

    const int M = BATCH * NTOK;              // 175616

    bias_expand_kernel<<<(NN + 255) / 256, 256>>>(bt, rpi);
    gemm_kernel<0><<<dim3(3 * CDIM / 64, M / 128), 256>>>(x, qkv_w, qkv_b, nullptr);
    attn_mma_kernel<<<dim3(NHEAD, BATCH, 3), 256, ATTN_SMEM_BYTES>>>(mask);
    gemm_kernel<1><<<dim3(CDIM / 64, M / 128), 256>>>(nullptr, proj_w, proj_b, out);
}

// round 4
// speedup vs baseline: 1.6878x; 1.3275x over previous
#include <cuda_runtime.h>
#include <cuda_bf16.h>
#include <cstdint>

// Problem constants
#define BATCH 512
#define NTOK  343
#define NP    384                  // padded token count (6 * 64)
#define CDIM  192
#define NHEAD 6
#define HD    32
#define NWIN  64
#define NN    (NTOK * NTOK)        // 117649
#define SCALE 0.17677669529663687f // 32^-0.5

// ---------------------------------------------------------------------------
// Scratch (device globals: allocation-free, zero-init; g_vt pads stay zero)
// ---------------------------------------------------------------------------
__device__ float g_q[BATCH * NHEAD * NTOK * HD];   // [b][h][n][d] tf32-rounded, pre-scaled
__device__ float g_k[BATCH * NHEAD * NTOK * HD];   // [b][h][n][d] tf32-rounded
__device__ float g_vt[BATCH * NHEAD * HD * NP];    // [b][h][d][np] tf32-rounded, transposed
__device__ float g_o[BATCH * NTOK * CDIM];         // [b][n][h*32+d]
__device__ float g_bm[NWIN * NHEAD * NN];          // [w][h][i][j] bias+mask combined

__device__ __forceinline__ float tf32r(float x) {   // round-to-nearest tf32
    uint32_t b;
    asm("cvt.rna.tf32.f32 %0, %1;" : "=r"(b) : "f"(x));
    return __uint_as_float(b);
}
__device__ __forceinline__ uint32_t tf32bits(float x) {
    uint32_t b;
    asm("cvt.rna.tf32.f32 %0, %1;" : "=r"(b) : "f"(x));
    return b;
}

// Warp-level tf32 MMA (baseline PTX, works on plain sm_103 target)
// Validated fragment layout (R3):
//  A(row):  a0=(m=lq,k=lr) a1=(m=lq+8,k=lr) a2=(m=lq,k=lr+4) a3=(m=lq+8,k=lr+4)
//  B(col):  b0=(n=lq,k=lr) b1=(n=lq,k=lr+4)
//  C:       c0=(m=lq,n=2lr) c1=(m=lq,n=2lr+1) c2=(m=lq+8,n=2lr) c3=(m=lq+8,n=2lr+1)
__device__ __forceinline__ void mma_tf32(float c[4], const uint32_t a[4],
                                         uint32_t b0, uint32_t b1) {
    asm volatile(
        "mma.sync.aligned.m16n8k8.row.col.f32.tf32.tf32.f32 "
        "{%0,%1,%2,%3}, {%4,%5,%6,%7}, {%8,%9}, {%0,%1,%2,%3};"
        : "+f"(c[0]), "+f"(c[1]), "+f"(c[2]), "+f"(c[3])
        : "r"(a[0]), "r"(a[1]), "r"(a[2]), "r"(a[3]), "r"(b0), "r"(b1));
}

// ---------------------------------------------------------------------------
// Kernel 1: combine bias table gather + per-window mask -> g_bm[w][h][i][j]
// ---------------------------------------------------------------------------
__global__ void bm_combine_kernel(const float* __restrict__ mask,
                                  const float* __restrict__ bt,
                                  const int* __restrict__ rpi)
{
    int ij = blockIdx.x * blockDim.x + threadIdx.x;
    if (ij >= NN) return;
    int w = blockIdx.y;
    int h = blockIdx.z;
    float v = bt[rpi[ij] * NHEAD + h] + mask[(size_t)w * NN + ij];
    g_bm[((size_t)(w * NHEAD + h)) * NN + ij] = v;
}

// ---------------------------------------------------------------------------
// Kernel 2/4: tf32 mma GEMM  C[M x NC] = A[M x 192] * W[192 x NC] (+bias)
//   MODE 0: A = x, NC = 576, epilogue scatters into g_q/g_k/g_vt (tf32-rounded)
//   MODE 1: A = g_o, NC = 192, epilogue writes d_out (+proj_b)
// CTA tile 256x64, 8 warps (4m x 2n), warp tile 64x32 (4 m16 x 4 n8), K step 16.
// As[r][k] pitch 20 (frag LDS conflict-free); Ws[k][c] pitch 72 (conflict-free).
// ---------------------------------------------------------------------------
#define AS_P 20
#define WS_P 72

template <int MODE>
__global__ void __launch_bounds__(256)
gemm_tc_kernel(const float* __restrict__ Ain,
               const float* __restrict__ W,
               const float* __restrict__ bias,
               float* __restrict__ Cout)
{
    constexpr int NC = (MODE == 0) ? 3 * CDIM : CDIM;
    const float* A = (MODE == 0) ? Ain : g_o;

    __shared__ float As[256 * AS_P];
    __shared__ float Ws[16 * WS_P];

    const int tid  = threadIdx.x;
    const int w    = tid >> 5;
    const int lane = tid & 31;
    const int lq   = lane >> 2;
    const int lr   = lane & 3;
    const int wm   = w >> 1;           // 0..3 (m)
    const int wn   = w & 1;            // 0..1 (n)
    const int row0 = blockIdx.y * 256;
    const int c0   = blockIdx.x * 64;

    float acc[4][4][4];
    #pragma unroll
    for (int mi = 0; mi < 4; mi++)
        #pragma unroll
        for (int ni = 0; ni < 4; ni++)
            #pragma unroll
            for (int r = 0; r < 4; r++) acc[mi][ni][r] = 0.f;

    for (int k0 = 0; k0 < CDIM; k0 += 16) {
        __syncthreads();
        // stage A: 256 rows x 16 k, tf32-rounded
        #pragma unroll
        for (int f = 0; f < 4; f++) {
            int idx = f * 256 + tid;           // 0..1023
            int r   = idx >> 2;
            int kq  = idx & 3;
            float4 a = *(const float4*)(A + (size_t)(row0 + r) * CDIM + k0 + kq * 4);
            a.x = tf32r(a.x); a.y = tf32r(a.y); a.z = tf32r(a.z); a.w = tf32r(a.w);
            *(float4*)&As[r * AS_P + kq * 4] = a;
        }
        // stage W: 16 k x 64 c, tf32-rounded
        {
            int idx = tid;                     // 0..255 = 16*64/4
            int c4  = idx & 15;
            int k   = idx >> 4;
            float4 wv = *(const float4*)(W + (size_t)(k0 + k) * NC + c0 + c4 * 4);
            wv.x = tf32r(wv.x); wv.y = tf32r(wv.y); wv.z = tf32r(wv.z); wv.w = tf32r(wv.w);
            *(float4*)&Ws[k * WS_P + c4 * 4] = wv;
        }
        __syncthreads();

        #pragma unroll
        for (int ks = 0; ks < 2; ks++) {
            uint32_t bf[4][2];
            #pragma unroll
            for (int ni = 0; ni < 4; ni++) {
                int cc = wn * 32 + ni * 8 + lq;
                bf[ni][0] = __float_as_uint(Ws[(ks * 8 + lr) * WS_P + cc]);
                bf[ni][1] = __float_as_uint(Ws[(ks * 8 + lr + 4) * WS_P + cc]);
            }
            #pragma unroll
            for (int mi = 0; mi < 4; mi++) {
                int r0 = wm * 64 + mi * 16 + lq;
                uint32_t af[4];
                af[0] = __float_as_uint(As[r0 * AS_P + ks * 8 + lr]);
                af[1] = __float_as_uint(As[(r0 + 8) * AS_P + ks * 8 + lr]);
                af[2] = __float_as_uint(As[r0 * AS_P + ks * 8 + lr + 4]);
                af[3] = __float_as_uint(As[(r0 + 8) * AS_P + ks * 8 + lr + 4]);
                #pragma unroll
                for (int ni = 0; ni < 4; ni++)
                    mma_tf32(acc[mi][ni], af, bf[ni][0], bf[ni][1]);
            }
        }
    }

    // epilogue
    #pragma unroll
    for (int mi = 0; mi < 4; mi++) {
        int rlo = row0 + wm * 64 + mi * 16 + lq;
        int rhi = rlo + 8;
        int blo = rlo / NTOK, nlo = rlo - blo * NTOK;
        int bhi = rhi / NTOK, nhi = rhi - bhi * NTOK;
        #pragma unroll
        for (int ni = 0; ni < 4; ni++) {
            int c = c0 + wn * 32 + ni * 8 + 2 * lr;
            float b0 = bias[c], b1 = bias[c + 1];
            if (MODE == 0) {
                int s   = c / CDIM;
                int rem = c - s * CDIM;
                int hh  = rem >> 5;
                int dd  = rem & 31;
                if (s == 2) {
                    float* vlo = g_vt + (size_t)(blo * NHEAD + hh) * HD * NP;
                    float* vhi = g_vt + (size_t)(bhi * NHEAD + hh) * HD * NP;
                    vlo[(size_t)dd * NP + nlo]       = tf32r(acc[mi][ni][0] + b0);
                    vlo[(size_t)(dd + 1) * NP + nlo] = tf32r(acc[mi][ni][1] + b1);
                    vhi[(size_t)dd * NP + nhi]       = tf32r(acc[mi][ni][2] + b0);
                    vhi[(size_t)(dd + 1) * NP + nhi] = tf32r(acc[mi][ni][3] + b1);
                } else {
                    float sc = (s == 0) ? SCALE : 1.f;
                    float* dst = (s == 0) ? g_q : g_k;
                    float2 vl, vh;
                    vl.x = tf32r((acc[mi][ni][0] + b0) * sc);
                    vl.y = tf32r((acc[mi][ni][1] + b1) * sc);
                    vh.x = tf32r((acc[mi][ni][2] + b0) * sc);
                    vh.y = tf32r((acc[mi][ni][3] + b1) * sc);
                    *(float2*)&dst[((size_t)(blo * NHEAD + hh) * NTOK + nlo) * HD + dd] = vl;
                    *(float2*)&dst[((size_t)(bhi * NHEAD + hh) * NTOK + nhi) * HD + dd] = vh;
                }
            } else {
                float2 vl, vh;
                vl.x = acc[mi][ni][0] + b0; vl.y = acc[mi][ni][1] + b1;
                vh.x = acc[mi][ni][2] + b0; vh.y = acc[mi][ni][3] + b1;
                *(float2*)&Cout[(size_t)rlo * CDIM + c] = vl;
                *(float2*)&Cout[(size_t)rhi * CDIM + c] = vh;
            }
        }
    }
}

// ---------------------------------------------------------------------------
// Kernel 3: warp-mma tf32 attention, 2 batches per CTA sharing the BM tile.
// Grid (NHEAD, NWIN, 12): z = mt*4 + bg; b = w + 64*(2bg + sb), sb in {0,1}.
// 256 threads = 8 warps, each warp m16. Per 64-wide j-chunk: stage BM once
// (from precombined g_bm), then per sb: stage K/V, S-mma, softmax, P->smem,
// PV-mma.
// ---------------------------------------------------------------------------
#define KS_PITCH 36
#define VS_PITCH 68
#define BM_PITCH 68
#define P_PITCH  68
#define OFF_KS 0
#define OFF_VS (OFF_KS + 64 * KS_PITCH)          // 2304
#define OFF_BM (OFF_VS + 32 * VS_PITCH)          // 4480
#define OFF_P  (OFF_BM + 128 * BM_PITCH)         // 13184
#define ATTN_SMEM_FLOATS (OFF_P + 128 * P_PITCH) // 21888
#define ATTN_SMEM_BYTES  (ATTN_SMEM_FLOATS * 4)  // 87552

__global__ void __launch_bounds__(256)
attn_mma_kernel()
{
    const int h   = blockIdx.x;
    const int wi  = blockIdx.y;        // window
    const int z   = blockIdx.z;
    const int mt  = z >> 2;
    const int bg  = z & 3;
    const int tid = threadIdx.x;
    const int w   = tid >> 5;
    const int lane = tid & 31;
    const int lq  = lane >> 2;
    const int lr  = lane & 3;

    int bb[2];
    bb[0] = wi + NWIN * (2 * bg);
    bb[1] = wi + NWIN * (2 * bg + 1);

    extern __shared__ float sm[];
    float* Ks = sm + OFF_KS;
    float* Vs = sm + OFF_VS;
    float* BM = sm + OFF_BM;
    float* Pw = sm + OFF_P + w * 16 * P_PITCH;

    const int i0 = mt * 128;
    const int m0 = i0 + w * 16;
    const float* bmg = g_bm + (size_t)(wi * NHEAD + h) * NN;

    // --- load Q fragments for both batches (stage via BM area, pitch 36)
    uint32_t qf[2][4][4];
    #pragma unroll
    for (int sb = 0; sb < 2; sb++) {
        const float4* qg = (const float4*)(g_q + (size_t)(bb[sb] * NHEAD + h) * NTOK * HD);
        __syncthreads();
        for (int idx = tid; idx < 128 * 8; idx += 256) {
            int r = idx >> 3, dq = idx & 7;
            int i = i0 + r;
            float4 v = (i < NTOK) ? qg[i * 8 + dq] : make_float4(0.f, 0.f, 0.f, 0.f);
            *(float4*)&BM[r * KS_PITCH + dq * 4] = v;
        }
        __syncthreads();
        const int r0 = w * 16 + lq;
        #pragma unroll
        for (int ks = 0; ks < 4; ks++) {
            int c = ks * 8 + lr;
            qf[sb][ks][0] = __float_as_uint(BM[r0 * KS_PITCH + c]);
            qf[sb][ks][1] = __float_as_uint(BM[(r0 + 8) * KS_PITCH + c]);
            qf[sb][ks][2] = __float_as_uint(BM[r0 * KS_PITCH + c + 4]);
            qf[sb][ks][3] = __float_as_uint(BM[(r0 + 8) * KS_PITCH + c + 4]);
        }
    }

    float o[2][4][4];
    #pragma unroll
    for (int sb = 0; sb < 2; sb++)
        #pragma unroll
        for (int nt = 0; nt < 4; nt++)
            #pragma unroll
            for (int r = 0; r < 4; r++) o[sb][nt][r] = 0.f;
    float lsum[2][2] = {{0.f, 0.f}, {0.f, 0.f}};

    for (int jc = 0; jc < 6; jc++) {
        const int j0 = jc * 64;
        #pragma unroll
        for (int sb = 0; sb < 2; sb++) {
            __syncthreads();
            if (sb == 0) {
                // stage combined bias+mask [128 i x 64 j], pitch 68
                for (int idx = tid; idx < 128 * 64; idx += 256) {
                    int r = idx >> 6, cc = idx & 63;
                    int i = i0 + r, j = j0 + cc;
                    BM[r * BM_PITCH + cc] =
                        (i < NTOK && j < NTOK) ? bmg[(size_t)i * NTOK + j] : 0.f;
                }
            }
            // stage K chunk [64 j x 32 d], pitch 36
            const float4* kg = (const float4*)(g_k + (size_t)(bb[sb] * NHEAD + h) * NTOK * HD);
            for (int idx = tid; idx < 64 * 8; idx += 256) {
                int jl = idx >> 3, dq = idx & 7;
                int j = j0 + jl;
                float4 v = (j < NTOK) ? kg[j * 8 + dq] : make_float4(0.f, 0.f, 0.f, 0.f);
                *(float4*)&Ks[jl * KS_PITCH + dq * 4] = v;
            }
            // stage VT chunk [32 d x 64 j], pitch 68 (pad cols zero in g_vt)
            const float* vg = g_vt + (size_t)(bb[sb] * NHEAD + h) * HD * NP;
            for (int idx = tid; idx < 32 * 16; idx += 256) {
                int d = idx >> 4, jq = idx & 15;
                float4 v = *(const float4*)(vg + (size_t)d * NP + j0 + jq * 4);
                *(float4*)&Vs[d * VS_PITCH + jq * 4] = v;
            }
            __syncthreads();

            // S = Q * K^T for this warp's m16 x 64 chunk
            float s[8][4];
            #pragma unroll
            for (int nt = 0; nt < 8; nt++) {
                #pragma unroll
                for (int r = 0; r < 4; r++) s[nt][r] = 0.f;
                #pragma unroll
                for (int ks = 0; ks < 4; ks++) {
                    int kc = ks * 8 + lr;
                    uint32_t b0 = __float_as_uint(Ks[(nt * 8 + lq) * KS_PITCH + kc]);
                    uint32_t b1 = __float_as_uint(Ks[(nt * 8 + lq) * KS_PITCH + kc + 4]);
                    mma_tf32(s[nt], qf[sb][ks], b0, b1);
                }
            }

            // softmax on fragments; write P (tf32) to warp-private smem
            const int rbm0 = w * 16 + lq;
            #pragma unroll
            for (int nt = 0; nt < 8; nt++) {
                int cl = nt * 8 + 2 * lr;
                int jgl = j0 + cl;
                float2 bm0 = *(const float2*)&BM[rbm0 * BM_PITCH + cl];
                float2 bm1 = *(const float2*)&BM[(rbm0 + 8) * BM_PITCH + cl];
                bool v0 = jgl < NTOK, v1 = (jgl + 1) < NTOK;
                float p00 = v0 ? __expf(s[nt][0] + bm0.x) : 0.f;
                float p01 = v1 ? __expf(s[nt][1] + bm0.y) : 0.f;
                float p10 = v0 ? __expf(s[nt][2] + bm1.x) : 0.f;
                float p11 = v1 ? __expf(s[nt][3] + bm1.y) : 0.f;
                lsum[sb][0] += p00 + p01;
                lsum[sb][1] += p10 + p11;
                float2 w0, w1;
                w0.x = __uint_as_float(tf32bits(p00));
                w0.y = __uint_as_float(tf32bits(p01));
                w1.x = __uint_as_float(tf32bits(p10));
                w1.y = __uint_as_float(tf32bits(p11));
                *(float2*)&Pw[lq * P_PITCH + cl] = w0;
                *(float2*)&Pw[(lq + 8) * P_PITCH + cl] = w1;
            }
            __syncwarp();

            // O += P * V
            #pragma unroll
            for (int ks = 0; ks < 8; ks++) {
                int kc = ks * 8 + lr;
                uint32_t a[4];
                a[0] = __float_as_uint(Pw[lq * P_PITCH + kc]);
                a[1] = __float_as_uint(Pw[(lq + 8) * P_PITCH + kc]);
                a[2] = __float_as_uint(Pw[lq * P_PITCH + kc + 4]);
                a[3] = __float_as_uint(Pw[(lq + 8) * P_PITCH + kc + 4]);
                #pragma unroll
                for (int nt = 0; nt < 4; nt++) {
                    uint32_t b0 = __float_as_uint(Vs[(nt * 8 + lq) * VS_PITCH + kc]);
                    uint32_t b1 = __float_as_uint(Vs[(nt * 8 + lq) * VS_PITCH + kc + 4]);
                    mma_tf32(o[sb][nt], a, b0, b1);
                }
            }
            __syncwarp();
        }
    }

    // epilogue: reduce row sums, normalize, store (both batches)
    #pragma unroll
    for (int sb = 0; sb < 2; sb++) {
        float l0 = lsum[sb][0], l1 = lsum[sb][1];
        l0 += __shfl_xor_sync(0xffffffffu, l0, 1);
        l0 += __shfl_xor_sync(0xffffffffu, l0, 2);
        l1 += __shfl_xor_sync(0xffffffffu, l1, 1);
        l1 += __shfl_xor_sync(0xffffffffu, l1, 2);
        float inv0 = 1.f / l0;
        float inv1 = 1.f / l1;

        const int ir0 = m0 + lq;
        const int ir1 = ir0 + 8;
        if (ir0 < NTOK) {
            float* base = g_o + ((size_t)bb[sb] * NTOK + ir0) * CDIM + h * HD;
            #pragma unroll
            for (int nt = 0; nt < 4; nt++) {
                float2 v; v.x = o[sb][nt][0] * inv0; v.y = o[sb][nt][1] * inv0;
                *(float2*)(base + nt * 8 + 2 * lr) = v;
            }
        }
        if (ir1 < NTOK) {
            float* base = g_o + ((size_t)bb[sb] * NTOK + ir1) * CDIM + h * HD;
            #pragma unroll
            for (int nt = 0; nt < 4; nt++) {
                float2 v; v.x = o[sb][nt][2] * inv1; v.y = o[sb][nt][3] * inv1;
                *(float2*)(base + nt * 8 + 2 * lr) = v;
            }
        }
    }
}

// ---------------------------------------------------------------------------
// Launch
// ---------------------------------------------------------------------------
extern "C" void kernel_launch(void* const* d_in, const int* in_sizes, int n_in,
                              void* d_out, int out_size)
{
    const float* x      = (const float*)d_in[0];
    const float* mask   = (const float*)d_in[1];
    const float* qkv_w  = (const float*)d_in[2];
    const float* qkv_b  = (const float*)d_in[3];
    const float* proj_w = (const float*)d_in[4];
    const float* proj_b = (const float*)d_in[5];
    const float* bt     = (const float*)d_in[6];
    const int*   rpi    = (const int*)d_in[7];
    float* out = (float*)d_out;

    cudaFuncSetAttribute(attn_mma_kernel,
                         cudaFuncAttributeMaxDynamicSharedMemorySize,
                         ATTN_SMEM_BYTES);

    bm_combine_kernel<<<dim3((NN + 255) / 256, NWIN, NHEAD), 256>>>(mask, bt, rpi);
    gemm_tc_kernel<0><<<dim3(9, 686), 256>>>(x, qkv_w, qkv_b, nullptr);
    attn_mma_kernel<<<dim3(NHEAD, NWIN, 12), 256, ATTN_SMEM_BYTES>>>();
    gemm_tc_kernel<1><<<dim3(3, 686), 256>>>(nullptr, proj_w, proj_b, out);
}

// round 6
// speedup vs baseline: 1.7507x; 1.0373x over previous
#include <cuda_runtime.h>
#include <cuda_bf16.h>
#include <cstdint>

// Problem constants
#define BATCH 512
#define NTOK  343
#define NP    384                  // padded token count (6 * 64)
#define CDIM  192
#define NHEAD 6
#define HD    32
#define NWIN  64
#define NN    (NTOK * NTOK)        // 117649
#define BMP   384                  // padded g_bm row pitch (floats)
#define SCALE 0.17677669529663687f // 32^-0.5

// ---------------------------------------------------------------------------
// Scratch (device globals: allocation-free, zero-init; pads stay zero)
// ---------------------------------------------------------------------------
__device__ float g_q[BATCH * NHEAD * NTOK * HD];   // [b][h][n][d] tf32-rounded, pre-scaled
__device__ float g_k[BATCH * NHEAD * NTOK * HD];   // [b][h][n][d] tf32-rounded
__device__ float g_vt[BATCH * NHEAD * HD * NP];    // [b][h][d][np] tf32-rounded, transposed
__device__ float g_o[BATCH * NTOK * CDIM];         // [b][n][h*32+d]
__device__ float g_bm[NWIN * NHEAD * NP * BMP];    // [w][h][i][j] bias+mask, padded

__device__ __forceinline__ float tf32r(float x) {
    uint32_t b;
    asm("cvt.rna.tf32.f32 %0, %1;" : "=r"(b) : "f"(x));
    return __uint_as_float(b);
}
__device__ __forceinline__ uint32_t tf32bits(float x) {
    uint32_t b;
    asm("cvt.rna.tf32.f32 %0, %1;" : "=r"(b) : "f"(x));
    return b;
}

// Warp-level tf32 MMA. Fragment layout (validated R3/R4):
//  A(row):  a0=(m=lq,k=lr) a1=(m=lq+8,k=lr) a2=(m=lq,k=lr+4) a3=(m=lq+8,k=lr+4)
//  B(col):  b0=(n=lq,k=lr) b1=(n=lq,k=lr+4)
//  C:       c0=(m=lq,n=2lr) c1=(m=lq,n=2lr+1) c2=(m=lq+8,n=2lr) c3=(m=lq+8,n=2lr+1)
__device__ __forceinline__ void mma_tf32(float c[4], const uint32_t a[4],
                                         uint32_t b0, uint32_t b1) {
    asm volatile(
        "mma.sync.aligned.m16n8k8.row.col.f32.tf32.tf32.f32 "
        "{%0,%1,%2,%3}, {%4,%5,%6,%7}, {%8,%9}, {%0,%1,%2,%3};"
        : "+f"(c[0]), "+f"(c[1]), "+f"(c[2]), "+f"(c[3])
        : "r"(a[0]), "r"(a[1]), "r"(a[2]), "r"(a[3]), "r"(b0), "r"(b1));
}

// ---------------------------------------------------------------------------
// Kernel 1: combine bias table gather + per-window mask -> g_bm (padded pitch)
// ---------------------------------------------------------------------------
__global__ void bm_combine_kernel(const float* __restrict__ mask,
                                  const float* __restrict__ bt,
                                  const int* __restrict__ rpi)
{
    int ij = blockIdx.x * blockDim.x + threadIdx.x;
    if (ij >= NN) return;
    int w = blockIdx.y;
    int h = blockIdx.z;
    int i = ij / NTOK;
    int j = ij - i * NTOK;
    float v = bt[rpi[ij] * NHEAD + h] + mask[(size_t)w * NN + ij];
    g_bm[((size_t)(w * NHEAD + h) * NP + i) * BMP + j] = v;
}

// ---------------------------------------------------------------------------
// Kernel 2/4: tf32 mma GEMM  C[M x NC] = A[M x 192] * W[192 x NC] (+bias)
//   MODE 0: NC=576, scatter into g_q/g_k/g_vt.  MODE 1: NC=192 -> d_out.
// CTA tile 128x64, 8 warps (4m x 2n), warp 32x32 (2 m16 x 4 n8), K step 16,
// register-prefetch of the next K slab. Target 2 CTAs/SM.
// ---------------------------------------------------------------------------
#define AS_P 20
#define WS_P 72

template <int MODE>
__global__ void __launch_bounds__(256, 2)
gemm_tc_kernel(const float* __restrict__ Ain,
               const float* __restrict__ W,
               const float* __restrict__ bias,
               float* __restrict__ Cout)
{
    constexpr int NC = (MODE == 0) ? 3 * CDIM : CDIM;
    const float* A = (MODE == 0) ? Ain : g_o;

    __shared__ float As[128 * AS_P];
    __shared__ float Ws[16 * WS_P];

    const int tid  = threadIdx.x;
    const int w    = tid >> 5;
    const int lane = tid & 31;
    const int lq   = lane >> 2;
    const int lr   = lane & 3;
    const int wm   = w >> 1;           // 0..3 (m stripes of 32)
    const int wn   = w & 1;            // 0..1 (n halves of 32)
    const int row0 = blockIdx.y * 128;
    const int c0   = blockIdx.x * 64;

    // per-thread staging coords
    const int ar = tid >> 1;           // 0..127 (A row; 2 float4 per row pair)
    const int akq = (tid & 1) * 2;     // A k-quad base (loads kq, kq+1)
    const int wc4 = tid & 15;          // W col quad
    const int wk  = tid >> 4;          // W k row

    float acc[2][4][4];
    #pragma unroll
    for (int mi = 0; mi < 2; mi++)
        #pragma unroll
        for (int ni = 0; ni < 4; ni++)
            #pragma unroll
            for (int r = 0; r < 4; r++) acc[mi][ni][r] = 0.f;

    float4 pa0, pa1, pw;
    // prefetch k0 = 0
    pa0 = *(const float4*)(A + (size_t)(row0 + ar) * CDIM + akq * 4);
    pa1 = *(const float4*)(A + (size_t)(row0 + ar) * CDIM + (akq + 1) * 4);
    pw  = *(const float4*)(W + (size_t)wk * NC + c0 + wc4 * 4);

    for (int kb = 0; kb < 12; kb++) {
        // store staged regs to smem (tf32-rounded)
        {
            float4 a0 = pa0, a1 = pa1, wv = pw;
            a0.x = tf32r(a0.x); a0.y = tf32r(a0.y); a0.z = tf32r(a0.z); a0.w = tf32r(a0.w);
            a1.x = tf32r(a1.x); a1.y = tf32r(a1.y); a1.z = tf32r(a1.z); a1.w = tf32r(a1.w);
            wv.x = tf32r(wv.x); wv.y = tf32r(wv.y); wv.z = tf32r(wv.z); wv.w = tf32r(wv.w);
            *(float4*)&As[ar * AS_P + akq * 4] = a0;
            *(float4*)&As[ar * AS_P + (akq + 1) * 4] = a1;
            *(float4*)&Ws[wk * WS_P + wc4 * 4] = wv;
        }
        __syncthreads();

        // prefetch next slab
        if (kb < 11) {
            int k0 = (kb + 1) * 16;
            pa0 = *(const float4*)(A + (size_t)(row0 + ar) * CDIM + k0 + akq * 4);
            pa1 = *(const float4*)(A + (size_t)(row0 + ar) * CDIM + k0 + (akq + 1) * 4);
            pw  = *(const float4*)(W + (size_t)(k0 + wk) * NC + c0 + wc4 * 4);
        }

        #pragma unroll
        for (int ks = 0; ks < 2; ks++) {
            uint32_t bf[4][2];
            #pragma unroll
            for (int ni = 0; ni < 4; ni++) {
                int cc = wn * 32 + ni * 8 + lq;
                bf[ni][0] = __float_as_uint(Ws[(ks * 8 + lr) * WS_P + cc]);
                bf[ni][1] = __float_as_uint(Ws[(ks * 8 + lr + 4) * WS_P + cc]);
            }
            #pragma unroll
            for (int mi = 0; mi < 2; mi++) {
                int r0 = wm * 32 + mi * 16 + lq;
                uint32_t af[4];
                af[0] = __float_as_uint(As[r0 * AS_P + ks * 8 + lr]);
                af[1] = __float_as_uint(As[(r0 + 8) * AS_P + ks * 8 + lr]);
                af[2] = __float_as_uint(As[r0 * AS_P + ks * 8 + lr + 4]);
                af[3] = __float_as_uint(As[(r0 + 8) * AS_P + ks * 8 + lr + 4]);
                #pragma unroll
                for (int ni = 0; ni < 4; ni++)
                    mma_tf32(acc[mi][ni], af, bf[ni][0], bf[ni][1]);
            }
        }
        __syncthreads();
    }

    // epilogue
    #pragma unroll
    for (int mi = 0; mi < 2; mi++) {
        int rlo = row0 + wm * 32 + mi * 16 + lq;
        int rhi = rlo + 8;
        int blo = rlo / NTOK, nlo = rlo - blo * NTOK;
        int bhi = rhi / NTOK, nhi = rhi - bhi * NTOK;
        #pragma unroll
        for (int ni = 0; ni < 4; ni++) {
            int c = c0 + wn * 32 + ni * 8 + 2 * lr;
            float b0 = bias[c], b1 = bias[c + 1];
            if (MODE == 0) {
                int s   = c / CDIM;
                int rem = c - s * CDIM;
                int hh  = rem >> 5;
                int dd  = rem & 31;
                if (s == 2) {
                    float* vlo = g_vt + (size_t)(blo * NHEAD + hh) * HD * NP;
                    float* vhi = g_vt + (size_t)(bhi * NHEAD + hh) * HD * NP;
                    vlo[(size_t)dd * NP + nlo]       = tf32r(acc[mi][ni][0] + b0);
                    vlo[(size_t)(dd + 1) * NP + nlo] = tf32r(acc[mi][ni][1] + b1);
                    vhi[(size_t)dd * NP + nhi]       = tf32r(acc[mi][ni][2] + b0);
                    vhi[(size_t)(dd + 1) * NP + nhi] = tf32r(acc[mi][ni][3] + b1);
                } else {
                    float sc = (s == 0) ? SCALE : 1.f;
                    float* dst = (s == 0) ? g_q : g_k;
                    float2 vl, vh;
                    vl.x = tf32r((acc[mi][ni][0] + b0) * sc);
                    vl.y = tf32r((acc[mi][ni][1] + b1) * sc);
                    vh.x = tf32r((acc[mi][ni][2] + b0) * sc);
                    vh.y = tf32r((acc[mi][ni][3] + b1) * sc);
                    *(float2*)&dst[((size_t)(blo * NHEAD + hh) * NTOK + nlo) * HD + dd] = vl;
                    *(float2*)&dst[((size_t)(bhi * NHEAD + hh) * NTOK + nhi) * HD + dd] = vh;
                }
            } else {
                float2 vl, vh;
                vl.x = acc[mi][ni][0] + b0; vl.y = acc[mi][ni][1] + b1;
                vh.x = acc[mi][ni][2] + b0; vh.y = acc[mi][ni][3] + b1;
                *(float2*)&Cout[(size_t)rlo * CDIM + c] = vl;
                *(float2*)&Cout[(size_t)rhi * CDIM + c] = vh;
            }
        }
    }
}

// ---------------------------------------------------------------------------
// Kernel 3: warp-mma tf32 attention, 2 batches per CTA, fused per-nt softmax.
// Grid (NHEAD, NWIN, 12): z = mt*4 + bg; b = w + 64*(2bg + sb), sb in {0,1}.
// ---------------------------------------------------------------------------
#define KS_PITCH 36
#define VS_PITCH 68
#define BM_PITCH 68
#define P_PITCH  68
#define OFF_KS 0
#define OFF_VS (OFF_KS + 64 * KS_PITCH)          // 2304
#define OFF_BM (OFF_VS + 32 * VS_PITCH)          // 4480
#define OFF_P  (OFF_BM + 128 * BM_PITCH)         // 13184
#define ATTN_SMEM_FLOATS (OFF_P + 128 * P_PITCH) // 21888
#define ATTN_SMEM_BYTES  (ATTN_SMEM_FLOATS * 4)  // 87552

__global__ void __launch_bounds__(256, 2)
attn_mma_kernel()
{
    const int h   = blockIdx.x;
    const int wi  = blockIdx.y;
    const int z   = blockIdx.z;
    const int mt  = z >> 2;
    const int bg  = z & 3;
    const int tid = threadIdx.x;
    const int w   = tid >> 5;
    const int lane = tid & 31;
    const int lq  = lane >> 2;
    const int lr  = lane & 3;

    int bb[2];
    bb[0] = wi + NWIN * (2 * bg);
    bb[1] = wi + NWIN * (2 * bg + 1);

    extern __shared__ float sm[];
    float* Ks = sm + OFF_KS;
    float* Vs = sm + OFF_VS;
    float* BM = sm + OFF_BM;
    float* Pw = sm + OFF_P + w * 16 * P_PITCH;

    const int i0 = mt * 128;
    const int m0 = i0 + w * 16;
    const float* bmg = g_bm + (size_t)(wi * NHEAD + h) * NP * BMP;

    // --- load Q fragments for both batches (stage via BM area, pitch 36)
    uint32_t qf[2][4][4];
    #pragma unroll
    for (int sb = 0; sb < 2; sb++) {
        const float4* qg = (const float4*)(g_q + (size_t)(bb[sb] * NHEAD + h) * NTOK * HD);
        __syncthreads();
        for (int idx = tid; idx < 128 * 8; idx += 256) {
            int r = idx >> 3, dq = idx & 7;
            int i = i0 + r;
            float4 v = (i < NTOK) ? qg[i * 8 + dq] : make_float4(0.f, 0.f, 0.f, 0.f);
            *(float4*)&BM[r * KS_PITCH + dq * 4] = v;
        }
        __syncthreads();
        const int r0 = w * 16 + lq;
        #pragma unroll
        for (int ks = 0; ks < 4; ks++) {
            int c = ks * 8 + lr;
            qf[sb][ks][0] = __float_as_uint(BM[r0 * KS_PITCH + c]);
            qf[sb][ks][1] = __float_as_uint(BM[(r0 + 8) * KS_PITCH + c]);
            qf[sb][ks][2] = __float_as_uint(BM[r0 * KS_PITCH + c + 4]);
            qf[sb][ks][3] = __float_as_uint(BM[(r0 + 8) * KS_PITCH + c + 4]);
        }
    }

    float o[2][4][4];
    #pragma unroll
    for (int sb = 0; sb < 2; sb++)
        #pragma unroll
        for (int nt = 0; nt < 4; nt++)
            #pragma unroll
            for (int r = 0; r < 4; r++) o[sb][nt][r] = 0.f;
    float lsum[2][2] = {{0.f, 0.f}, {0.f, 0.f}};

    for (int jc = 0; jc < 6; jc++) {
        const int j0 = jc * 64;
        #pragma unroll
        for (int sb = 0; sb < 2; sb++) {
            __syncthreads();
            if (sb == 0) {
                // stage combined bias+mask [128 i x 64 j], float4 (padded gmem)
                for (int idx = tid; idx < 128 * 16; idx += 256) {
                    int r = idx >> 4, c4 = idx & 15;
                    float4 v = *(const float4*)(bmg + (size_t)(i0 + r) * BMP + j0 + c4 * 4);
                    *(float4*)&BM[r * BM_PITCH + c4 * 4] = v;
                }
            }
            // stage K chunk [64 j x 32 d], pitch 36
            const float4* kg = (const float4*)(g_k + (size_t)(bb[sb] * NHEAD + h) * NTOK * HD);
            for (int idx = tid; idx < 64 * 8; idx += 256) {
                int jl = idx >> 3, dq = idx & 7;
                int j = j0 + jl;
                float4 v = (j < NTOK) ? kg[j * 8 + dq] : make_float4(0.f, 0.f, 0.f, 0.f);
                *(float4*)&Ks[jl * KS_PITCH + dq * 4] = v;
            }
            // stage VT chunk [32 d x 64 j], pitch 68 (pad cols zero in g_vt)
            const float* vg = g_vt + (size_t)(bb[sb] * NHEAD + h) * HD * NP;
            for (int idx = tid; idx < 32 * 16; idx += 256) {
                int d = idx >> 4, jq = idx & 15;
                float4 v = *(const float4*)(vg + (size_t)d * NP + j0 + jq * 4);
                *(float4*)&Vs[d * VS_PITCH + jq * 4] = v;
            }
            __syncthreads();

            // fused: S-mma -> softmax -> P-store, per nt (s[4] transient)
            const int rbm0 = w * 16 + lq;
            #pragma unroll
            for (int nt = 0; nt < 8; nt++) {
                float s[4] = {0.f, 0.f, 0.f, 0.f};
                #pragma unroll
                for (int ks = 0; ks < 4; ks++) {
                    int kc = ks * 8 + lr;
                    uint32_t b0 = __float_as_uint(Ks[(nt * 8 + lq) * KS_PITCH + kc]);
                    uint32_t b1 = __float_as_uint(Ks[(nt * 8 + lq) * KS_PITCH + kc + 4]);
                    mma_tf32(s, qf[sb][ks], b0, b1);
                }
                int cl = nt * 8 + 2 * lr;
                int jgl = j0 + cl;
                float2 bm0 = *(const float2*)&BM[rbm0 * BM_PITCH + cl];
                float2 bm1 = *(const float2*)&BM[(rbm0 + 8) * BM_PITCH + cl];
                bool v0 = jgl < NTOK, v1 = (jgl + 1) < NTOK;
                float p00 = v0 ? __expf(s[0] + bm0.x) : 0.f;
                float p01 = v1 ? __expf(s[1] + bm0.y) : 0.f;
                float p10 = v0 ? __expf(s[2] + bm1.x) : 0.f;
                float p11 = v1 ? __expf(s[3] + bm1.y) : 0.f;
                lsum[sb][0] += p00 + p01;
                lsum[sb][1] += p10 + p11;
                float2 w0, w1;
                w0.x = __uint_as_float(tf32bits(p00));
                w0.y = __uint_as_float(tf32bits(p01));
                w1.x = __uint_as_float(tf32bits(p10));
                w1.y = __uint_as_float(tf32bits(p11));
                *(float2*)&Pw[lq * P_PITCH + cl] = w0;
                *(float2*)&Pw[(lq + 8) * P_PITCH + cl] = w1;
            }
            __syncwarp();

            // O += P * V
            #pragma unroll
            for (int ks = 0; ks < 8; ks++) {
                int kc = ks * 8 + lr;
                uint32_t a[4];
                a[0] = __float_as_uint(Pw[lq * P_PITCH + kc]);
                a[1] = __float_as_uint(Pw[(lq + 8) * P_PITCH + kc]);
                a[2] = __float_as_uint(Pw[lq * P_PITCH + kc + 4]);
                a[3] = __float_as_uint(Pw[(lq + 8) * P_PITCH + kc + 4]);
                #pragma unroll
                for (int nt = 0; nt < 4; nt++) {
                    uint32_t b0 = __float_as_uint(Vs[(nt * 8 + lq) * VS_PITCH + kc]);
                    uint32_t b1 = __float_as_uint(Vs[(nt * 8 + lq) * VS_PITCH + kc + 4]);
                    mma_tf32(o[sb][nt], a, b0, b1);
                }
            }
            __syncwarp();
        }
    }

    // epilogue
    #pragma unroll
    for (int sb = 0; sb < 2; sb++) {
        float l0 = lsum[sb][0], l1 = lsum[sb][1];
        l0 += __shfl_xor_sync(0xffffffffu, l0, 1);
        l0 += __shfl_xor_sync(0xffffffffu, l0, 2);
        l1 += __shfl_xor_sync(0xffffffffu, l1, 1);
        l1 += __shfl_xor_sync(0xffffffffu, l1, 2);
        float inv0 = 1.f / l0;
        float inv1 = 1.f / l1;

        const int ir0 = m0 + lq;
        const int ir1 = ir0 + 8;
        if (ir0 < NTOK) {
            float* base = g_o + ((size_t)bb[sb] * NTOK + ir0) * CDIM + h * HD;
            #pragma unroll
            for (int nt = 0; nt < 4; nt++) {
                float2 v; v.x = o[sb][nt][0] * inv0; v.y = o[sb][nt][1] * inv0;
                *(float2*)(base + nt * 8 + 2 * lr) = v;
            }
        }
        if (ir1 < NTOK) {
            float* base = g_o + ((size_t)bb[sb] * NTOK + ir1) * CDIM + h * HD;
            #pragma unroll
            for (int nt = 0; nt < 4; nt++) {
                float2 v; v.x = o[sb][nt][2] * inv1; v.y = o[sb][nt][3] * inv1;
                *(float2*)(base + nt * 8 + 2 * lr) = v;
            }
        }
    }
}

// ---------------------------------------------------------------------------
// Launch
// ---------------------------------------------------------------------------
extern "C" void kernel_launch(void* const* d_in, const int* in_sizes, int n_in,
                              void* d_out, int out_size)
{
    const float* x      = (const float*)d_in[0];
    const float* mask   = (const float*)d_in[1];
    const float* qkv_w  = (const float*)d_in[2];
    const float* qkv_b  = (const float*)d_in[3];
    const float* proj_w = (const float*)d_in[4];
    const float* proj_b = (const float*)d_in[5];
    const float* bt     = (const float*)d_in[6];
    const int*   rpi    = (const int*)d_in[7];
    float* out = (float*)d_out;

    cudaFuncSetAttribute(attn_mma_kernel,
                         cudaFuncAttributeMaxDynamicSharedMemorySize,
                         ATTN_SMEM_BYTES);

    bm_combine_kernel<<<dim3((NN + 255) / 256, NWIN, NHEAD), 256>>>(mask, bt, rpi);
    gemm_tc_kernel<0><<<dim3(9, 1372), 256>>>(x, qkv_w, qkv_b, nullptr);
    attn_mma_kernel<<<dim3(NHEAD, NWIN, 12), 256, ATTN_SMEM_BYTES>>>();
    gemm_tc_kernel<1><<<dim3(3, 1372), 256>>>(nullptr, proj_w, proj_b, out);
}

// round 7
// speedup vs baseline: 1.7965x; 1.0262x over previous
#include <cuda_runtime.h>
#include <cuda_bf16.h>
#include <cstdint>

// Problem constants
#define BATCH 512
#define NTOK  343
#define NP    384                  // padded token count (6 * 64)
#define CDIM  192
#define NHEAD 6
#define HD    32
#define NWIN  64
#define NN    (NTOK * NTOK)        // 117649
#define BMP   384                  // padded g_bm row pitch (floats)
#define SCALE 0.17677669529663687f // 32^-0.5

// ---------------------------------------------------------------------------
// Scratch (device globals: allocation-free, zero-init; pads stay zero)
// ---------------------------------------------------------------------------
__device__ float g_q[BATCH * NHEAD * NTOK * HD];   // [b][h][n][d] tf32-rounded, pre-scaled
__device__ float g_k[BATCH * NHEAD * NTOK * HD];   // [b][h][n][d] tf32-rounded
__device__ float g_vt[BATCH * NHEAD * HD * NP];    // [b][h][d][np] tf32-rounded, transposed
__device__ float g_o[BATCH * NTOK * CDIM];         // [b][n][h*32+d]
__device__ float g_bm[NWIN * NHEAD * NP * BMP];    // [w][h][i][j] bias+mask, padded

__device__ __forceinline__ float tf32r(float x) {
    uint32_t b;
    asm("cvt.rna.tf32.f32 %0, %1;" : "=r"(b) : "f"(x));
    return __uint_as_float(b);
}
__device__ __forceinline__ uint32_t tf32bits(float x) {
    uint32_t b;
    asm("cvt.rna.tf32.f32 %0, %1;" : "=r"(b) : "f"(x));
    return b;
}

// Warp-level tf32 MMA. Fragment layout (validated R3/R4):
//  A(row):  a0=(m=lq,k=lr) a1=(m=lq+8,k=lr) a2=(m=lq,k=lr+4) a3=(m=lq+8,k=lr+4)
//  B(col):  b0=(n=lq,k=lr) b1=(n=lq,k=lr+4)
//  C:       c0=(m=lq,n=2lr) c1=(m=lq,n=2lr+1) c2=(m=lq+8,n=2lr) c3=(m=lq+8,n=2lr+1)
__device__ __forceinline__ void mma_tf32(float c[4], const uint32_t a[4],
                                         uint32_t b0, uint32_t b1) {
    asm volatile(
        "mma.sync.aligned.m16n8k8.row.col.f32.tf32.tf32.f32 "
        "{%0,%1,%2,%3}, {%4,%5,%6,%7}, {%8,%9}, {%0,%1,%2,%3};"
        : "+f"(c[0]), "+f"(c[1]), "+f"(c[2]), "+f"(c[3])
        : "r"(a[0]), "r"(a[1]), "r"(a[2]), "r"(a[3]), "r"(b0), "r"(b1));
}

// ---------------------------------------------------------------------------
// Kernel 1: combine bias table gather + per-window mask -> g_bm (padded pitch)
// ---------------------------------------------------------------------------
__global__ void bm_combine_kernel(const float* __restrict__ mask,
                                  const float* __restrict__ bt,
                                  const int* __restrict__ rpi)
{
    int ij = blockIdx.x * blockDim.x + threadIdx.x;
    if (ij >= NN) return;
    int w = blockIdx.y;
    int h = blockIdx.z;
    int i = ij / NTOK;
    int j = ij - i * NTOK;
    float v = bt[rpi[ij] * NHEAD + h] + mask[(size_t)w * NN + ij];
    g_bm[((size_t)(w * NHEAD + h) * NP + i) * BMP + j] = v;
}

// ---------------------------------------------------------------------------
// Kernel 2/4: tf32 mma GEMM  C[M x NC] = A[M x 192] * W[192 x NC] (+bias)
//   MODE 0: NC=576, scatter into g_q/g_k/g_vt.  MODE 1: NC=192 -> d_out.
// CTA tile 128x64, 8 warps (4m x 2n), warp 32x32, K step 16.
// Double-buffered smem: 1 syncthreads per slab, staging overlaps compute.
// ---------------------------------------------------------------------------
#define AS_P 20
#define WS_P 72
#define AS_SZ (128 * AS_P)
#define WS_SZ (16 * WS_P)

template <int MODE>
__global__ void __launch_bounds__(256, 2)
gemm_tc_kernel(const float* __restrict__ Ain,
               const float* __restrict__ W,
               const float* __restrict__ bias,
               float* __restrict__ Cout)
{
    constexpr int NC = (MODE == 0) ? 3 * CDIM : CDIM;
    const float* A = (MODE == 0) ? Ain : g_o;

    __shared__ float As[2 * AS_SZ];
    __shared__ float Ws[2 * WS_SZ];

    const int tid  = threadIdx.x;
    const int w    = tid >> 5;
    const int lane = tid & 31;
    const int lq   = lane >> 2;
    const int lr   = lane & 3;
    const int wm   = w >> 1;
    const int wn   = w & 1;
    const int row0 = blockIdx.y * 128;
    const int c0   = blockIdx.x * 64;

    const int ar  = tid >> 1;
    const int akq = (tid & 1) * 2;
    const int wc4 = tid & 15;
    const int wk  = tid >> 4;

    float acc[2][4][4];
    #pragma unroll
    for (int mi = 0; mi < 2; mi++)
        #pragma unroll
        for (int ni = 0; ni < 4; ni++)
            #pragma unroll
            for (int r = 0; r < 4; r++) acc[mi][ni][r] = 0.f;

    // prefetch + store slab 0 into buffer 0
    {
        float4 a0 = *(const float4*)(A + (size_t)(row0 + ar) * CDIM + akq * 4);
        float4 a1 = *(const float4*)(A + (size_t)(row0 + ar) * CDIM + (akq + 1) * 4);
        float4 wv = *(const float4*)(W + (size_t)wk * NC + c0 + wc4 * 4);
        a0.x = tf32r(a0.x); a0.y = tf32r(a0.y); a0.z = tf32r(a0.z); a0.w = tf32r(a0.w);
        a1.x = tf32r(a1.x); a1.y = tf32r(a1.y); a1.z = tf32r(a1.z); a1.w = tf32r(a1.w);
        wv.x = tf32r(wv.x); wv.y = tf32r(wv.y); wv.z = tf32r(wv.z); wv.w = tf32r(wv.w);
        *(float4*)&As[ar * AS_P + akq * 4] = a0;
        *(float4*)&As[ar * AS_P + (akq + 1) * 4] = a1;
        *(float4*)&Ws[wk * WS_P + wc4 * 4] = wv;
    }
    __syncthreads();

    for (int kb = 0; kb < 12; kb++) {
        const float* Ab = &As[(kb & 1) * AS_SZ];
        const float* Wb = &Ws[(kb & 1) * WS_SZ];

        // prefetch next slab into registers
        float4 pa0, pa1, pw;
        if (kb < 11) {
            int k0 = (kb + 1) * 16;
            pa0 = *(const float4*)(A + (size_t)(row0 + ar) * CDIM + k0 + akq * 4);
            pa1 = *(const float4*)(A + (size_t)(row0 + ar) * CDIM + k0 + (akq + 1) * 4);
            pw  = *(const float4*)(W + (size_t)(k0 + wk) * NC + c0 + wc4 * 4);
        }

        #pragma unroll
        for (int ks = 0; ks < 2; ks++) {
            uint32_t bf[4][2];
            #pragma unroll
            for (int ni = 0; ni < 4; ni++) {
                int cc = wn * 32 + ni * 8 + lq;
                bf[ni][0] = __float_as_uint(Wb[(ks * 8 + lr) * WS_P + cc]);
                bf[ni][1] = __float_as_uint(Wb[(ks * 8 + lr + 4) * WS_P + cc]);
            }
            #pragma unroll
            for (int mi = 0; mi < 2; mi++) {
                int r0 = wm * 32 + mi * 16 + lq;
                uint32_t af[4];
                af[0] = __float_as_uint(Ab[r0 * AS_P + ks * 8 + lr]);
                af[1] = __float_as_uint(Ab[(r0 + 8) * AS_P + ks * 8 + lr]);
                af[2] = __float_as_uint(Ab[r0 * AS_P + ks * 8 + lr + 4]);
                af[3] = __float_as_uint(Ab[(r0 + 8) * AS_P + ks * 8 + lr + 4]);
                #pragma unroll
                for (int ni = 0; ni < 4; ni++)
                    mma_tf32(acc[mi][ni], af, bf[ni][0], bf[ni][1]);
            }
        }

        // store next slab into other buffer (safe: that buffer's readers
        // finished before the barrier at the end of the previous iteration)
        if (kb < 11) {
            float* An = &As[((kb + 1) & 1) * AS_SZ];
            float* Wn = &Ws[((kb + 1) & 1) * WS_SZ];
            pa0.x = tf32r(pa0.x); pa0.y = tf32r(pa0.y); pa0.z = tf32r(pa0.z); pa0.w = tf32r(pa0.w);
            pa1.x = tf32r(pa1.x); pa1.y = tf32r(pa1.y); pa1.z = tf32r(pa1.z); pa1.w = tf32r(pa1.w);
            pw.x = tf32r(pw.x); pw.y = tf32r(pw.y); pw.z = tf32r(pw.z); pw.w = tf32r(pw.w);
            *(float4*)&An[ar * AS_P + akq * 4] = pa0;
            *(float4*)&An[ar * AS_P + (akq + 1) * 4] = pa1;
            *(float4*)&Wn[wk * WS_P + wc4 * 4] = pw;
            __syncthreads();
        }
    }

    // epilogue
    #pragma unroll
    for (int mi = 0; mi < 2; mi++) {
        int rlo = row0 + wm * 32 + mi * 16 + lq;
        int rhi = rlo + 8;
        int blo = rlo / NTOK, nlo = rlo - blo * NTOK;
        int bhi = rhi / NTOK, nhi = rhi - bhi * NTOK;
        #pragma unroll
        for (int ni = 0; ni < 4; ni++) {
            int c = c0 + wn * 32 + ni * 8 + 2 * lr;
            float b0 = bias[c], b1 = bias[c + 1];
            if (MODE == 0) {
                int s   = c / CDIM;
                int rem = c - s * CDIM;
                int hh  = rem >> 5;
                int dd  = rem & 31;
                if (s == 2) {
                    float* vlo = g_vt + (size_t)(blo * NHEAD + hh) * HD * NP;
                    float* vhi = g_vt + (size_t)(bhi * NHEAD + hh) * HD * NP;
                    vlo[(size_t)dd * NP + nlo]       = tf32r(acc[mi][ni][0] + b0);
                    vlo[(size_t)(dd + 1) * NP + nlo] = tf32r(acc[mi][ni][1] + b1);
                    vhi[(size_t)dd * NP + nhi]       = tf32r(acc[mi][ni][2] + b0);
                    vhi[(size_t)(dd + 1) * NP + nhi] = tf32r(acc[mi][ni][3] + b1);
                } else {
                    float sc = (s == 0) ? SCALE : 1.f;
                    float* dst = (s == 0) ? g_q : g_k;
                    float2 vl, vh;
                    vl.x = tf32r((acc[mi][ni][0] + b0) * sc);
                    vl.y = tf32r((acc[mi][ni][1] + b1) * sc);
                    vh.x = tf32r((acc[mi][ni][2] + b0) * sc);
                    vh.y = tf32r((acc[mi][ni][3] + b1) * sc);
                    *(float2*)&dst[((size_t)(blo * NHEAD + hh) * NTOK + nlo) * HD + dd] = vl;
                    *(float2*)&dst[((size_t)(bhi * NHEAD + hh) * NTOK + nhi) * HD + dd] = vh;
                }
            } else {
                float2 vl, vh;
                vl.x = acc[mi][ni][0] + b0; vl.y = acc[mi][ni][1] + b1;
                vh.x = acc[mi][ni][2] + b0; vh.y = acc[mi][ni][3] + b1;
                *(float2*)&Cout[(size_t)rlo * CDIM + c] = vl;
                *(float2*)&Cout[(size_t)rhi * CDIM + c] = vh;
            }
        }
    }
}

// ---------------------------------------------------------------------------
// Kernel 3: warp-mma tf32 attention, 2 batches per CTA.
// Per chunk: ONE staging phase (BM + K/V for BOTH batches, 2 syncthreads),
// then per sb: S-mma in nt-pairs (2 indep chains) -> softmax -> P (warp-
// private smem, __syncwarp only) -> PV-mma (4 indep chains).
// Grid (NHEAD, NWIN, 12): z = mt*4 + bg; b = wi + 64*(2bg + sb).
// ---------------------------------------------------------------------------
#define KS_PITCH 36
#define VS_PITCH 68
#define BM_PITCH 68
#define P_PITCH  68
#define KS_SZ (64 * KS_PITCH)                     // 2304
#define VS_SZ (32 * VS_PITCH)                     // 2176
#define OFF_KS 0
#define OFF_VS (OFF_KS + 2 * KS_SZ)               // 4608
#define OFF_BM (OFF_VS + 2 * VS_SZ)               // 8960
#define OFF_P  (OFF_BM + 128 * BM_PITCH)          // 17664
#define ATTN_SMEM_FLOATS (OFF_P + 128 * P_PITCH)  // 26368
#define ATTN_SMEM_BYTES  (ATTN_SMEM_FLOATS * 4)   // 105472

__global__ void __launch_bounds__(256, 2)
attn_mma_kernel()
{
    const int h   = blockIdx.x;
    const int wi  = blockIdx.y;
    const int z   = blockIdx.z;
    const int mt  = z >> 2;
    const int bg  = z & 3;
    const int tid = threadIdx.x;
    const int w   = tid >> 5;
    const int lane = tid & 31;
    const int lq  = lane >> 2;
    const int lr  = lane & 3;

    int bb[2];
    bb[0] = wi + NWIN * (2 * bg);
    bb[1] = wi + NWIN * (2 * bg + 1);

    extern __shared__ float sm[];
    float* BM = sm + OFF_BM;
    float* Pw = sm + OFF_P + w * 16 * P_PITCH;

    const int i0 = mt * 128;
    const int m0 = i0 + w * 16;
    const float* bmg = g_bm + (size_t)(wi * NHEAD + h) * NP * BMP;

    // --- load Q fragments for both batches (stage via BM area, pitch 36)
    uint32_t qf[2][4][4];
    #pragma unroll
    for (int sb = 0; sb < 2; sb++) {
        const float4* qg = (const float4*)(g_q + (size_t)(bb[sb] * NHEAD + h) * NTOK * HD);
        __syncthreads();
        for (int idx = tid; idx < 128 * 8; idx += 256) {
            int r = idx >> 3, dq = idx & 7;
            int i = i0 + r;
            float4 v = (i < NTOK) ? qg[i * 8 + dq] : make_float4(0.f, 0.f, 0.f, 0.f);
            *(float4*)&BM[r * KS_PITCH + dq * 4] = v;
        }
        __syncthreads();
        const int r0 = w * 16 + lq;
        #pragma unroll
        for (int ks = 0; ks < 4; ks++) {
            int c = ks * 8 + lr;
            qf[sb][ks][0] = __float_as_uint(BM[r0 * KS_PITCH + c]);
            qf[sb][ks][1] = __float_as_uint(BM[(r0 + 8) * KS_PITCH + c]);
            qf[sb][ks][2] = __float_as_uint(BM[r0 * KS_PITCH + c + 4]);
            qf[sb][ks][3] = __float_as_uint(BM[(r0 + 8) * KS_PITCH + c + 4]);
        }
    }

    float o[2][4][4];
    #pragma unroll
    for (int sb = 0; sb < 2; sb++)
        #pragma unroll
        for (int nt = 0; nt < 4; nt++)
            #pragma unroll
            for (int r = 0; r < 4; r++) o[sb][nt][r] = 0.f;
    float lsum[2][2] = {{0.f, 0.f}, {0.f, 0.f}};

    for (int jc = 0; jc < 6; jc++) {
        const int j0 = jc * 64;
        __syncthreads();
        // stage BM chunk [128 x 64], float4 from padded gmem
        for (int idx = tid; idx < 128 * 16; idx += 256) {
            int r = idx >> 4, c4 = idx & 15;
            float4 v = *(const float4*)(bmg + (size_t)(i0 + r) * BMP + j0 + c4 * 4);
            *(float4*)&BM[r * BM_PITCH + c4 * 4] = v;
        }
        // stage K + VT for BOTH batches
        #pragma unroll
        for (int sb = 0; sb < 2; sb++) {
            float* Ks = sm + OFF_KS + sb * KS_SZ;
            float* Vs = sm + OFF_VS + sb * VS_SZ;
            const float4* kg = (const float4*)(g_k + (size_t)(bb[sb] * NHEAD + h) * NTOK * HD);
            for (int idx = tid; idx < 64 * 8; idx += 256) {
                int jl = idx >> 3, dq = idx & 7;
                int j = j0 + jl;
                float4 v = (j < NTOK) ? kg[j * 8 + dq] : make_float4(0.f, 0.f, 0.f, 0.f);
                *(float4*)&Ks[jl * KS_PITCH + dq * 4] = v;
            }
            const float* vg = g_vt + (size_t)(bb[sb] * NHEAD + h) * HD * NP;
            for (int idx = tid; idx < 32 * 16; idx += 256) {
                int d = idx >> 4, jq = idx & 15;
                float4 v = *(const float4*)(vg + (size_t)d * NP + j0 + jq * 4);
                *(float4*)&Vs[d * VS_PITCH + jq * 4] = v;
            }
        }
        __syncthreads();

        #pragma unroll
        for (int sb = 0; sb < 2; sb++) {
            const float* Ks = sm + OFF_KS + sb * KS_SZ;
            const float* Vs = sm + OFF_VS + sb * VS_SZ;
            const int rbm0 = w * 16 + lq;

            // S phase in nt-pairs: two independent accumulation chains
            #pragma unroll
            for (int ntp = 0; ntp < 4; ntp++) {
                const int nt0 = 2 * ntp, nt1 = 2 * ntp + 1;
                float s0[4] = {0.f, 0.f, 0.f, 0.f};
                float s1[4] = {0.f, 0.f, 0.f, 0.f};
                #pragma unroll
                for (int ks = 0; ks < 4; ks++) {
                    int kc = ks * 8 + lr;
                    uint32_t b00 = __float_as_uint(Ks[(nt0 * 8 + lq) * KS_PITCH + kc]);
                    uint32_t b01 = __float_as_uint(Ks[(nt0 * 8 + lq) * KS_PITCH + kc + 4]);
                    uint32_t b10 = __float_as_uint(Ks[(nt1 * 8 + lq) * KS_PITCH + kc]);
                    uint32_t b11 = __float_as_uint(Ks[(nt1 * 8 + lq) * KS_PITCH + kc + 4]);
                    mma_tf32(s0, qf[sb][ks], b00, b01);
                    mma_tf32(s1, qf[sb][ks], b10, b11);
                }
                #pragma unroll
                for (int half = 0; half < 2; half++) {
                    const float* s = half ? s1 : s0;
                    const int nt = half ? nt1 : nt0;
                    int cl = nt * 8 + 2 * lr;
                    int jgl = j0 + cl;
                    float2 bm0 = *(const float2*)&BM[rbm0 * BM_PITCH + cl];
                    float2 bm1 = *(const float2*)&BM[(rbm0 + 8) * BM_PITCH + cl];
                    bool v0 = jgl < NTOK, v1 = (jgl + 1) < NTOK;
                    float p00 = v0 ? __expf(s[0] + bm0.x) : 0.f;
                    float p01 = v1 ? __expf(s[1] + bm0.y) : 0.f;
                    float p10 = v0 ? __expf(s[2] + bm1.x) : 0.f;
                    float p11 = v1 ? __expf(s[3] + bm1.y) : 0.f;
                    lsum[sb][0] += p00 + p01;
                    lsum[sb][1] += p10 + p11;
                    float2 w0, w1;
                    w0.x = __uint_as_float(tf32bits(p00));
                    w0.y = __uint_as_float(tf32bits(p01));
                    w1.x = __uint_as_float(tf32bits(p10));
                    w1.y = __uint_as_float(tf32bits(p11));
                    *(float2*)&Pw[lq * P_PITCH + cl] = w0;
                    *(float2*)&Pw[(lq + 8) * P_PITCH + cl] = w1;
                }
            }
            __syncwarp();

            // O += P * V  (4 independent accumulation chains)
            #pragma unroll
            for (int ks = 0; ks < 8; ks++) {
                int kc = ks * 8 + lr;
                uint32_t a[4];
                a[0] = __float_as_uint(Pw[lq * P_PITCH + kc]);
                a[1] = __float_as_uint(Pw[(lq + 8) * P_PITCH + kc]);
                a[2] = __float_as_uint(Pw[lq * P_PITCH + kc + 4]);
                a[3] = __float_as_uint(Pw[(lq + 8) * P_PITCH + kc + 4]);
                #pragma unroll
                for (int nt = 0; nt < 4; nt++) {
                    uint32_t b0 = __float_as_uint(Vs[(nt * 8 + lq) * VS_PITCH + kc]);
                    uint32_t b1 = __float_as_uint(Vs[(nt * 8 + lq) * VS_PITCH + kc + 4]);
                    mma_tf32(o[sb][nt], a, b0, b1);
                }
            }
            __syncwarp();
        }
    }

    // epilogue
    #pragma unroll
    for (int sb = 0; sb < 2; sb++) {
        float l0 = lsum[sb][0], l1 = lsum[sb][1];
        l0 += __shfl_xor_sync(0xffffffffu, l0, 1);
        l0 += __shfl_xor_sync(0xffffffffu, l0, 2);
        l1 += __shfl_xor_sync(0xffffffffu, l1, 1);
        l1 += __shfl_xor_sync(0xffffffffu, l1, 2);
        float inv0 = 1.f / l0;
        float inv1 = 1.f / l1;

        const int ir0 = m0 + lq;
        const int ir1 = ir0 + 8;
        if (ir0 < NTOK) {
            float* base = g_o + ((size_t)bb[sb] * NTOK + ir0) * CDIM + h * HD;
            #pragma unroll
            for (int nt = 0; nt < 4; nt++) {
                float2 v; v.x = o[sb][nt][0] * inv0; v.y = o[sb][nt][1] * inv0;
                *(float2*)(base + nt * 8 + 2 * lr) = v;
            }
        }
        if (ir1 < NTOK) {
            float* base = g_o + ((size_t)bb[sb] * NTOK + ir1) * CDIM + h * HD;
            #pragma unroll
            for (int nt = 0; nt < 4; nt++) {
                float2 v; v.x = o[sb][nt][2] * inv1; v.y = o[sb][nt][3] * inv1;
                *(float2*)(base + nt * 8 + 2 * lr) = v;
            }
        }
    }
}

// ---------------------------------------------------------------------------
// Launch
// ---------------------------------------------------------------------------
extern "C" void kernel_launch(void* const* d_in, const int* in_sizes, int n_in,
                              void* d_out, int out_size)
{
    const float* x      = (const float*)d_in[0];
    const float* mask   = (const float*)d_in[1];
    const float* qkv_w  = (const float*)d_in[2];
    const float* qkv_b  = (const float*)d_in[3];
    const float* proj_w = (const float*)d_in[4];
    const float* proj_b = (const float*)d_in[5];
    const float* bt     = (const float*)d_in[6];
    const int*   rpi    = (const int*)d_in[7];
    float* out = (float*)d_out;

    cudaFuncSetAttribute(attn_mma_kernel,
                         cudaFuncAttributeMaxDynamicSharedMemorySize,
                         ATTN_SMEM_BYTES);

    bm_combine_kernel<<<dim3((NN + 255) / 256, NWIN, NHEAD), 256>>>(mask, bt, rpi);
    gemm_tc_kernel<0><<<dim3(9, 1372), 256>>>(x, qkv_w, qkv_b, nullptr);
    attn_mma_kernel<<<dim3(NHEAD, NWIN, 12), 256, ATTN_SMEM_BYTES>>>();
    gemm_tc_kernel<1><<<dim3(3, 1372), 256>>>(nullptr, proj_w, proj_b, out);
}

// round 8
// speedup vs baseline: 1.9008x; 1.0581x over previous
#include <cuda_runtime.h>
#include <cuda_bf16.h>
#include <cstdint>

// Problem constants
#define BATCH 512
#define NTOK  343
#define NP    384                  // padded token count
#define CDIM  192
#define NHEAD 6
#define HD    32
#define NWIN  64
#define NN    (NTOK * NTOK)
#define BMP   384                  // padded g_bm row pitch (floats)
#define SCALE 0.17677669529663687f

// ---------------------------------------------------------------------------
// Scratch (device globals: allocation-free, zero-init; pads stay zero)
// ---------------------------------------------------------------------------
__device__ float g_q[BATCH * NHEAD * NTOK * HD];
__device__ float g_k[BATCH * NHEAD * NTOK * HD];
__device__ float g_vt[BATCH * NHEAD * HD * NP];
__device__ float g_o[BATCH * NTOK * CDIM];
__device__ float g_bm[NWIN * NHEAD * NP * BMP];

__device__ __forceinline__ float tf32r(float x) {
    uint32_t b;
    asm("cvt.rna.tf32.f32 %0, %1;" : "=r"(b) : "f"(x));
    return __uint_as_float(b);
}
__device__ __forceinline__ uint32_t tf32bits(float x) {
    uint32_t b;
    asm("cvt.rna.tf32.f32 %0, %1;" : "=r"(b) : "f"(x));
    return b;
}

// Warp-level tf32 MMA. Fragment layout (validated R3/R4):
//  A(row):  a0=(m=lq,k=lr) a1=(m=lq+8,k=lr) a2=(m=lq,k=lr+4) a3=(m=lq+8,k=lr+4)
//  B(col):  b0=(n=lq,k=lr) b1=(n=lq,k=lr+4)
//  C:       c0=(m=lq,n=2lr) c1=(m=lq,n=2lr+1) c2=(m=lq+8,n=2lr) c3=(m=lq+8,n=2lr+1)
__device__ __forceinline__ void mma_tf32(float c[4], const uint32_t a[4],
                                         uint32_t b0, uint32_t b1) {
    asm volatile(
        "mma.sync.aligned.m16n8k8.row.col.f32.tf32.tf32.f32 "
        "{%0,%1,%2,%3}, {%4,%5,%6,%7}, {%8,%9}, {%0,%1,%2,%3};"
        : "+f"(c[0]), "+f"(c[1]), "+f"(c[2]), "+f"(c[3])
        : "r"(a[0]), "r"(a[1]), "r"(a[2]), "r"(a[3]), "r"(b0), "r"(b1));
}

// ---------------------------------------------------------------------------
// Kernel 1: combine bias table gather + per-window mask -> g_bm (padded pitch)
// ---------------------------------------------------------------------------
__global__ void bm_combine_kernel(const float* __restrict__ mask,
                                  const float* __restrict__ bt,
                                  const int* __restrict__ rpi)
{
    int ij = blockIdx.x * blockDim.x + threadIdx.x;
    if (ij >= NN) return;
    int w = blockIdx.y;
    int h = blockIdx.z;
    int i = ij / NTOK;
    int j = ij - i * NTOK;
    float v = bt[rpi[ij] * NHEAD + h] + mask[(size_t)w * NN + ij];
    g_bm[((size_t)(w * NHEAD + h) * NP + i) * BMP + j] = v;
}

// ---------------------------------------------------------------------------
// Kernel 2/4: tf32 mma GEMM (R4 shape: CTA 256x64, warp 64x32, 1 CTA/SM)
// + double-buffered smem with register prefetch (1 syncthreads per slab).
//   MODE 0: NC=576, scatter into g_q/g_k/g_vt.  MODE 1: NC=192 -> d_out.
// ---------------------------------------------------------------------------
#define AS_P 20
#define WS_P 72
#define AS_SZ (256 * AS_P)
#define WS_SZ (16 * WS_P)

template <int MODE>
__global__ void __launch_bounds__(256, 1)
gemm_tc_kernel(const float* __restrict__ Ain,
               const float* __restrict__ W,
               const float* __restrict__ bias,
               float* __restrict__ Cout)
{
    constexpr int NC = (MODE == 0) ? 3 * CDIM : CDIM;
    const float* A = (MODE == 0) ? Ain : g_o;

    __shared__ float As[2 * AS_SZ];
    __shared__ float Ws[2 * WS_SZ];

    const int tid  = threadIdx.x;
    const int w    = tid >> 5;
    const int lane = tid & 31;
    const int lq   = lane >> 2;
    const int lr   = lane & 3;
    const int wm   = w >> 1;           // 4 m-stripes of 64
    const int wn   = w & 1;            // 2 n-halves of 32
    const int row0 = blockIdx.y * 256;
    const int c0   = blockIdx.x * 64;

    // staging coords: 4 A float4s per thread (rows 64f + tid/4), 1 W float4
    const int arq = tid >> 2;          // base A row (0..63), +64 per f
    const int akq = tid & 3;           // A col quad
    const int wc4 = tid & 15;
    const int wk  = tid >> 4;

    float acc[4][4][4];
    #pragma unroll
    for (int mi = 0; mi < 4; mi++)
        #pragma unroll
        for (int ni = 0; ni < 4; ni++)
            #pragma unroll
            for (int r = 0; r < 4; r++) acc[mi][ni][r] = 0.f;

    // stage slab 0 into buffer 0
    {
        #pragma unroll
        for (int f = 0; f < 4; f++) {
            float4 a = *(const float4*)(A + (size_t)(row0 + f * 64 + arq) * CDIM + akq * 4);
            a.x = tf32r(a.x); a.y = tf32r(a.y); a.z = tf32r(a.z); a.w = tf32r(a.w);
            *(float4*)&As[(f * 64 + arq) * AS_P + akq * 4] = a;
        }
        float4 wv = *(const float4*)(W + (size_t)wk * NC + c0 + wc4 * 4);
        wv.x = tf32r(wv.x); wv.y = tf32r(wv.y); wv.z = tf32r(wv.z); wv.w = tf32r(wv.w);
        *(float4*)&Ws[wk * WS_P + wc4 * 4] = wv;
    }
    __syncthreads();

    for (int kb = 0; kb < 12; kb++) {
        const float* Ab = &As[(kb & 1) * AS_SZ];
        const float* Wb = &Ws[(kb & 1) * WS_SZ];

        float4 pa[4], pw;
        if (kb < 11) {
            int k0 = (kb + 1) * 16;
            #pragma unroll
            for (int f = 0; f < 4; f++)
                pa[f] = *(const float4*)(A + (size_t)(row0 + f * 64 + arq) * CDIM + k0 + akq * 4);
            pw = *(const float4*)(W + (size_t)(k0 + wk) * NC + c0 + wc4 * 4);
        }

        #pragma unroll
        for (int ks = 0; ks < 2; ks++) {
            uint32_t bf[4][2];
            #pragma unroll
            for (int ni = 0; ni < 4; ni++) {
                int cc = wn * 32 + ni * 8 + lq;
                bf[ni][0] = __float_as_uint(Wb[(ks * 8 + lr) * WS_P + cc]);
                bf[ni][1] = __float_as_uint(Wb[(ks * 8 + lr + 4) * WS_P + cc]);
            }
            #pragma unroll
            for (int mi = 0; mi < 4; mi++) {
                int r0 = wm * 64 + mi * 16 + lq;
                uint32_t af[4];
                af[0] = __float_as_uint(Ab[r0 * AS_P + ks * 8 + lr]);
                af[1] = __float_as_uint(Ab[(r0 + 8) * AS_P + ks * 8 + lr]);
                af[2] = __float_as_uint(Ab[r0 * AS_P + ks * 8 + lr + 4]);
                af[3] = __float_as_uint(Ab[(r0 + 8) * AS_P + ks * 8 + lr + 4]);
                #pragma unroll
                for (int ni = 0; ni < 4; ni++)
                    mma_tf32(acc[mi][ni], af, bf[ni][0], bf[ni][1]);
            }
        }

        if (kb < 11) {
            float* An = &As[((kb + 1) & 1) * AS_SZ];
            float* Wn = &Ws[((kb + 1) & 1) * WS_SZ];
            #pragma unroll
            for (int f = 0; f < 4; f++) {
                float4 a = pa[f];
                a.x = tf32r(a.x); a.y = tf32r(a.y); a.z = tf32r(a.z); a.w = tf32r(a.w);
                *(float4*)&An[(f * 64 + arq) * AS_P + akq * 4] = a;
            }
            pw.x = tf32r(pw.x); pw.y = tf32r(pw.y); pw.z = tf32r(pw.z); pw.w = tf32r(pw.w);
            *(float4*)&Wn[wk * WS_P + wc4 * 4] = pw;
            __syncthreads();
        }
    }

    // epilogue
    #pragma unroll
    for (int mi = 0; mi < 4; mi++) {
        int rlo = row0 + wm * 64 + mi * 16 + lq;
        int rhi = rlo + 8;
        int blo = rlo / NTOK, nlo = rlo - blo * NTOK;
        int bhi = rhi / NTOK, nhi = rhi - bhi * NTOK;
        #pragma unroll
        for (int ni = 0; ni < 4; ni++) {
            int c = c0 + wn * 32 + ni * 8 + 2 * lr;
            float b0 = bias[c], b1 = bias[c + 1];
            if (MODE == 0) {
                int s   = c / CDIM;
                int rem = c - s * CDIM;
                int hh  = rem >> 5;
                int dd  = rem & 31;
                if (s == 2) {
                    float* vlo = g_vt + (size_t)(blo * NHEAD + hh) * HD * NP;
                    float* vhi = g_vt + (size_t)(bhi * NHEAD + hh) * HD * NP;
                    vlo[(size_t)dd * NP + nlo]       = tf32r(acc[mi][ni][0] + b0);
                    vlo[(size_t)(dd + 1) * NP + nlo] = tf32r(acc[mi][ni][1] + b1);
                    vhi[(size_t)dd * NP + nhi]       = tf32r(acc[mi][ni][2] + b0);
                    vhi[(size_t)(dd + 1) * NP + nhi] = tf32r(acc[mi][ni][3] + b1);
                } else {
                    float sc = (s == 0) ? SCALE : 1.f;
                    float* dst = (s == 0) ? g_q : g_k;
                    float2 vl, vh;
                    vl.x = tf32r((acc[mi][ni][0] + b0) * sc);
                    vl.y = tf32r((acc[mi][ni][1] + b1) * sc);
                    vh.x = tf32r((acc[mi][ni][2] + b0) * sc);
                    vh.y = tf32r((acc[mi][ni][3] + b1) * sc);
                    *(float2*)&dst[((size_t)(blo * NHEAD + hh) * NTOK + nlo) * HD + dd] = vl;
                    *(float2*)&dst[((size_t)(bhi * NHEAD + hh) * NTOK + nhi) * HD + dd] = vh;
                }
            } else {
                float2 vl, vh;
                vl.x = acc[mi][ni][0] + b0; vl.y = acc[mi][ni][1] + b1;
                vh.x = acc[mi][ni][2] + b0; vh.y = acc[mi][ni][3] + b1;
                *(float2*)&Cout[(size_t)rlo * CDIM + c] = vl;
                *(float2*)&Cout[(size_t)rhi * CDIM + c] = vh;
            }
        }
    }
}

// ---------------------------------------------------------------------------
// Kernel 3: warp-mma tf32 attention, 1 batch/CTA, NO BM smem (reg-prefetched
// bias+mask LDGs from padded g_bm), 53 KB smem -> 3 CTAs/SM.
// Grid (48, NWIN, 3): x = bg + 8*h (bg fastest => 8 adjacent CTAs share the
// same BM tile in L2); b = wi + 64*bg; z = m-tile.
// ---------------------------------------------------------------------------
#define KS_PITCH 36
#define VS_PITCH 68
#define P_PITCH  68
#define OFF_KS 0
#define OFF_VS (OFF_KS + 64 * KS_PITCH)           // 2304
#define OFF_P  (OFF_VS + 32 * VS_PITCH)           // 4480
#define ATTN_SMEM_FLOATS (OFF_P + 128 * P_PITCH)  // 13184
#define ATTN_SMEM_BYTES  (ATTN_SMEM_FLOATS * 4)   // 52736

__global__ void __launch_bounds__(256, 3)
attn_mma_kernel()
{
    const int bg  = blockIdx.x & 7;
    const int h   = blockIdx.x >> 3;
    const int wi  = blockIdx.y;
    const int mt  = blockIdx.z;
    const int b   = wi + NWIN * bg;
    const int tid = threadIdx.x;
    const int w   = tid >> 5;
    const int lane = tid & 31;
    const int lq  = lane >> 2;
    const int lr  = lane & 3;

    extern __shared__ float sm[];
    float* Ks = sm + OFF_KS;
    float* Vs = sm + OFF_VS;
    float* Pw = sm + OFF_P + w * 16 * P_PITCH;

    const int i0 = mt * 128;
    const int m0 = i0 + w * 16;
    const size_t bh = (size_t)(b * NHEAD + h);

    // --- load Q fragments (stage via P region, pitch 36)
    uint32_t qf[4][4];
    {
        float* Qs = sm + OFF_P;
        const float4* qg = (const float4*)(g_q + bh * NTOK * HD);
        for (int idx = tid; idx < 128 * 8; idx += 256) {
            int r = idx >> 3, dq = idx & 7;
            int i = i0 + r;
            float4 v = (i < NTOK) ? qg[i * 8 + dq] : make_float4(0.f, 0.f, 0.f, 0.f);
            *(float4*)&Qs[r * KS_PITCH + dq * 4] = v;
        }
        __syncthreads();
        const int r0 = w * 16 + lq;
        #pragma unroll
        for (int ks = 0; ks < 4; ks++) {
            int c = ks * 8 + lr;
            qf[ks][0] = __float_as_uint(Qs[r0 * KS_PITCH + c]);
            qf[ks][1] = __float_as_uint(Qs[(r0 + 8) * KS_PITCH + c]);
            qf[ks][2] = __float_as_uint(Qs[r0 * KS_PITCH + c + 4]);
            qf[ks][3] = __float_as_uint(Qs[(r0 + 8) * KS_PITCH + c + 4]);
        }
    }

    float o[4][4];
    #pragma unroll
    for (int nt = 0; nt < 4; nt++)
        #pragma unroll
        for (int r = 0; r < 4; r++) o[nt][r] = 0.f;
    float lsum0 = 0.f, lsum1 = 0.f;

    // bias+mask row pointers (rows padded to NP, cols padded to BMP; pads = 0)
    const float* bm0 = g_bm + ((size_t)(wi * NHEAD + h) * NP + i0 + w * 16 + lq) * BMP;
    const float* bm1 = bm0 + 8 * BMP;

    const float4* kg = (const float4*)(g_k + bh * NTOK * HD);
    const float*  vg = g_vt + bh * HD * NP;

    for (int jc = 0; jc < 6; jc++) {
        const int j0 = jc * 64;
        __syncthreads();
        // stage K chunk [64 j x 32 d], pitch 36
        for (int idx = tid; idx < 64 * 8; idx += 256) {
            int jl = idx >> 3, dq = idx & 7;
            int j = j0 + jl;
            float4 v = (j < NTOK) ? kg[j * 8 + dq] : make_float4(0.f, 0.f, 0.f, 0.f);
            *(float4*)&Ks[jl * KS_PITCH + dq * 4] = v;
        }
        // stage VT chunk [32 d x 64 j], pitch 68 (pad cols zero in g_vt)
        for (int idx = tid; idx < 32 * 16; idx += 256) {
            int d = idx >> 4, jq = idx & 15;
            float4 v = *(const float4*)(vg + (size_t)d * NP + j0 + jq * 4);
            *(float4*)&Vs[d * VS_PITCH + jq * 4] = v;
        }
        __syncthreads();

        const int colb = j0 + 2 * lr;
        // prefetch bm for nt-pair 0
        float2 nb00 = *(const float2*)(bm0 + colb);
        float2 nb01 = *(const float2*)(bm1 + colb);
        float2 nb10 = *(const float2*)(bm0 + colb + 8);
        float2 nb11 = *(const float2*)(bm1 + colb + 8);

        // S phase in nt-pairs (2 independent mma chains), fused softmax
        #pragma unroll
        for (int ntp = 0; ntp < 4; ntp++) {
            const int nt0 = 2 * ntp, nt1 = 2 * ntp + 1;
            float2 c00 = nb00, c01 = nb01, c10 = nb10, c11 = nb11;
            if (ntp < 3) {
                nb00 = *(const float2*)(bm0 + colb + (2 * ntp + 2) * 8);
                nb01 = *(const float2*)(bm1 + colb + (2 * ntp + 2) * 8);
                nb10 = *(const float2*)(bm0 + colb + (2 * ntp + 3) * 8);
                nb11 = *(const float2*)(bm1 + colb + (2 * ntp + 3) * 8);
            }
            float s0[4] = {0.f, 0.f, 0.f, 0.f};
            float s1[4] = {0.f, 0.f, 0.f, 0.f};
            #pragma unroll
            for (int ks = 0; ks < 4; ks++) {
                int kc = ks * 8 + lr;
                uint32_t b00 = __float_as_uint(Ks[(nt0 * 8 + lq) * KS_PITCH + kc]);
                uint32_t b01 = __float_as_uint(Ks[(nt0 * 8 + lq) * KS_PITCH + kc + 4]);
                uint32_t b10 = __float_as_uint(Ks[(nt1 * 8 + lq) * KS_PITCH + kc]);
                uint32_t b11 = __float_as_uint(Ks[(nt1 * 8 + lq) * KS_PITCH + kc + 4]);
                mma_tf32(s0, qf[ks], b00, b01);
                mma_tf32(s1, qf[ks], b10, b11);
            }
            #pragma unroll
            for (int half = 0; half < 2; half++) {
                const float* s = half ? s1 : s0;
                const float2 bml = half ? c10 : c00;
                const float2 bmh = half ? c11 : c01;
                const int nt = half ? nt1 : nt0;
                int cl = nt * 8 + 2 * lr;
                int jgl = j0 + cl;
                bool v0 = jgl < NTOK, v1 = (jgl + 1) < NTOK;
                float p00 = v0 ? __expf(s[0] + bml.x) : 0.f;
                float p01 = v1 ? __expf(s[1] + bml.y) : 0.f;
                float p10 = v0 ? __expf(s[2] + bmh.x) : 0.f;
                float p11 = v1 ? __expf(s[3] + bmh.y) : 0.f;
                lsum0 += p00 + p01;
                lsum1 += p10 + p11;
                float2 w0, w1;
                w0.x = __uint_as_float(tf32bits(p00));
                w0.y = __uint_as_float(tf32bits(p01));
                w1.x = __uint_as_float(tf32bits(p10));
                w1.y = __uint_as_float(tf32bits(p11));
                *(float2*)&Pw[lq * P_PITCH + cl] = w0;
                *(float2*)&Pw[(lq + 8) * P_PITCH + cl] = w1;
            }
        }
        __syncwarp();

        // O += P * V  (4 independent accumulation chains)
        #pragma unroll
        for (int ks = 0; ks < 8; ks++) {
            int kc = ks * 8 + lr;
            uint32_t a[4];
            a[0] = __float_as_uint(Pw[lq * P_PITCH + kc]);
            a[1] = __float_as_uint(Pw[(lq + 8) * P_PITCH + kc]);
            a[2] = __float_as_uint(Pw[lq * P_PITCH + kc + 4]);
            a[3] = __float_as_uint(Pw[(lq + 8) * P_PITCH + kc + 4]);
            #pragma unroll
            for (int nt = 0; nt < 4; nt++) {
                uint32_t b0 = __float_as_uint(Vs[(nt * 8 + lq) * VS_PITCH + kc]);
                uint32_t b1 = __float_as_uint(Vs[(nt * 8 + lq) * VS_PITCH + kc + 4]);
                mma_tf32(o[nt], a, b0, b1);
            }
        }
        __syncwarp();
    }

    // epilogue
    lsum0 += __shfl_xor_sync(0xffffffffu, lsum0, 1);
    lsum0 += __shfl_xor_sync(0xffffffffu, lsum0, 2);
    lsum1 += __shfl_xor_sync(0xffffffffu, lsum1, 1);
    lsum1 += __shfl_xor_sync(0xffffffffu, lsum1, 2);
    float inv0 = 1.f / lsum0;
    float inv1 = 1.f / lsum1;

    const int ir0 = m0 + lq;
    const int ir1 = ir0 + 8;
    if (ir0 < NTOK) {
        float* base = g_o + ((size_t)b * NTOK + ir0) * CDIM + h * HD;
        #pragma unroll
        for (int nt = 0; nt < 4; nt++) {
            float2 v; v.x = o[nt][0] * inv0; v.y = o[nt][1] * inv0;
            *(float2*)(base + nt * 8 + 2 * lr) = v;
        }
    }
    if (ir1 < NTOK) {
        float* base = g_o + ((size_t)b * NTOK + ir1) * CDIM + h * HD;
        #pragma unroll
        for (int nt = 0; nt < 4; nt++) {
            float2 v; v.x = o[nt][2] * inv1; v.y = o[nt][3] * inv1;
            *(float2*)(base + nt * 8 + 2 * lr) = v;
        }
    }
}

// ---------------------------------------------------------------------------
// Launch
// ---------------------------------------------------------------------------
extern "C" void kernel_launch(void* const* d_in, const int* in_sizes, int n_in,
                              void* d_out, int out_size)
{
    const float* x      = (const float*)d_in[0];
    const float* mask   = (const float*)d_in[1];
    const float* qkv_w  = (const float*)d_in[2];
    const float* qkv_b  = (const float*)d_in[3];
    const float* proj_w = (const float*)d_in[4];
    const float* proj_b = (const float*)d_in[5];
    const float* bt     = (const float*)d_in[6];
    const int*   rpi    = (const int*)d_in[7];
    float* out = (float*)d_out;

    cudaFuncSetAttribute(attn_mma_kernel,
                         cudaFuncAttributeMaxDynamicSharedMemorySize,
                         ATTN_SMEM_BYTES);

    bm_combine_kernel<<<dim3((NN + 255) / 256, NWIN, NHEAD), 256>>>(mask, bt, rpi);
    gemm_tc_kernel<0><<<dim3(9, 686), 256>>>(x, qkv_w, qkv_b, nullptr);
    attn_mma_kernel<<<dim3(48, NWIN, 3), 256, ATTN_SMEM_BYTES>>>();
    gemm_tc_kernel<1><<<dim3(3, 686), 256>>>(nullptr, proj_w, proj_b, out);
}

// round 9
// speedup vs baseline: 2.2414x; 1.1792x over previous
#include <cuda_runtime.h>
#include <cuda_bf16.h>
#include <cstdint>

// Problem constants
#define BATCH 512
#define NTOK  343
#define NP    384
#define CDIM  192
#define NHEAD 6
#define HD    32
#define NWIN  64
#define NN    (NTOK * NTOK)
#define BMP   384
#define SCALE 0.17677669529663687f
#define MROWS (BATCH * NTOK)           // 175616

// ---------------------------------------------------------------------------
// Scratch (device globals: allocation-free, zero-init; pads stay zero)
// ---------------------------------------------------------------------------
__device__ float g_q[BATCH * NHEAD * NTOK * HD];
__device__ float g_k[BATCH * NHEAD * NTOK * HD];
__device__ float g_vt[BATCH * NHEAD * HD * NP];
__device__ float g_o[BATCH * NTOK * CDIM];        // tf32-rounded by attention
__device__ float g_bm[NWIN * NHEAD * NP * BMP];
__device__ float g_xr[MROWS * CDIM];              // tf32-rounded x
__device__ float g_wr[CDIM * 3 * CDIM + CDIM * CDIM];  // rounded qkv_w | proj_w

__device__ __forceinline__ float tf32r(float x) {
    uint32_t b;
    asm("cvt.rna.tf32.f32 %0, %1;" : "=r"(b) : "f"(x));
    return __uint_as_float(b);
}
__device__ __forceinline__ uint32_t tf32bits(float x) {
    uint32_t b;
    asm("cvt.rna.tf32.f32 %0, %1;" : "=r"(b) : "f"(x));
    return b;
}
__device__ __forceinline__ void cpa16(void* smem_dst, const void* gmem_src) {
    uint32_t d = (uint32_t)__cvta_generic_to_shared(smem_dst);
    asm volatile("cp.async.cg.shared.global [%0], [%1], 16;" :: "r"(d), "l"(gmem_src));
}

// Warp-level tf32 MMA. Fragment layout (validated R3/R4).
__device__ __forceinline__ void mma_tf32(float c[4], const uint32_t a[4],
                                         uint32_t b0, uint32_t b1) {
    asm volatile(
        "mma.sync.aligned.m16n8k8.row.col.f32.tf32.tf32.f32 "
        "{%0,%1,%2,%3}, {%4,%5,%6,%7}, {%8,%9}, {%0,%1,%2,%3};"
        : "+f"(c[0]), "+f"(c[1]), "+f"(c[2]), "+f"(c[3])
        : "r"(a[0]), "r"(a[1]), "r"(a[2]), "r"(a[3]), "r"(b0), "r"(b1));
}

// ---------------------------------------------------------------------------
// Prepass: tf32-round x and weights into device globals
// ---------------------------------------------------------------------------
__global__ void round_x_kernel(const float* __restrict__ x)
{
    size_t i = (size_t)blockIdx.x * 256 + threadIdx.x;   // float4 index
    float4 v = ((const float4*)x)[i];
    v.x = tf32r(v.x); v.y = tf32r(v.y); v.z = tf32r(v.z); v.w = tf32r(v.w);
    ((float4*)g_xr)[i] = v;
}
__global__ void round_w_kernel(const float* __restrict__ qkv_w,
                               const float* __restrict__ proj_w)
{
    int i = blockIdx.x * 256 + threadIdx.x;              // float4 index
    const int nq = CDIM * 3 * CDIM / 4;                  // 27648
    float4 v;
    if (i < nq) v = ((const float4*)qkv_w)[i];
    else        v = ((const float4*)proj_w)[i - nq];
    v.x = tf32r(v.x); v.y = tf32r(v.y); v.z = tf32r(v.z); v.w = tf32r(v.w);
    ((float4*)g_wr)[i] = v;
}

// ---------------------------------------------------------------------------
// bm_combine: bias gather + mask -> g_bm (padded)
// ---------------------------------------------------------------------------
__global__ void bm_combine_kernel(const float* __restrict__ mask,
                                  const float* __restrict__ bt,
                                  const int* __restrict__ rpi)
{
    int ij = blockIdx.x * blockDim.x + threadIdx.x;
    if (ij >= NN) return;
    int w = blockIdx.y;
    int h = blockIdx.z;
    int i = ij / NTOK;
    int j = ij - i * NTOK;
    float v = bt[rpi[ij] * NHEAD + h] + mask[(size_t)w * NN + ij];
    g_bm[((size_t)(w * NHEAD + h) * NP + i) * BMP + j] = v;
}

// ---------------------------------------------------------------------------
// GEMM: CTA 256x64, warp 64x32, 3-stage cp.async pipeline, 1 barrier/slab.
// Inputs pre-rounded (g_xr/g_o, g_wr) -> no in-loop conversion.
//   MODE 0: A=g_xr, W=qkv part, scatter epilogue. MODE 1: A=g_o, W=proj -> Cout.
// ---------------------------------------------------------------------------
#define AS_P 20
#define WS_P 72
#define AS_SZ (256 * AS_P)
#define WS_SZ (16 * WS_P)

template <int MODE>
__global__ void __launch_bounds__(256, 2)
gemm_tc_kernel(const float* __restrict__ bias, float* __restrict__ Cout)
{
    constexpr int NC = (MODE == 0) ? 3 * CDIM : CDIM;
    const float* A = (MODE == 0) ? g_xr : g_o;
    const float* W = (MODE == 0) ? g_wr : (g_wr + CDIM * 3 * CDIM);

    __shared__ __align__(16) float As[3 * AS_SZ];
    __shared__ __align__(16) float Ws[3 * WS_SZ];

    const int tid  = threadIdx.x;
    const int w    = tid >> 5;
    const int lane = tid & 31;
    const int lq   = lane >> 2;
    const int lr   = lane & 3;
    const int wm   = w >> 1;
    const int wn   = w & 1;
    const int row0 = blockIdx.y * 256;
    const int c0   = blockIdx.x * 64;

    const int arq = tid >> 2;          // A row base (0..63), +64 per f
    const int akq = tid & 3;           // A col quad
    const int wc4 = tid & 15;
    const int wk  = tid >> 4;

    float acc[4][4][4];
    #pragma unroll
    for (int mi = 0; mi < 4; mi++)
        #pragma unroll
        for (int ni = 0; ni < 4; ni++)
            #pragma unroll
            for (int r = 0; r < 4; r++) acc[mi][ni][r] = 0.f;

    auto stage = [&](int kb) {
        const int buf = kb % 3;
        const int k0 = kb * 16;
        float* An = &As[buf * AS_SZ];
        float* Wn = &Ws[buf * WS_SZ];
        #pragma unroll
        for (int f = 0; f < 4; f++)
            cpa16(&An[(f * 64 + arq) * AS_P + akq * 4],
                  A + (size_t)(row0 + f * 64 + arq) * CDIM + k0 + akq * 4);
        cpa16(&Wn[wk * WS_P + wc4 * 4],
              W + (size_t)(k0 + wk) * NC + c0 + wc4 * 4);
        asm volatile("cp.async.commit_group;" ::: "memory");
    };

    stage(0);
    stage(1);

    for (int kb = 0; kb < 12; kb++) {
        if (kb < 11) asm volatile("cp.async.wait_group 1;" ::: "memory");
        else         asm volatile("cp.async.wait_group 0;" ::: "memory");
        __syncthreads();
        if (kb + 2 < 12) stage(kb + 2);   // overwrites buf computed at kb-1: safe past barrier

        const float* Ab = &As[(kb % 3) * AS_SZ];
        const float* Wb = &Ws[(kb % 3) * WS_SZ];
        #pragma unroll
        for (int ks = 0; ks < 2; ks++) {
            uint32_t bf[4][2];
            #pragma unroll
            for (int ni = 0; ni < 4; ni++) {
                int cc = wn * 32 + ni * 8 + lq;
                bf[ni][0] = __float_as_uint(Wb[(ks * 8 + lr) * WS_P + cc]);
                bf[ni][1] = __float_as_uint(Wb[(ks * 8 + lr + 4) * WS_P + cc]);
            }
            #pragma unroll
            for (int mi = 0; mi < 4; mi++) {
                int r0 = wm * 64 + mi * 16 + lq;
                uint32_t af[4];
                af[0] = __float_as_uint(Ab[r0 * AS_P + ks * 8 + lr]);
                af[1] = __float_as_uint(Ab[(r0 + 8) * AS_P + ks * 8 + lr]);
                af[2] = __float_as_uint(Ab[r0 * AS_P + ks * 8 + lr + 4]);
                af[3] = __float_as_uint(Ab[(r0 + 8) * AS_P + ks * 8 + lr + 4]);
                #pragma unroll
                for (int ni = 0; ni < 4; ni++)
                    mma_tf32(acc[mi][ni], af, bf[ni][0], bf[ni][1]);
            }
        }
    }

    // epilogue
    #pragma unroll
    for (int mi = 0; mi < 4; mi++) {
        int rlo = row0 + wm * 64 + mi * 16 + lq;
        int rhi = rlo + 8;
        int blo = rlo / NTOK, nlo = rlo - blo * NTOK;
        int bhi = rhi / NTOK, nhi = rhi - bhi * NTOK;
        #pragma unroll
        for (int ni = 0; ni < 4; ni++) {
            int c = c0 + wn * 32 + ni * 8 + 2 * lr;
            float b0 = bias[c], b1 = bias[c + 1];
            if (MODE == 0) {
                int s   = c / CDIM;
                int rem = c - s * CDIM;
                int hh  = rem >> 5;
                int dd  = rem & 31;
                if (s == 2) {
                    float* vlo = g_vt + (size_t)(blo * NHEAD + hh) * HD * NP;
                    float* vhi = g_vt + (size_t)(bhi * NHEAD + hh) * HD * NP;
                    vlo[(size_t)dd * NP + nlo]       = tf32r(acc[mi][ni][0] + b0);
                    vlo[(size_t)(dd + 1) * NP + nlo] = tf32r(acc[mi][ni][1] + b1);
                    vhi[(size_t)dd * NP + nhi]       = tf32r(acc[mi][ni][2] + b0);
                    vhi[(size_t)(dd + 1) * NP + nhi] = tf32r(acc[mi][ni][3] + b1);
                } else {
                    float sc = (s == 0) ? SCALE : 1.f;
                    float* dst = (s == 0) ? g_q : g_k;
                    float2 vl, vh;
                    vl.x = tf32r((acc[mi][ni][0] + b0) * sc);
                    vl.y = tf32r((acc[mi][ni][1] + b1) * sc);
                    vh.x = tf32r((acc[mi][ni][2] + b0) * sc);
                    vh.y = tf32r((acc[mi][ni][3] + b1) * sc);
                    *(float2*)&dst[((size_t)(blo * NHEAD + hh) * NTOK + nlo) * HD + dd] = vl;
                    *(float2*)&dst[((size_t)(bhi * NHEAD + hh) * NTOK + nhi) * HD + dd] = vh;
                }
            } else {
                float2 vl, vh;
                vl.x = acc[mi][ni][0] + b0; vl.y = acc[mi][ni][1] + b1;
                vh.x = acc[mi][ni][2] + b0; vh.y = acc[mi][ni][3] + b1;
                *(float2*)&Cout[(size_t)rlo * CDIM + c] = vl;
                *(float2*)&Cout[(size_t)rhi * CDIM + c] = vh;
            }
        }
    }
}

// ---------------------------------------------------------------------------
// Attention (R8 structure, unchanged except epilogue tf32-rounds g_o).
// 1 batch/CTA, no BM smem (reg-prefetched LDGs), 53 KB smem -> 3 CTAs/SM.
// ---------------------------------------------------------------------------
#define KS_PITCH 36
#define VS_PITCH 68
#define P_PITCH  68
#define OFF_KS 0
#define OFF_VS (OFF_KS + 64 * KS_PITCH)
#define OFF_P  (OFF_VS + 32 * VS_PITCH)
#define ATTN_SMEM_FLOATS (OFF_P + 128 * P_PITCH)
#define ATTN_SMEM_BYTES  (ATTN_SMEM_FLOATS * 4)

__global__ void __launch_bounds__(256, 3)
attn_mma_kernel()
{
    const int bg  = blockIdx.x & 7;
    const int h   = blockIdx.x >> 3;
    const int wi  = blockIdx.y;
    const int mt  = blockIdx.z;
    const int b   = wi + NWIN * bg;
    const int tid = threadIdx.x;
    const int w   = tid >> 5;
    const int lane = tid & 31;
    const int lq  = lane >> 2;
    const int lr  = lane & 3;

    extern __shared__ float sm[];
    float* Ks = sm + OFF_KS;
    float* Vs = sm + OFF_VS;
    float* Pw = sm + OFF_P + w * 16 * P_PITCH;

    const int i0 = mt * 128;
    const int m0 = i0 + w * 16;
    const size_t bh = (size_t)(b * NHEAD + h);

    uint32_t qf[4][4];
    {
        float* Qs = sm + OFF_P;
        const float4* qg = (const float4*)(g_q + bh * NTOK * HD);
        for (int idx = tid; idx < 128 * 8; idx += 256) {
            int r = idx >> 3, dq = idx & 7;
            int i = i0 + r;
            float4 v = (i < NTOK) ? qg[i * 8 + dq] : make_float4(0.f, 0.f, 0.f, 0.f);
            *(float4*)&Qs[r * KS_PITCH + dq * 4] = v;
        }
        __syncthreads();
        const int r0 = w * 16 + lq;
        #pragma unroll
        for (int ks = 0; ks < 4; ks++) {
            int c = ks * 8 + lr;
            qf[ks][0] = __float_as_uint(Qs[r0 * KS_PITCH + c]);
            qf[ks][1] = __float_as_uint(Qs[(r0 + 8) * KS_PITCH + c]);
            qf[ks][2] = __float_as_uint(Qs[r0 * KS_PITCH + c + 4]);
            qf[ks][3] = __float_as_uint(Qs[(r0 + 8) * KS_PITCH + c + 4]);
        }
    }

    float o[4][4];
    #pragma unroll
    for (int nt = 0; nt < 4; nt++)
        #pragma unroll
        for (int r = 0; r < 4; r++) o[nt][r] = 0.f;
    float lsum0 = 0.f, lsum1 = 0.f;

    const float* bm0 = g_bm + ((size_t)(wi * NHEAD + h) * NP + i0 + w * 16 + lq) * BMP;
    const float* bm1 = bm0 + 8 * BMP;

    const float4* kg = (const float4*)(g_k + bh * NTOK * HD);
    const float*  vg = g_vt + bh * HD * NP;

    for (int jc = 0; jc < 6; jc++) {
        const int j0 = jc * 64;
        __syncthreads();
        for (int idx = tid; idx < 64 * 8; idx += 256) {
            int jl = idx >> 3, dq = idx & 7;
            int j = j0 + jl;
            float4 v = (j < NTOK) ? kg[j * 8 + dq] : make_float4(0.f, 0.f, 0.f, 0.f);
            *(float4*)&Ks[jl * KS_PITCH + dq * 4] = v;
        }
        for (int idx = tid; idx < 32 * 16; idx += 256) {
            int d = idx >> 4, jq = idx & 15;
            float4 v = *(const float4*)(vg + (size_t)d * NP + j0 + jq * 4);
            *(float4*)&Vs[d * VS_PITCH + jq * 4] = v;
        }
        __syncthreads();

        const int colb = j0 + 2 * lr;
        float2 nb00 = *(const float2*)(bm0 + colb);
        float2 nb01 = *(const float2*)(bm1 + colb);
        float2 nb10 = *(const float2*)(bm0 + colb + 8);
        float2 nb11 = *(const float2*)(bm1 + colb + 8);

        #pragma unroll
        for (int ntp = 0; ntp < 4; ntp++) {
            const int nt0 = 2 * ntp, nt1 = 2 * ntp + 1;
            float2 c00 = nb00, c01 = nb01, c10 = nb10, c11 = nb11;
            if (ntp < 3) {
                nb00 = *(const float2*)(bm0 + colb + (2 * ntp + 2) * 8);
                nb01 = *(const float2*)(bm1 + colb + (2 * ntp + 2) * 8);
                nb10 = *(const float2*)(bm0 + colb + (2 * ntp + 3) * 8);
                nb11 = *(const float2*)(bm1 + colb + (2 * ntp + 3) * 8);
            }
            float s0[4] = {0.f, 0.f, 0.f, 0.f};
            float s1[4] = {0.f, 0.f, 0.f, 0.f};
            #pragma unroll
            for (int ks = 0; ks < 4; ks++) {
                int kc = ks * 8 + lr;
                uint32_t b00 = __float_as_uint(Ks[(nt0 * 8 + lq) * KS_PITCH + kc]);
                uint32_t b01 = __float_as_uint(Ks[(nt0 * 8 + lq) * KS_PITCH + kc + 4]);
                uint32_t b10 = __float_as_uint(Ks[(nt1 * 8 + lq) * KS_PITCH + kc]);
                uint32_t b11 = __float_as_uint(Ks[(nt1 * 8 + lq) * KS_PITCH + kc + 4]);
                mma_tf32(s0, qf[ks], b00, b01);
                mma_tf32(s1, qf[ks], b10, b11);
            }
            #pragma unroll
            for (int half = 0; half < 2; half++) {
                const float* s = half ? s1 : s0;
                const float2 bml = half ? c10 : c00;
                const float2 bmh = half ? c11 : c01;
                const int nt = half ? nt1 : nt0;
                int cl = nt * 8 + 2 * lr;
                int jgl = j0 + cl;
                bool v0 = jgl < NTOK, v1 = (jgl + 1) < NTOK;
                float p00 = v0 ? __expf(s[0] + bml.x) : 0.f;
                float p01 = v1 ? __expf(s[1] + bml.y) : 0.f;
                float p10 = v0 ? __expf(s[2] + bmh.x) : 0.f;
                float p11 = v1 ? __expf(s[3] + bmh.y) : 0.f;
                lsum0 += p00 + p01;
                lsum1 += p10 + p11;
                float2 w0, w1;
                w0.x = __uint_as_float(tf32bits(p00));
                w0.y = __uint_as_float(tf32bits(p01));
                w1.x = __uint_as_float(tf32bits(p10));
                w1.y = __uint_as_float(tf32bits(p11));
                *(float2*)&Pw[lq * P_PITCH + cl] = w0;
                *(float2*)&Pw[(lq + 8) * P_PITCH + cl] = w1;
            }
        }
        __syncwarp();

        #pragma unroll
        for (int ks = 0; ks < 8; ks++) {
            int kc = ks * 8 + lr;
            uint32_t a[4];
            a[0] = __float_as_uint(Pw[lq * P_PITCH + kc]);
            a[1] = __float_as_uint(Pw[(lq + 8) * P_PITCH + kc]);
            a[2] = __float_as_uint(Pw[lq * P_PITCH + kc + 4]);
            a[3] = __float_as_uint(Pw[(lq + 8) * P_PITCH + kc + 4]);
            #pragma unroll
            for (int nt = 0; nt < 4; nt++) {
                uint32_t b0 = __float_as_uint(Vs[(nt * 8 + lq) * VS_PITCH + kc]);
                uint32_t b1 = __float_as_uint(Vs[(nt * 8 + lq) * VS_PITCH + kc + 4]);
                mma_tf32(o[nt], a, b0, b1);
            }
        }
        __syncwarp();
    }

    lsum0 += __shfl_xor_sync(0xffffffffu, lsum0, 1);
    lsum0 += __shfl_xor_sync(0xffffffffu, lsum0, 2);
    lsum1 += __shfl_xor_sync(0xffffffffu, lsum1, 1);
    lsum1 += __shfl_xor_sync(0xffffffffu, lsum1, 2);
    float inv0 = 1.f / lsum0;
    float inv1 = 1.f / lsum1;

    const int ir0 = m0 + lq;
    const int ir1 = ir0 + 8;
    if (ir0 < NTOK) {
        float* base = g_o + ((size_t)b * NTOK + ir0) * CDIM + h * HD;
        #pragma unroll
        for (int nt = 0; nt < 4; nt++) {
            float2 v;
            v.x = tf32r(o[nt][0] * inv0);
            v.y = tf32r(o[nt][1] * inv0);
            *(float2*)(base + nt * 8 + 2 * lr) = v;
        }
    }
    if (ir1 < NTOK) {
        float* base = g_o + ((size_t)b * NTOK + ir1) * CDIM + h * HD;
        #pragma unroll
        for (int nt = 0; nt < 4; nt++) {
            float2 v;
            v.x = tf32r(o[nt][2] * inv1);
            v.y = tf32r(o[nt][3] * inv1);
            *(float2*)(base + nt * 8 + 2 * lr) = v;
        }
    }
}

// ---------------------------------------------------------------------------
// Launch
// ---------------------------------------------------------------------------
extern "C" void kernel_launch(void* const* d_in, const int* in_sizes, int n_in,
                              void* d_out, int out_size)
{
    const float* x      = (const float*)d_in[0];
    const float* mask   = (const float*)d_in[1];
    const float* qkv_w  = (const float*)d_in[2];
    const float* qkv_b  = (const float*)d_in[3];
    const float* proj_w = (const float*)d_in[4];
    const float* proj_b = (const float*)d_in[5];
    const float* bt     = (const float*)d_in[6];
    const int*   rpi    = (const int*)d_in[7];
    float* out = (float*)d_out;

    cudaFuncSetAttribute(attn_mma_kernel,
                         cudaFuncAttributeMaxDynamicSharedMemorySize,
                         ATTN_SMEM_BYTES);

    round_x_kernel<<<MROWS * CDIM / 4 / 256, 256>>>(x);
    round_w_kernel<<<(CDIM * 3 * CDIM + CDIM * CDIM) / 4 / 256, 256>>>(qkv_w, proj_w);
    bm_combine_kernel<<<dim3((NN + 255) / 256, NWIN, NHEAD), 256>>>(mask, bt, rpi);
    gemm_tc_kernel<0><<<dim3(9, 686), 256>>>(qkv_b, nullptr);
    attn_mma_kernel<<<dim3(48, NWIN, 3), 256, ATTN_SMEM_BYTES>>>();
    gemm_tc_kernel<1><<<dim3(3, 686), 256>>>(proj_b, out);
}

// round 11
// speedup vs baseline: 3.6247x; 1.6172x over previous
#include <cuda_runtime.h>
#include <cuda_fp16.h>
#include <cstdint>

// Problem constants
#define BATCH 512
#define NTOK  343
#define NP    384
#define CDIM  192
#define NHEAD 6
#define HD    32
#define NWIN  64
#define NN    (NTOK * NTOK)
#define BMP   384                  // g_bm row pitch (halves)
#define SCALE 0.17677669529663687f
#define MROWS (BATCH * NTOK)       // 175616
#define ESHIFT 10.0f

// ---------------------------------------------------------------------------
// Scratch (device globals: allocation-free, zero-init; pads stay zero halves)
// ---------------------------------------------------------------------------
__device__ __half g_q[BATCH * NHEAD * NTOK * HD];     // pre-scaled
__device__ __half g_k[BATCH * NHEAD * NTOK * HD];
__device__ __half g_vt[BATCH * NHEAD * HD * NP];      // transposed, pads zero
__device__ __half g_o[BATCH * NTOK * CDIM];
__device__ __half g_bm[NWIN * NHEAD * NP * BMP];      // bias+mask
__device__ __half g_xh[MROWS * CDIM];                 // x in half
__device__ __half g_wt[3 * CDIM * CDIM + CDIM * CDIM]; // qkv_w^T | proj_w^T ([n][k])

__device__ __forceinline__ void cpa16(void* smem_dst, const void* gmem_src) {
    uint32_t d = (uint32_t)__cvta_generic_to_shared(smem_dst);
    asm volatile("cp.async.cg.shared.global [%0], [%1], 16;" :: "r"(d), "l"(gmem_src));
}

// fp16 MMA m16n8k16, fp32 accum. Fragment layout:
//  A: a0=(m=lq,k=2lr..2lr+1) a1=(m=lq+8,same) a2=(m=lq,k=2lr+8..9) a3=(m=lq+8,..)
//  B: b0=(n=lq,k=2lr..2lr+1) b1=(n=lq,k=2lr+8..9)
//  C: c0=(m=lq,n=2lr) c1=(m=lq,n=2lr+1) c2=(m=lq+8,n=2lr) c3=(m=lq+8,n=2lr+1)
__device__ __forceinline__ void mma_f16(float c[4], const uint32_t a[4],
                                        uint32_t b0, uint32_t b1) {
    asm volatile(
        "mma.sync.aligned.m16n8k16.row.col.f32.f16.f16.f32 "
        "{%0,%1,%2,%3}, {%4,%5,%6,%7}, {%8,%9}, {%0,%1,%2,%3};"
        : "+f"(c[0]), "+f"(c[1]), "+f"(c[2]), "+f"(c[3])
        : "r"(a[0]), "r"(a[1]), "r"(a[2]), "r"(a[3]), "r"(b0), "r"(b1));
}

// ---------------------------------------------------------------------------
// Prepass kernels
// ---------------------------------------------------------------------------
__global__ void round_x_kernel(const float* __restrict__ x)
{
    size_t i = (size_t)blockIdx.x * 256 + threadIdx.x;   // float4 index
    float4 v = ((const float4*)x)[i];
    __half2* dst = (__half2*)g_xh;
    dst[2 * i]     = __floats2half2_rn(v.x, v.y);
    dst[2 * i + 1] = __floats2half2_rn(v.z, v.w);
}
__global__ void round_wt_kernel(const float* __restrict__ qkv_w,
                                const float* __restrict__ proj_w)
{
    int idx = blockIdx.x * 256 + threadIdx.x;            // element in g_wt
    const int nq = 3 * CDIM * CDIM;                      // 110592
    float v;
    if (idx < nq) {
        int c = idx / CDIM, k = idx - c * CDIM;
        v = qkv_w[k * (3 * CDIM) + c];
    } else {
        int i2 = idx - nq;
        int c = i2 / CDIM, k = i2 - c * CDIM;
        v = proj_w[k * CDIM + c];
    }
    g_wt[idx] = __float2half_rn(v);
}
__global__ void bm_combine_kernel(const float* __restrict__ mask,
                                  const float* __restrict__ bt,
                                  const int* __restrict__ rpi)
{
    int ij = blockIdx.x * blockDim.x + threadIdx.x;
    if (ij >= NN) return;
    int w = blockIdx.y;
    int h = blockIdx.z;
    int i = ij / NTOK;
    int j = ij - i * NTOK;
    float v = bt[rpi[ij] * NHEAD + h] + mask[(size_t)w * NN + ij];
    g_bm[((size_t)(w * NHEAD + h) * NP + i) * BMP + j] = __float2half_rn(v);
}

// ---------------------------------------------------------------------------
// GEMM: fp16 mma, CTA 256x64, warp 64x32, K-slab 32, 3-stage cp.async.
//   MODE 0: A=g_xh, W=qkv^T, scatter into g_q/g_k/g_vt (half).
//   MODE 1: A=g_o,  W=proj^T -> Cout (fp32 + bias).
// smem pitches in HALVES: As 40, Ws 40 (both conflict-free for frag loads).
// ---------------------------------------------------------------------------
#define AS_P 40
#define WS_P 40
#define AS_SZ (256 * AS_P)
#define WS_SZ (64 * WS_P)

template <int MODE>
__global__ void __launch_bounds__(256, 2)
gemm_tc_kernel(const float* __restrict__ bias, float* __restrict__ Cout)
{
    constexpr int NC = (MODE == 0) ? 3 * CDIM : CDIM;
    const __half* A = (MODE == 0) ? g_xh : g_o;
    const __half* W = (MODE == 0) ? g_wt : (g_wt + 3 * CDIM * CDIM);

    __shared__ __align__(16) __half As[3 * AS_SZ];
    __shared__ __align__(16) __half Ws[3 * WS_SZ];

    const int tid  = threadIdx.x;
    const int w    = tid >> 5;
    const int lane = tid & 31;
    const int lq   = lane >> 2;
    const int lr   = lane & 3;
    const int wm   = w >> 1;
    const int wn   = w & 1;
    const int row0 = blockIdx.y * 256;
    const int c0   = blockIdx.x * 64;

    const int arq = tid >> 2;          // A row base (0..63), +64 per f
    const int aq  = tid & 3;           // 8-half quad within the 32-half row
    const int wcq = tid >> 2;          // W col (0..63)
    const int wq  = tid & 3;

    float acc[4][4][4];
    #pragma unroll
    for (int mi = 0; mi < 4; mi++)
        #pragma unroll
        for (int ni = 0; ni < 4; ni++)
            #pragma unroll
            for (int r = 0; r < 4; r++) acc[mi][ni][r] = 0.f;

    auto stage = [&](int kb) {
        const int buf = kb % 3;
        const int k0 = kb * 32;
        __half* An = &As[buf * AS_SZ];
        __half* Wn = &Ws[buf * WS_SZ];
        #pragma unroll
        for (int f = 0; f < 4; f++)
            cpa16(&An[(f * 64 + arq) * AS_P + aq * 8],
                  A + (size_t)(row0 + f * 64 + arq) * CDIM + k0 + aq * 8);
        cpa16(&Wn[wcq * WS_P + wq * 8],
              W + (size_t)(c0 + wcq) * CDIM + k0 + wq * 8);
        asm volatile("cp.async.commit_group;" ::: "memory");
    };

    stage(0);
    stage(1);

    for (int kb = 0; kb < 6; kb++) {
        if (kb < 5) asm volatile("cp.async.wait_group 1;" ::: "memory");
        else        asm volatile("cp.async.wait_group 0;" ::: "memory");
        __syncthreads();
        if (kb + 2 < 6) stage(kb + 2);

        const __half* Ab = &As[(kb % 3) * AS_SZ];
        const __half* Wb = &Ws[(kb % 3) * WS_SZ];
        #pragma unroll
        for (int ks = 0; ks < 2; ks++) {
            const int kc = ks * 16 + 2 * lr;
            uint32_t bf[4][2];
            #pragma unroll
            for (int ni = 0; ni < 4; ni++) {
                int cc = wn * 32 + ni * 8 + lq;
                bf[ni][0] = *(const uint32_t*)&Wb[cc * WS_P + kc];
                bf[ni][1] = *(const uint32_t*)&Wb[cc * WS_P + kc + 8];
            }
            #pragma unroll
            for (int mi = 0; mi < 4; mi++) {
                int r0 = wm * 64 + mi * 16 + lq;
                uint32_t af[4];
                af[0] = *(const uint32_t*)&Ab[r0 * AS_P + kc];
                af[1] = *(const uint32_t*)&Ab[(r0 + 8) * AS_P + kc];
                af[2] = *(const uint32_t*)&Ab[r0 * AS_P + kc + 8];
                af[3] = *(const uint32_t*)&Ab[(r0 + 8) * AS_P + kc + 8];
                #pragma unroll
                for (int ni = 0; ni < 4; ni++)
                    mma_f16(acc[mi][ni], af, bf[ni][0], bf[ni][1]);
            }
        }
    }

    // epilogue
    #pragma unroll
    for (int mi = 0; mi < 4; mi++) {
        int rlo = row0 + wm * 64 + mi * 16 + lq;
        int rhi = rlo + 8;
        int blo = rlo / NTOK, nlo = rlo - blo * NTOK;
        int bhi = rhi / NTOK, nhi = rhi - bhi * NTOK;
        #pragma unroll
        for (int ni = 0; ni < 4; ni++) {
            int c = c0 + wn * 32 + ni * 8 + 2 * lr;
            float b0 = bias[c], b1 = bias[c + 1];
            if (MODE == 0) {
                int s   = c / CDIM;
                int rem = c - s * CDIM;
                int hh  = rem >> 5;
                int dd  = rem & 31;
                if (s == 2) {
                    __half* vlo = g_vt + (size_t)(blo * NHEAD + hh) * HD * NP;
                    __half* vhi = g_vt + (size_t)(bhi * NHEAD + hh) * HD * NP;
                    vlo[(size_t)dd * NP + nlo]       = __float2half_rn(acc[mi][ni][0] + b0);
                    vlo[(size_t)(dd + 1) * NP + nlo] = __float2half_rn(acc[mi][ni][1] + b1);
                    vhi[(size_t)dd * NP + nhi]       = __float2half_rn(acc[mi][ni][2] + b0);
                    vhi[(size_t)(dd + 1) * NP + nhi] = __float2half_rn(acc[mi][ni][3] + b1);
                } else {
                    float sc = (s == 0) ? SCALE : 1.f;
                    __half* dst = (s == 0) ? g_q : g_k;
                    *(__half2*)&dst[((size_t)(blo * NHEAD + hh) * NTOK + nlo) * HD + dd] =
                        __floats2half2_rn((acc[mi][ni][0] + b0) * sc, (acc[mi][ni][1] + b1) * sc);
                    *(__half2*)&dst[((size_t)(bhi * NHEAD + hh) * NTOK + nhi) * HD + dd] =
                        __floats2half2_rn((acc[mi][ni][2] + b0) * sc, (acc[mi][ni][3] + b1) * sc);
                }
            } else {
                float2 vl, vh;
                vl.x = acc[mi][ni][0] + b0; vl.y = acc[mi][ni][1] + b1;
                vh.x = acc[mi][ni][2] + b0; vh.y = acc[mi][ni][3] + b1;
                *(float2*)&Cout[(size_t)rlo * CDIM + c] = vl;
                *(float2*)&Cout[(size_t)rhi * CDIM + c] = vh;
            }
        }
    }
}

// ---------------------------------------------------------------------------
// Attention: fp16 mma, 1 batch/CTA, no BM smem (half LDGs), ~28 KB smem.
// Grid (48, NWIN, 3): x = bg + 8*h; b = wi + 64*bg; z = m-tile of 128.
// Pitches (halves): Ks 40, Vs 72, Pw 72. All frag accesses conflict-free.
// ---------------------------------------------------------------------------
#define KS_P 40
#define VS_P 72
#define P_P  72
#define OFF_KS 0
#define OFF_VS (OFF_KS + 64 * KS_P)               // 2560 halves
#define OFF_P  (OFF_VS + 32 * VS_P)               // 4864
#define ATTN_SMEM_HALVES (OFF_P + 128 * P_P)      // 14080
#define ATTN_SMEM_BYTES  (ATTN_SMEM_HALVES * 2)   // 28160

__global__ void __launch_bounds__(256, 3)
attn_mma_kernel()
{
    const int bg  = blockIdx.x & 7;
    const int h   = blockIdx.x >> 3;
    const int wi  = blockIdx.y;
    const int mt  = blockIdx.z;
    const int b   = wi + NWIN * bg;
    const int tid = threadIdx.x;
    const int w   = tid >> 5;
    const int lane = tid & 31;
    const int lq  = lane >> 2;
    const int lr  = lane & 3;

    extern __shared__ __half smh[];
    __half* Ks = smh + OFF_KS;
    __half* Vs = smh + OFF_VS;
    __half* Pw = smh + OFF_P + w * 16 * P_P;

    const int i0 = mt * 128;
    const int m0 = i0 + w * 16;
    const size_t bh = (size_t)(b * NHEAD + h);

    // --- load Q fragments (stage via P region, pitch 40)
    uint32_t qf[2][4];
    {
        __half* Qs = smh + OFF_P;
        const uint4* qg = (const uint4*)(g_q + bh * NTOK * HD);   // 4 uint4/row
        for (int idx = tid; idx < 128 * 4; idx += 256) {
            int r = idx >> 2, q = idx & 3;
            int i = i0 + r;
            uint4 v = (i < NTOK) ? qg[i * 4 + q] : make_uint4(0, 0, 0, 0);
            *(uint4*)&Qs[r * KS_P + q * 8] = v;
        }
        __syncthreads();
        const int r0 = w * 16 + lq;
        #pragma unroll
        for (int ks = 0; ks < 2; ks++) {
            int kc = ks * 16 + 2 * lr;
            qf[ks][0] = *(const uint32_t*)&Qs[r0 * KS_P + kc];
            qf[ks][1] = *(const uint32_t*)&Qs[(r0 + 8) * KS_P + kc];
            qf[ks][2] = *(const uint32_t*)&Qs[r0 * KS_P + kc + 8];
            qf[ks][3] = *(const uint32_t*)&Qs[(r0 + 8) * KS_P + kc + 8];
        }
    }

    float o[4][4];
    #pragma unroll
    for (int nt = 0; nt < 4; nt++)
        #pragma unroll
        for (int r = 0; r < 4; r++) o[nt][r] = 0.f;
    float lsum0 = 0.f, lsum1 = 0.f;

    const __half* bm0 = g_bm + ((size_t)(wi * NHEAD + h) * NP + i0 + w * 16 + lq) * BMP;
    const __half* bm1 = bm0 + 8 * BMP;

    const uint4* kg = (const uint4*)(g_k + bh * NTOK * HD);
    const __half* vg = g_vt + bh * HD * NP;

    for (int jc = 0; jc < 6; jc++) {
        const int j0 = jc * 64;
        __syncthreads();
        // stage K chunk [64 j x 32 d]: 1 uint4 per thread
        {
            int jl = tid >> 2, q = tid & 3;
            int j = j0 + jl;
            uint4 v = (j < NTOK) ? kg[j * 4 + q] : make_uint4(0, 0, 0, 0);
            *(uint4*)&Ks[jl * KS_P + q * 8] = v;
        }
        // stage VT chunk [32 d x 64 j]: 1 uint4 per thread (pads zero in g_vt)
        {
            int d = tid >> 3, q = tid & 7;
            uint4 v = *(const uint4*)(vg + (size_t)d * NP + j0 + q * 8);
            *(uint4*)&Vs[d * VS_P + q * 8] = v;
        }
        __syncthreads();

        const int colb = j0 + 2 * lr;
        __half2 nb00 = *(const __half2*)(bm0 + colb);
        __half2 nb01 = *(const __half2*)(bm1 + colb);
        __half2 nb10 = *(const __half2*)(bm0 + colb + 8);
        __half2 nb11 = *(const __half2*)(bm1 + colb + 8);

        // S phase in nt-pairs (2 independent chains), fused softmax, P->Pw fp16
        #pragma unroll
        for (int ntp = 0; ntp < 4; ntp++) {
            const int nt0 = 2 * ntp, nt1 = 2 * ntp + 1;
            float2 c00 = __half22float2(nb00), c01 = __half22float2(nb01);
            float2 c10 = __half22float2(nb10), c11 = __half22float2(nb11);
            if (ntp < 3) {
                nb00 = *(const __half2*)(bm0 + colb + (2 * ntp + 2) * 8);
                nb01 = *(const __half2*)(bm1 + colb + (2 * ntp + 2) * 8);
                nb10 = *(const __half2*)(bm0 + colb + (2 * ntp + 3) * 8);
                nb11 = *(const __half2*)(bm1 + colb + (2 * ntp + 3) * 8);
            }
            float s0[4] = {0.f, 0.f, 0.f, 0.f};
            float s1[4] = {0.f, 0.f, 0.f, 0.f};
            #pragma unroll
            for (int ks = 0; ks < 2; ks++) {
                int kc = ks * 16 + 2 * lr;
                uint32_t b00 = *(const uint32_t*)&Ks[(nt0 * 8 + lq) * KS_P + kc];
                uint32_t b01 = *(const uint32_t*)&Ks[(nt0 * 8 + lq) * KS_P + kc + 8];
                uint32_t b10 = *(const uint32_t*)&Ks[(nt1 * 8 + lq) * KS_P + kc];
                uint32_t b11 = *(const uint32_t*)&Ks[(nt1 * 8 + lq) * KS_P + kc + 8];
                mma_f16(s0, qf[ks], b00, b01);
                mma_f16(s1, qf[ks], b10, b11);
            }
            #pragma unroll
            for (int half = 0; half < 2; half++) {
                const float* s = half ? s1 : s0;
                const float2 bml = half ? c10 : c00;
                const float2 bmh = half ? c11 : c01;
                const int nt = half ? nt1 : nt0;
                int cl = nt * 8 + 2 * lr;
                int jgl = j0 + cl;
                bool v0 = jgl < NTOK, v1 = (jgl + 1) < NTOK;
                float p00 = v0 ? __expf(s[0] + bml.x - ESHIFT) : 0.f;
                float p01 = v1 ? __expf(s[1] + bml.y - ESHIFT) : 0.f;
                float p10 = v0 ? __expf(s[2] + bmh.x - ESHIFT) : 0.f;
                float p11 = v1 ? __expf(s[3] + bmh.y - ESHIFT) : 0.f;
                lsum0 += p00 + p01;
                lsum1 += p10 + p11;
                *(__half2*)&Pw[lq * P_P + cl]       = __floats2half2_rn(p00, p01);
                *(__half2*)&Pw[(lq + 8) * P_P + cl] = __floats2half2_rn(p10, p11);
            }
        }
        __syncwarp();

        // O += P * V  (k = 64 per chunk -> 4 fp16 mma steps, 4 indep chains)
        #pragma unroll
        for (int ks = 0; ks < 4; ks++) {
            int kc = ks * 16 + 2 * lr;
            uint32_t a[4];
            a[0] = *(const uint32_t*)&Pw[lq * P_P + kc];
            a[1] = *(const uint32_t*)&Pw[(lq + 8) * P_P + kc];
            a[2] = *(const uint32_t*)&Pw[lq * P_P + kc + 8];
            a[3] = *(const uint32_t*)&Pw[(lq + 8) * P_P + kc + 8];
            #pragma unroll
            for (int nt = 0; nt < 4; nt++) {
                uint32_t b0 = *(const uint32_t*)&Vs[(nt * 8 + lq) * VS_P + kc];
                uint32_t b1 = *(const uint32_t*)&Vs[(nt * 8 + lq) * VS_P + kc + 8];
                mma_f16(o[nt], a, b0, b1);
            }
        }
        __syncwarp();
    }

    // epilogue
    lsum0 += __shfl_xor_sync(0xffffffffu, lsum0, 1);
    lsum0 += __shfl_xor_sync(0xffffffffu, lsum0, 2);
    lsum1 += __shfl_xor_sync(0xffffffffu, lsum1, 1);
    lsum1 += __shfl_xor_sync(0xffffffffu, lsum1, 2);
    float inv0 = 1.f / lsum0;
    float inv1 = 1.f / lsum1;

    const int ir0 = m0 + lq;
    const int ir1 = ir0 + 8;
    if (ir0 < NTOK) {
        __half* base = g_o + ((size_t)b * NTOK + ir0) * CDIM + h * HD;
        #pragma unroll
        for (int nt = 0; nt < 4; nt++)
            *(__half2*)(base + nt * 8 + 2 * lr) =
                __floats2half2_rn(o[nt][0] * inv0, o[nt][1] * inv0);
    }
    if (ir1 < NTOK) {
        __half* base = g_o + ((size_t)b * NTOK + ir1) * CDIM + h * HD;
        #pragma unroll
        for (int nt = 0; nt < 4; nt++)
            *(__half2*)(base + nt * 8 + 2 * lr) =
                __floats2half2_rn(o[nt][2] * inv1, o[nt][3] * inv1);
    }
}

// ---------------------------------------------------------------------------
// Launch
// ---------------------------------------------------------------------------
extern "C" void kernel_launch(void* const* d_in, const int* in_sizes, int n_in,
                              void* d_out, int out_size)
{
    const float* x      = (const float*)d_in[0];
    const float* mask   = (const float*)d_in[1];
    const float* qkv_w  = (const float*)d_in[2];
    const float* qkv_b  = (const float*)d_in[3];
    const float* proj_w = (const float*)d_in[4];
    const float* proj_b = (const float*)d_in[5];
    const float* bt     = (const float*)d_in[6];
    const int*   rpi    = (const int*)d_in[7];
    float* out = (float*)d_out;

    cudaFuncSetAttribute(attn_mma_kernel,
                         cudaFuncAttributeMaxDynamicSharedMemorySize,
                         ATTN_SMEM_BYTES);

    round_x_kernel<<<MROWS * CDIM / 4 / 256, 256>>>(x);
    round_wt_kernel<<<(3 * CDIM * CDIM + CDIM * CDIM) / 256, 256>>>(qkv_w, proj_w);
    bm_combine_kernel<<<dim3((NN + 255) / 256, NWIN, NHEAD), 256>>>(mask, bt, rpi);
    gemm_tc_kernel<0><<<dim3(9, 686), 256>>>(qkv_b, nullptr);
    attn_mma_kernel<<<dim3(48, NWIN, 3), 256, ATTN_SMEM_BYTES>>>();
    gemm_tc_kernel<1><<<dim3(3, 686), 256>>>(proj_b, out);
}

// round 15
// speedup vs baseline: 4.0482x; 1.1168x over previous
#include <cuda_runtime.h>
#include <cuda_fp16.h>
#include <cstdint>

// Problem constants
#define BATCH 512
#define NTOK  343
#define NP    384
#define CDIM  192
#define NHEAD 6
#define HD    32
#define NWIN  64
#define NN    (NTOK * NTOK)
#define BMP   384                  // g_bm row pitch (halves)
#define SCALE 0.17677669529663687f
#define MROWS (BATCH * NTOK)       // 175616
#define ESHIFT 10.0f

// ---------------------------------------------------------------------------
// Scratch (device globals: allocation-free, zero-init; pads stay zero halves)
// ---------------------------------------------------------------------------
__device__ __half g_q[BATCH * NHEAD * NTOK * HD];     // pre-scaled
__device__ __half g_k[BATCH * NHEAD * NTOK * HD];
__device__ __half g_vt[BATCH * NHEAD * HD * NP];      // transposed, pads zero
__device__ __half g_o[BATCH * NTOK * CDIM];
__device__ __half g_bm[NWIN * NHEAD * NP * BMP];      // bias+mask
__device__ __half g_xh[MROWS * CDIM];                 // x in half
__device__ __half g_wt[3 * CDIM * CDIM + CDIM * CDIM]; // qkv_w^T | proj_w^T

__device__ __forceinline__ void cpa16(void* smem_dst, const void* gmem_src) {
    uint32_t d = (uint32_t)__cvta_generic_to_shared(smem_dst);
    asm volatile("cp.async.cg.shared.global [%0], [%1], 16;" :: "r"(d), "l"(gmem_src));
}
__device__ __forceinline__ void cpa16z(void* smem_dst, const void* gmem_src, int sz) {
    uint32_t d = (uint32_t)__cvta_generic_to_shared(smem_dst);
    asm volatile("cp.async.cg.shared.global [%0], [%1], 16, %2;"
                 :: "r"(d), "l"(gmem_src), "r"(sz));
}

// fp16 MMA m16n8k16, fp32 accum (fragment layout validated R10).
__device__ __forceinline__ void mma_f16(float c[4], const uint32_t a[4],
                                        uint32_t b0, uint32_t b1) {
    asm volatile(
        "mma.sync.aligned.m16n8k16.row.col.f32.f16.f16.f32 "
        "{%0,%1,%2,%3}, {%4,%5,%6,%7}, {%8,%9}, {%0,%1,%2,%3};"
        : "+f"(c[0]), "+f"(c[1]), "+f"(c[2]), "+f"(c[3])
        : "r"(a[0]), "r"(a[1]), "r"(a[2]), "r"(a[3]), "r"(b0), "r"(b1));
}

// ---------------------------------------------------------------------------
// Prepass kernels
// ---------------------------------------------------------------------------
__global__ void round_x_kernel(const float* __restrict__ x)
{
    size_t i = (size_t)blockIdx.x * 256 + threadIdx.x;
    float4 v = ((const float4*)x)[i];
    __half2* dst = (__half2*)g_xh;
    dst[2 * i]     = __floats2half2_rn(v.x, v.y);
    dst[2 * i + 1] = __floats2half2_rn(v.z, v.w);
}
__global__ void round_wt_kernel(const float* __restrict__ qkv_w,
                                const float* __restrict__ proj_w)
{
    int idx = blockIdx.x * 256 + threadIdx.x;
    const int nq = 3 * CDIM * CDIM;
    float v;
    if (idx < nq) {
        int c = idx / CDIM, k = idx - c * CDIM;
        v = qkv_w[k * (3 * CDIM) + c];
    } else {
        int i2 = idx - nq;
        int c = i2 / CDIM, k = i2 - c * CDIM;
        v = proj_w[k * CDIM + c];
    }
    g_wt[idx] = __float2half_rn(v);
}
__global__ void bm_combine_kernel(const float* __restrict__ mask,
                                  const float* __restrict__ bt,
                                  const int* __restrict__ rpi)
{
    int ij = blockIdx.x * blockDim.x + threadIdx.x;
    if (ij >= NN) return;
    int w = blockIdx.y;
    int h = blockIdx.z;
    int i = ij / NTOK;
    int j = ij - i * NTOK;
    float v = bt[rpi[ij] * NHEAD + h] + mask[(size_t)w * NN + ij];
    g_bm[((size_t)(w * NHEAD + h) * NP + i) * BMP + j] = __float2half_rn(v);
}

// ---------------------------------------------------------------------------
// GEMM: fp16 mma, CTA 256x64, warp 64x32, K-slab 32, 3-stage cp.async.
// (unchanged from R11)
// ---------------------------------------------------------------------------
#define AS_P 40
#define WS_P 40
#define AS_SZ (256 * AS_P)
#define WS_SZ (64 * WS_P)

template <int MODE>
__global__ void __launch_bounds__(256, 2)
gemm_tc_kernel(const float* __restrict__ bias, float* __restrict__ Cout)
{
    const __half* A = (MODE == 0) ? g_xh : g_o;
    const __half* W = (MODE == 0) ? g_wt : (g_wt + 3 * CDIM * CDIM);

    __shared__ __align__(16) __half As[3 * AS_SZ];
    __shared__ __align__(16) __half Ws[3 * WS_SZ];

    const int tid  = threadIdx.x;
    const int w    = tid >> 5;
    const int lane = tid & 31;
    const int lq   = lane >> 2;
    const int lr   = lane & 3;
    const int wm   = w >> 1;
    const int wn   = w & 1;
    const int row0 = blockIdx.y * 256;
    const int c0   = blockIdx.x * 64;

    const int arq = tid >> 2;
    const int aq  = tid & 3;
    const int wcq = tid >> 2;
    const int wq  = tid & 3;

    float acc[4][4][4];
    #pragma unroll
    for (int mi = 0; mi < 4; mi++)
        #pragma unroll
        for (int ni = 0; ni < 4; ni++)
            #pragma unroll
            for (int r = 0; r < 4; r++) acc[mi][ni][r] = 0.f;

    auto stage = [&](int kb) {
        const int buf = kb % 3;
        const int k0 = kb * 32;
        __half* An = &As[buf * AS_SZ];
        __half* Wn = &Ws[buf * WS_SZ];
        #pragma unroll
        for (int f = 0; f < 4; f++)
            cpa16(&An[(f * 64 + arq) * AS_P + aq * 8],
                  A + (size_t)(row0 + f * 64 + arq) * CDIM + k0 + aq * 8);
        cpa16(&Wn[wcq * WS_P + wq * 8],
              W + (size_t)(c0 + wcq) * CDIM + k0 + wq * 8);
        asm volatile("cp.async.commit_group;" ::: "memory");
    };

    stage(0);
    stage(1);

    for (int kb = 0; kb < 6; kb++) {
        if (kb < 5) asm volatile("cp.async.wait_group 1;" ::: "memory");
        else        asm volatile("cp.async.wait_group 0;" ::: "memory");
        __syncthreads();
        if (kb + 2 < 6) stage(kb + 2);

        const __half* Ab = &As[(kb % 3) * AS_SZ];
        const __half* Wb = &Ws[(kb % 3) * WS_SZ];
        #pragma unroll
        for (int ks = 0; ks < 2; ks++) {
            const int kc = ks * 16 + 2 * lr;
            uint32_t bf[4][2];
            #pragma unroll
            for (int ni = 0; ni < 4; ni++) {
                int cc = wn * 32 + ni * 8 + lq;
                bf[ni][0] = *(const uint32_t*)&Wb[cc * WS_P + kc];
                bf[ni][1] = *(const uint32_t*)&Wb[cc * WS_P + kc + 8];
            }
            #pragma unroll
            for (int mi = 0; mi < 4; mi++) {
                int r0 = wm * 64 + mi * 16 + lq;
                uint32_t af[4];
                af[0] = *(const uint32_t*)&Ab[r0 * AS_P + kc];
                af[1] = *(const uint32_t*)&Ab[(r0 + 8) * AS_P + kc];
                af[2] = *(const uint32_t*)&Ab[r0 * AS_P + kc + 8];
                af[3] = *(const uint32_t*)&Ab[(r0 + 8) * AS_P + kc + 8];
                #pragma unroll
                for (int ni = 0; ni < 4; ni++)
                    mma_f16(acc[mi][ni], af, bf[ni][0], bf[ni][1]);
            }
        }
    }

    // epilogue
    #pragma unroll
    for (int mi = 0; mi < 4; mi++) {
        int rlo = row0 + wm * 64 + mi * 16 + lq;
        int rhi = rlo + 8;
        int blo = rlo / NTOK, nlo = rlo - blo * NTOK;
        int bhi = rhi / NTOK, nhi = rhi - bhi * NTOK;
        #pragma unroll
        for (int ni = 0; ni < 4; ni++) {
            int c = c0 + wn * 32 + ni * 8 + 2 * lr;
            float b0 = bias[c], b1 = bias[c + 1];
            if (MODE == 0) {
                int s   = c / CDIM;
                int rem = c - s * CDIM;
                int hh  = rem >> 5;
                int dd  = rem & 31;
                if (s == 2) {
                    __half* vlo = g_vt + (size_t)(blo * NHEAD + hh) * HD * NP;
                    __half* vhi = g_vt + (size_t)(bhi * NHEAD + hh) * HD * NP;
                    vlo[(size_t)dd * NP + nlo]       = __float2half_rn(acc[mi][ni][0] + b0);
                    vlo[(size_t)(dd + 1) * NP + nlo] = __float2half_rn(acc[mi][ni][1] + b1);
                    vhi[(size_t)dd * NP + nhi]       = __float2half_rn(acc[mi][ni][2] + b0);
                    vhi[(size_t)(dd + 1) * NP + nhi] = __float2half_rn(acc[mi][ni][3] + b1);
                } else {
                    float sc = (s == 0) ? SCALE : 1.f;
                    __half* dst = (s == 0) ? g_q : g_k;
                    *(__half2*)&dst[((size_t)(blo * NHEAD + hh) * NTOK + nlo) * HD + dd] =
                        __floats2half2_rn((acc[mi][ni][0] + b0) * sc, (acc[mi][ni][1] + b1) * sc);
                    *(__half2*)&dst[((size_t)(bhi * NHEAD + hh) * NTOK + nhi) * HD + dd] =
                        __floats2half2_rn((acc[mi][ni][2] + b0) * sc, (acc[mi][ni][3] + b1) * sc);
                }
            } else {
                float2 vl, vh;
                vl.x = acc[mi][ni][0] + b0; vl.y = acc[mi][ni][1] + b1;
                vh.x = acc[mi][ni][2] + b0; vh.y = acc[mi][ni][3] + b1;
                *(float2*)&Cout[(size_t)rlo * CDIM + c] = vl;
                *(float2*)&Cout[(size_t)rhi * CDIM + c] = vh;
            }
        }
    }
}

// ---------------------------------------------------------------------------
// Attention: fp16 mma, double-buffered cp.async for K, VT AND the bias+mask
// tile. 2 barriers per chunk; staging entirely asynchronous, one chunk ahead.
// smem 73 KB -> 3 CTAs/SM. Grid (48, NWIN, 3).
// ---------------------------------------------------------------------------
#define KS_P 40
#define VS_P 72
#define BM_P 72
#define P_P  72
#define KS_SZ (64 * KS_P)      // 2560
#define VS_SZ (32 * VS_P)      // 2304
#define BM_SZ (128 * BM_P)     // 9216
#define OFF_KS 0
#define OFF_VS (2 * KS_SZ)                 // 5120
#define OFF_BM (OFF_VS + 2 * VS_SZ)        // 9728
#define OFF_P  (OFF_BM + 2 * BM_SZ)        // 28160
#define ATTN_SMEM_HALVES (OFF_P + 8 * 16 * P_P)   // 37376
#define ATTN_SMEM_BYTES  (ATTN_SMEM_HALVES * 2)   // 74752

__global__ void __launch_bounds__(256, 3)
attn_mma_kernel()
{
    const int bg  = blockIdx.x & 7;
    const int h   = blockIdx.x >> 3;
    const int wi  = blockIdx.y;
    const int mt  = blockIdx.z;
    const int b   = wi + NWIN * bg;
    const int tid = threadIdx.x;
    const int w   = tid >> 5;
    const int lane = tid & 31;
    const int lq  = lane >> 2;
    const int lr  = lane & 3;

    extern __shared__ __half smh[];
    __half* Pw = smh + OFF_P + w * 16 * P_P;

    const int i0 = mt * 128;
    const int m0 = i0 + w * 16;
    const size_t bh = (size_t)(b * NHEAD + h);

    const __half* kgh = g_k + bh * NTOK * HD;
    const __half* vg  = g_vt + bh * HD * NP;
    const __half* bmrow = g_bm + ((size_t)(wi * NHEAD + h) * NP + i0) * BMP;

    // async stage of chunk jc into buffer jc&1 (K, VT, BM), one commit group
    auto stage = [&](int jc) {
        const int buf = jc & 1;
        const int j0 = jc * 64;
        {   // K: 64 j-rows x 32 d (4 KB): 256 thr = 64 rows x 4 quads
            int jl = tid >> 2, q = tid & 3;
            int j = j0 + jl;
            const __half* src = kgh + (size_t)(j < NTOK ? j : 0) * HD + q * 8;
            cpa16z(&smh[OFF_KS + buf * KS_SZ + jl * KS_P + q * 8], src,
                   (j < NTOK) ? 16 : 0);
        }
        {   // VT: 32 d-rows x 64 j (4 KB): 256 thr = 32 rows x 8 quads
            int d = tid >> 3, q = tid & 7;
            cpa16(&smh[OFF_VS + buf * VS_SZ + d * VS_P + q * 8],
                  vg + (size_t)d * NP + j0 + q * 8);
        }
        #pragma unroll
        for (int f = 0; f < 4; f++) {   // BM: 128 i-rows x 64 j (16 KB): 1024 = 128 x 8
            int idx = f * 256 + tid;
            int r = idx >> 3, q = idx & 7;
            cpa16(&smh[OFF_BM + buf * BM_SZ + r * BM_P + q * 8],
                  bmrow + (size_t)r * BMP + j0 + q * 8);
        }
        asm volatile("cp.async.commit_group;" ::: "memory");
    };

    // --- load Q fragments (stage via Pw region, pitch 40)
    uint32_t qf[2][4];
    {
        __half* Qs = smh + OFF_P;
        const uint4* qg = (const uint4*)(g_q + bh * NTOK * HD);
        for (int idx = tid; idx < 128 * 4; idx += 256) {
            int r = idx >> 2, q = idx & 3;
            int i = i0 + r;
            uint4 v = (i < NTOK) ? qg[i * 4 + q] : make_uint4(0, 0, 0, 0);
            *(uint4*)&Qs[r * KS_P + q * 8] = v;
        }
        __syncthreads();
        const int r0 = w * 16 + lq;
        #pragma unroll
        for (int ks = 0; ks < 2; ks++) {
            int kc = ks * 16 + 2 * lr;
            qf[ks][0] = *(const uint32_t*)&Qs[r0 * KS_P + kc];
            qf[ks][1] = *(const uint32_t*)&Qs[(r0 + 8) * KS_P + kc];
            qf[ks][2] = *(const uint32_t*)&Qs[r0 * KS_P + kc + 8];
            qf[ks][3] = *(const uint32_t*)&Qs[(r0 + 8) * KS_P + kc + 8];
        }
        __syncthreads();   // Qs region is reused as Pw below
    }

    float o[4][4];
    #pragma unroll
    for (int nt = 0; nt < 4; nt++)
        #pragma unroll
        for (int r = 0; r < 4; r++) o[nt][r] = 0.f;
    float lsum0 = 0.f, lsum1 = 0.f;

    stage(0);
    stage(1);

    for (int jc = 0; jc < 6; jc++) {
        if (jc < 5) asm volatile("cp.async.wait_group 1;" ::: "memory");
        else        asm volatile("cp.async.wait_group 0;" ::: "memory");
        __syncthreads();

        const int buf = jc & 1;
        const int j0 = jc * 64;
        const __half* Ks = smh + OFF_KS + buf * KS_SZ;
        const __half* Vs = smh + OFF_VS + buf * VS_SZ;
        const __half* Bm = smh + OFF_BM + buf * BM_SZ;
        const int rb0 = w * 16 + lq;

        // S phase in nt-pairs (2 independent chains), fused softmax, P -> Pw
        #pragma unroll
        for (int ntp = 0; ntp < 4; ntp++) {
            const int nt0 = 2 * ntp, nt1 = 2 * ntp + 1;
            float s0[4] = {0.f, 0.f, 0.f, 0.f};
            float s1[4] = {0.f, 0.f, 0.f, 0.f};
            #pragma unroll
            for (int ks = 0; ks < 2; ks++) {
                int kc = ks * 16 + 2 * lr;
                uint32_t b00 = *(const uint32_t*)&Ks[(nt0 * 8 + lq) * KS_P + kc];
                uint32_t b01 = *(const uint32_t*)&Ks[(nt0 * 8 + lq) * KS_P + kc + 8];
                uint32_t b10 = *(const uint32_t*)&Ks[(nt1 * 8 + lq) * KS_P + kc];
                uint32_t b11 = *(const uint32_t*)&Ks[(nt1 * 8 + lq) * KS_P + kc + 8];
                mma_f16(s0, qf[ks], b00, b01);
                mma_f16(s1, qf[ks], b10, b11);
            }
            #pragma unroll
            for (int half = 0; half < 2; half++) {
                const float* s = half ? s1 : s0;
                const int nt = half ? nt1 : nt0;
                int cl = nt * 8 + 2 * lr;
                int jgl = j0 + cl;
                float2 bml = __half22float2(*(const __half2*)&Bm[rb0 * BM_P + cl]);
                float2 bmh = __half22float2(*(const __half2*)&Bm[(rb0 + 8) * BM_P + cl]);
                bool v0 = jgl < NTOK, v1 = (jgl + 1) < NTOK;
                float p00 = v0 ? __expf(s[0] + bml.x - ESHIFT) : 0.f;
                float p01 = v1 ? __expf(s[1] + bml.y - ESHIFT) : 0.f;
                float p10 = v0 ? __expf(s[2] + bmh.x - ESHIFT) : 0.f;
                float p11 = v1 ? __expf(s[3] + bmh.y - ESHIFT) : 0.f;
                lsum0 += p00 + p01;
                lsum1 += p10 + p11;
                *(__half2*)&Pw[lq * P_P + cl]       = __floats2half2_rn(p00, p01);
                *(__half2*)&Pw[(lq + 8) * P_P + cl] = __floats2half2_rn(p10, p11);
            }
        }
        __syncwarp();

        // O += P * V  (4 fp16 mma k-steps, 4 independent chains)
        #pragma unroll
        for (int ks = 0; ks < 4; ks++) {
            int kc = ks * 16 + 2 * lr;
            uint32_t a[4];
            a[0] = *(const uint32_t*)&Pw[lq * P_P + kc];
            a[1] = *(const uint32_t*)&Pw[(lq + 8) * P_P + kc];
            a[2] = *(const uint32_t*)&Pw[lq * P_P + kc + 8];
            a[3] = *(const uint32_t*)&Pw[(lq + 8) * P_P + kc + 8];
            #pragma unroll
            for (int nt = 0; nt < 4; nt++) {
                uint32_t b0 = *(const uint32_t*)&Vs[(nt * 8 + lq) * VS_P + kc];
                uint32_t b1 = *(const uint32_t*)&Vs[(nt * 8 + lq) * VS_P + kc + 8];
                mma_f16(o[nt], a, b0, b1);
            }
        }

        __syncthreads();                 // all warps done with buffer jc&1
        if (jc + 2 < 6) stage(jc + 2);   // refill it asynchronously
    }

    // epilogue
    lsum0 += __shfl_xor_sync(0xffffffffu, lsum0, 1);
    lsum0 += __shfl_xor_sync(0xffffffffu, lsum0, 2);
    lsum1 += __shfl_xor_sync(0xffffffffu, lsum1, 1);
    lsum1 += __shfl_xor_sync(0xffffffffu, lsum1, 2);
    float inv0 = 1.f / lsum0;
    float inv1 = 1.f / lsum1;

    const int ir0 = m0 + lq;
    const int ir1 = ir0 + 8;
    if (ir0 < NTOK) {
        __half* base = g_o + ((size_t)b * NTOK + ir0) * CDIM + h * HD;
        #pragma unroll
        for (int nt = 0; nt < 4; nt++)
            *(__half2*)(base + nt * 8 + 2 * lr) =
                __floats2half2_rn(o[nt][0] * inv0, o[nt][1] * inv0);
    }
    if (ir1 < NTOK) {
        __half* base = g_o + ((size_t)b * NTOK + ir1) * CDIM + h * HD;
        #pragma unroll
        for (int nt = 0; nt < 4; nt++)
            *(__half2*)(base + nt * 8 + 2 * lr) =
                __floats2half2_rn(o[nt][2] * inv1, o[nt][3] * inv1);
    }
}

// ---------------------------------------------------------------------------
// Launch
// ---------------------------------------------------------------------------
extern "C" void kernel_launch(void* const* d_in, const int* in_sizes, int n_in,
                              void* d_out, int out_size)
{
    const float* x      = (const float*)d_in[0];
    const float* mask   = (const float*)d_in[1];
    const float* qkv_w  = (const float*)d_in[2];
    const float* qkv_b  = (const float*)d_in[3];
    const float* proj_w = (const float*)d_in[4];
    const float* proj_b = (const float*)d_in[5];
    const float* bt     = (const float*)d_in[6];
    const int*   rpi    = (const int*)d_in[7];
    float* out = (float*)d_out;

    cudaFuncSetAttribute(attn_mma_kernel,
                         cudaFuncAttributeMaxDynamicSharedMemorySize,
                         ATTN_SMEM_BYTES);

    round_x_kernel<<<MROWS * CDIM / 4 / 256, 256>>>(x);
    round_wt_kernel<<<(3 * CDIM * CDIM + CDIM * CDIM) / 256, 256>>>(qkv_w, proj_w);
    bm_combine_kernel<<<dim3((NN + 255) / 256, NWIN, NHEAD), 256>>>(mask, bt, rpi);
    gemm_tc_kernel<0><<<dim3(9, 686), 256>>>(qkv_b, nullptr);
    attn_mma_kernel<<<dim3(48, NWIN, 3), 256, ATTN_SMEM_BYTES>>>();
    gemm_tc_kernel<1><<<dim3(3, 686), 256>>>(proj_b, out);
}

// round 16
// speedup vs baseline: 4.3775x; 1.0813x over previous
#include <cuda_runtime.h>
#include <cuda_fp16.h>
#include <cstdint>

// Problem constants
#define BATCH 512
#define NTOK  343
#define NP    384
#define CDIM  192
#define NHEAD 6
#define HD    32
#define NWIN  64
#define NN    (NTOK * NTOK)
#define BMP   384                  // g_bm row pitch (halves)
#define SCALE 0.17677669529663687f
#define MROWS (BATCH * NTOK)       // 175616
#define ESHIFT 10.0f

// ---------------------------------------------------------------------------
// Scratch (device globals: allocation-free, zero-init; pads stay zero halves)
// ---------------------------------------------------------------------------
__device__ __half g_q[BATCH * NHEAD * NTOK * HD];     // pre-scaled
__device__ __half g_k[BATCH * NHEAD * NTOK * HD];
__device__ __half g_vt[BATCH * NHEAD * HD * NP];      // transposed, pads zero
__device__ __half g_o[BATCH * NTOK * CDIM];
__device__ __half g_bm[NWIN * NHEAD * NP * BMP];      // bias+mask
__device__ __half g_xh[MROWS * CDIM];                 // x in half
__device__ __half g_wt[3 * CDIM * CDIM + CDIM * CDIM]; // qkv_w^T | proj_w^T

__device__ __forceinline__ void cpa16(void* smem_dst, const void* gmem_src) {
    uint32_t d = (uint32_t)__cvta_generic_to_shared(smem_dst);
    asm volatile("cp.async.cg.shared.global [%0], [%1], 16;" :: "r"(d), "l"(gmem_src));
}
__device__ __forceinline__ void cpa16z(void* smem_dst, const void* gmem_src, int sz) {
    uint32_t d = (uint32_t)__cvta_generic_to_shared(smem_dst);
    asm volatile("cp.async.cg.shared.global [%0], [%1], 16, %2;"
                 :: "r"(d), "l"(gmem_src), "r"(sz));
}
// ldmatrix x4: d_i = 8x8 b16 matrix i; lane l holds (row l>>2, cols 2(l&3)+0,1).
__device__ __forceinline__ void ldsm4(uint32_t r[4], const void* p) {
    uint32_t a = (uint32_t)__cvta_generic_to_shared(p);
    asm volatile("ldmatrix.sync.aligned.m8n8.x4.shared.b16 {%0,%1,%2,%3}, [%4];"
                 : "=r"(r[0]), "=r"(r[1]), "=r"(r[2]), "=r"(r[3]) : "r"(a));
}

// fp16 MMA m16n8k16, fp32 accum (fragment layout validated R10).
__device__ __forceinline__ void mma_f16(float c[4], const uint32_t a[4],
                                        uint32_t b0, uint32_t b1) {
    asm volatile(
        "mma.sync.aligned.m16n8k16.row.col.f32.f16.f16.f32 "
        "{%0,%1,%2,%3}, {%4,%5,%6,%7}, {%8,%9}, {%0,%1,%2,%3};"
        : "+f"(c[0]), "+f"(c[1]), "+f"(c[2]), "+f"(c[3])
        : "r"(a[0]), "r"(a[1]), "r"(a[2]), "r"(a[3]), "r"(b0), "r"(b1));
}

// ---------------------------------------------------------------------------
// Prepass kernels (unchanged)
// ---------------------------------------------------------------------------
__global__ void round_x_kernel(const float* __restrict__ x)
{
    size_t i = (size_t)blockIdx.x * 256 + threadIdx.x;
    float4 v = ((const float4*)x)[i];
    __half2* dst = (__half2*)g_xh;
    dst[2 * i]     = __floats2half2_rn(v.x, v.y);
    dst[2 * i + 1] = __floats2half2_rn(v.z, v.w);
}
__global__ void round_wt_kernel(const float* __restrict__ qkv_w,
                                const float* __restrict__ proj_w)
{
    int idx = blockIdx.x * 256 + threadIdx.x;
    const int nq = 3 * CDIM * CDIM;
    float v;
    if (idx < nq) {
        int c = idx / CDIM, k = idx - c * CDIM;
        v = qkv_w[k * (3 * CDIM) + c];
    } else {
        int i2 = idx - nq;
        int c = i2 / CDIM, k = i2 - c * CDIM;
        v = proj_w[k * CDIM + c];
    }
    g_wt[idx] = __float2half_rn(v);
}
__global__ void bm_combine_kernel(const float* __restrict__ mask,
                                  const float* __restrict__ bt,
                                  const int* __restrict__ rpi)
{
    int ij = blockIdx.x * blockDim.x + threadIdx.x;
    if (ij >= NN) return;
    int w = blockIdx.y;
    int h = blockIdx.z;
    int i = ij / NTOK;
    int j = ij - i * NTOK;
    float v = bt[rpi[ij] * NHEAD + h] + mask[(size_t)w * NN + ij];
    g_bm[((size_t)(w * NHEAD + h) * NP + i) * BMP + j] = __float2half_rn(v);
}

// ---------------------------------------------------------------------------
// GEMM: fp16 mma, CTA 256x64, warp 64x32, K-slab 32, 3-stage cp.async,
// ldmatrix fragment loads.
// ---------------------------------------------------------------------------
#define AS_P 40
#define WS_P 40
#define AS_SZ (256 * AS_P)
#define WS_SZ (64 * WS_P)

template <int MODE>
__global__ void __launch_bounds__(256, 2)
gemm_tc_kernel(const float* __restrict__ bias, float* __restrict__ Cout)
{
    const __half* A = (MODE == 0) ? g_xh : g_o;
    const __half* W = (MODE == 0) ? g_wt : (g_wt + 3 * CDIM * CDIM);

    __shared__ __align__(16) __half As[3 * AS_SZ];
    __shared__ __align__(16) __half Ws[3 * WS_SZ];

    const int tid  = threadIdx.x;
    const int w    = tid >> 5;
    const int lane = tid & 31;
    const int lq   = lane >> 2;
    const int lr   = lane & 3;
    const int wm   = w >> 1;
    const int wn   = w & 1;
    const int row0 = blockIdx.y * 256;
    const int c0   = blockIdx.x * 64;

    const int arq = tid >> 2;
    const int aq  = tid & 3;
    const int wcq = tid >> 2;
    const int wq  = tid & 3;

    // ldmatrix per-lane address components
    const int lm_row16 = lane & 15;                 // A-operand row within 16
    const int lm_khi   = (lane >> 4) << 3;          // A col +8 for upper half
    const int lm_brow  = ((lane >> 4) << 3) + (lane & 7);   // B row within 16
    const int lm_bk    = ((lane >> 3) & 1) << 3;    // B col +8 selector

    float acc[4][4][4];
    #pragma unroll
    for (int mi = 0; mi < 4; mi++)
        #pragma unroll
        for (int ni = 0; ni < 4; ni++)
            #pragma unroll
            for (int r = 0; r < 4; r++) acc[mi][ni][r] = 0.f;

    auto stage = [&](int kb) {
        const int buf = kb % 3;
        const int k0 = kb * 32;
        __half* An = &As[buf * AS_SZ];
        __half* Wn = &Ws[buf * WS_SZ];
        #pragma unroll
        for (int f = 0; f < 4; f++)
            cpa16(&An[(f * 64 + arq) * AS_P + aq * 8],
                  A + (size_t)(row0 + f * 64 + arq) * CDIM + k0 + aq * 8);
        cpa16(&Wn[wcq * WS_P + wq * 8],
              W + (size_t)(c0 + wcq) * CDIM + k0 + wq * 8);
        asm volatile("cp.async.commit_group;" ::: "memory");
    };

    stage(0);
    stage(1);

    for (int kb = 0; kb < 6; kb++) {
        if (kb < 5) asm volatile("cp.async.wait_group 1;" ::: "memory");
        else        asm volatile("cp.async.wait_group 0;" ::: "memory");
        __syncthreads();
        if (kb + 2 < 6) stage(kb + 2);

        const __half* Ab = &As[(kb % 3) * AS_SZ];
        const __half* Wb = &Ws[(kb % 3) * WS_SZ];
        #pragma unroll
        for (int ks = 0; ks < 2; ks++) {
            const int kc = ks * 16;
            uint32_t bf[2][4];     // [ni-pair]{b[2np][0],b[2np][1],b[2np+1][0],b[2np+1][1]}
            #pragma unroll
            for (int np = 0; np < 2; np++)
                ldsm4(bf[np], &Wb[(wn * 32 + np * 16 + lm_brow) * WS_P + kc + lm_bk]);
            #pragma unroll
            for (int mi = 0; mi < 4; mi++) {
                uint32_t af[4];
                ldsm4(af, &Ab[(wm * 64 + mi * 16 + lm_row16) * AS_P + kc + lm_khi]);
                mma_f16(acc[mi][0], af, bf[0][0], bf[0][1]);
                mma_f16(acc[mi][1], af, bf[0][2], bf[0][3]);
                mma_f16(acc[mi][2], af, bf[1][0], bf[1][1]);
                mma_f16(acc[mi][3], af, bf[1][2], bf[1][3]);
            }
        }
    }

    // epilogue
    #pragma unroll
    for (int mi = 0; mi < 4; mi++) {
        int rlo = row0 + wm * 64 + mi * 16 + lq;
        int rhi = rlo + 8;
        int blo = rlo / NTOK, nlo = rlo - blo * NTOK;
        int bhi = rhi / NTOK, nhi = rhi - bhi * NTOK;
        #pragma unroll
        for (int ni = 0; ni < 4; ni++) {
            int c = c0 + wn * 32 + ni * 8 + 2 * lr;
            float b0 = bias[c], b1 = bias[c + 1];
            if (MODE == 0) {
                int s   = c / CDIM;
                int rem = c - s * CDIM;
                int hh  = rem >> 5;
                int dd  = rem & 31;
                if (s == 2) {
                    __half* vlo = g_vt + (size_t)(blo * NHEAD + hh) * HD * NP;
                    __half* vhi = g_vt + (size_t)(bhi * NHEAD + hh) * HD * NP;
                    vlo[(size_t)dd * NP + nlo]       = __float2half_rn(acc[mi][ni][0] + b0);
                    vlo[(size_t)(dd + 1) * NP + nlo] = __float2half_rn(acc[mi][ni][1] + b1);
                    vhi[(size_t)dd * NP + nhi]       = __float2half_rn(acc[mi][ni][2] + b0);
                    vhi[(size_t)(dd + 1) * NP + nhi] = __float2half_rn(acc[mi][ni][3] + b1);
                } else {
                    float sc = (s == 0) ? SCALE : 1.f;
                    __half* dst = (s == 0) ? g_q : g_k;
                    *(__half2*)&dst[((size_t)(blo * NHEAD + hh) * NTOK + nlo) * HD + dd] =
                        __floats2half2_rn((acc[mi][ni][0] + b0) * sc, (acc[mi][ni][1] + b1) * sc);
                    *(__half2*)&dst[((size_t)(bhi * NHEAD + hh) * NTOK + nhi) * HD + dd] =
                        __floats2half2_rn((acc[mi][ni][2] + b0) * sc, (acc[mi][ni][3] + b1) * sc);
                }
            } else {
                float2 vl, vh;
                vl.x = acc[mi][ni][0] + b0; vl.y = acc[mi][ni][1] + b1;
                vh.x = acc[mi][ni][2] + b0; vh.y = acc[mi][ni][3] + b1;
                *(float2*)&Cout[(size_t)rlo * CDIM + c] = vl;
                *(float2*)&Cout[(size_t)rhi * CDIM + c] = vh;
            }
        }
    }
}

// ---------------------------------------------------------------------------
// Attention: fp16 mma, double-buffered cp.async (K, VT, BM), ldmatrix frags.
// smem 73 KB -> 3 CTAs/SM. Grid (48, NWIN, 3).
// ---------------------------------------------------------------------------
#define KS_P 40
#define VS_P 72
#define BM_P 72
#define P_P  72
#define KS_SZ (64 * KS_P)      // 2560
#define VS_SZ (32 * VS_P)      // 2304
#define BM_SZ (128 * BM_P)     // 9216
#define OFF_KS 0
#define OFF_VS (2 * KS_SZ)                 // 5120
#define OFF_BM (OFF_VS + 2 * VS_SZ)        // 9728
#define OFF_P  (OFF_BM + 2 * BM_SZ)        // 28160
#define ATTN_SMEM_HALVES (OFF_P + 8 * 16 * P_P)   // 37376
#define ATTN_SMEM_BYTES  (ATTN_SMEM_HALVES * 2)   // 74752

__global__ void __launch_bounds__(256, 3)
attn_mma_kernel()
{
    const int bg  = blockIdx.x & 7;
    const int h   = blockIdx.x >> 3;
    const int wi  = blockIdx.y;
    const int mt  = blockIdx.z;
    const int b   = wi + NWIN * bg;
    const int tid = threadIdx.x;
    const int w   = tid >> 5;
    const int lane = tid & 31;
    const int lq  = lane >> 2;
    const int lr  = lane & 3;

    extern __shared__ __half smh[];
    __half* Pw = smh + OFF_P + w * 16 * P_P;

    const int i0 = mt * 128;
    const int m0 = i0 + w * 16;
    const size_t bh = (size_t)(b * NHEAD + h);

    const __half* kgh = g_k + bh * NTOK * HD;
    const __half* vg  = g_vt + bh * HD * NP;
    const __half* bmrow = g_bm + ((size_t)(wi * NHEAD + h) * NP + i0) * BMP;

    // ldmatrix per-lane address components
    const int lm_row16 = lane & 15;
    const int lm_khi   = (lane >> 4) << 3;
    const int lm_brow  = ((lane >> 4) << 3) + (lane & 7);
    const int lm_bk    = ((lane >> 3) & 1) << 3;

    // async stage of chunk jc into buffer jc&1 (K, VT, BM), one commit group
    auto stage = [&](int jc) {
        const int buf = jc & 1;
        const int j0 = jc * 64;
        {   // K: 64 j-rows x 32 d (4 KB): 256 thr = 64 rows x 4 quads
            int jl = tid >> 2, q = tid & 3;
            int j = j0 + jl;
            const __half* src = kgh + (size_t)(j < NTOK ? j : 0) * HD + q * 8;
            cpa16z(&smh[OFF_KS + buf * KS_SZ + jl * KS_P + q * 8], src,
                   (j < NTOK) ? 16 : 0);
        }
        {   // VT: 32 d-rows x 64 j (4 KB): 256 thr = 32 rows x 8 quads
            int d = tid >> 3, q = tid & 7;
            cpa16(&smh[OFF_VS + buf * VS_SZ + d * VS_P + q * 8],
                  vg + (size_t)d * NP + j0 + q * 8);
        }
        #pragma unroll
        for (int f = 0; f < 4; f++) {   // BM: 128 i-rows x 64 j (16 KB): 1024 = 128 x 8
            int idx = f * 256 + tid;
            int r = idx >> 3, q = idx & 7;
            cpa16(&smh[OFF_BM + buf * BM_SZ + r * BM_P + q * 8],
                  bmrow + (size_t)r * BMP + j0 + q * 8);
        }
        asm volatile("cp.async.commit_group;" ::: "memory");
    };

    // --- load Q fragments (stage via Pw region, pitch 40; ldmatrix)
    uint32_t qf[2][4];
    {
        __half* Qs = smh + OFF_P;
        const uint4* qg = (const uint4*)(g_q + bh * NTOK * HD);
        for (int idx = tid; idx < 128 * 4; idx += 256) {
            int r = idx >> 2, q = idx & 3;
            int i = i0 + r;
            uint4 v = (i < NTOK) ? qg[i * 4 + q] : make_uint4(0, 0, 0, 0);
            *(uint4*)&Qs[r * KS_P + q * 8] = v;
        }
        __syncthreads();
        #pragma unroll
        for (int ks = 0; ks < 2; ks++)
            ldsm4(qf[ks], &Qs[(w * 16 + lm_row16) * KS_P + ks * 16 + lm_khi]);
        __syncthreads();   // Qs region is reused as Pw below
    }

    float o[4][4];
    #pragma unroll
    for (int nt = 0; nt < 4; nt++)
        #pragma unroll
        for (int r = 0; r < 4; r++) o[nt][r] = 0.f;
    float lsum0 = 0.f, lsum1 = 0.f;

    stage(0);
    stage(1);

    for (int jc = 0; jc < 6; jc++) {
        if (jc < 5) asm volatile("cp.async.wait_group 1;" ::: "memory");
        else        asm volatile("cp.async.wait_group 0;" ::: "memory");
        __syncthreads();

        const int buf = jc & 1;
        const int j0 = jc * 64;
        const __half* Ks = smh + OFF_KS + buf * KS_SZ;
        const __half* Vs = smh + OFF_VS + buf * VS_SZ;
        const __half* Bm = smh + OFF_BM + buf * BM_SZ;
        const int rb0 = w * 16 + lq;

        // S phase: per nt-pair one ldmatrix.x4 delivers all 4 K fragments
        #pragma unroll
        for (int ntp = 0; ntp < 4; ntp++) {
            const int nt0 = 2 * ntp, nt1 = 2 * ntp + 1;
            float s0[4] = {0.f, 0.f, 0.f, 0.f};
            float s1[4] = {0.f, 0.f, 0.f, 0.f};
            #pragma unroll
            for (int ks = 0; ks < 2; ks++) {
                uint32_t bb[4];
                ldsm4(bb, &Ks[(ntp * 16 + lm_brow) * KS_P + ks * 16 + lm_bk]);
                mma_f16(s0, qf[ks], bb[0], bb[1]);
                mma_f16(s1, qf[ks], bb[2], bb[3]);
            }
            #pragma unroll
            for (int half = 0; half < 2; half++) {
                const float* s = half ? s1 : s0;
                const int nt = half ? nt1 : nt0;
                int cl = nt * 8 + 2 * lr;
                int jgl = j0 + cl;
                float2 bml = __half22float2(*(const __half2*)&Bm[rb0 * BM_P + cl]);
                float2 bmh = __half22float2(*(const __half2*)&Bm[(rb0 + 8) * BM_P + cl]);
                bool v0 = jgl < NTOK, v1 = (jgl + 1) < NTOK;
                float p00 = v0 ? __expf(s[0] + bml.x - ESHIFT) : 0.f;
                float p01 = v1 ? __expf(s[1] + bml.y - ESHIFT) : 0.f;
                float p10 = v0 ? __expf(s[2] + bmh.x - ESHIFT) : 0.f;
                float p11 = v1 ? __expf(s[3] + bmh.y - ESHIFT) : 0.f;
                lsum0 += p00 + p01;
                lsum1 += p10 + p11;
                *(__half2*)&Pw[lq * P_P + cl]       = __floats2half2_rn(p00, p01);
                *(__half2*)&Pw[(lq + 8) * P_P + cl] = __floats2half2_rn(p10, p11);
            }
        }
        __syncwarp();

        // O += P * V  (ldmatrix for P (A-op) and V (B-op pairs))
        #pragma unroll
        for (int ks = 0; ks < 4; ks++) {
            const int kc = ks * 16;
            uint32_t a[4];
            ldsm4(a, &Pw[lm_row16 * P_P + kc + lm_khi]);
            uint32_t vb0[4], vb1[4];
            ldsm4(vb0, &Vs[lm_brow * VS_P + kc + lm_bk]);          // nt 0,1
            ldsm4(vb1, &Vs[(16 + lm_brow) * VS_P + kc + lm_bk]);   // nt 2,3
            mma_f16(o[0], a, vb0[0], vb0[1]);
            mma_f16(o[1], a, vb0[2], vb0[3]);
            mma_f16(o[2], a, vb1[0], vb1[1]);
            mma_f16(o[3], a, vb1[2], vb1[3]);
        }

        __syncthreads();                 // all warps done with buffer jc&1
        if (jc + 2 < 6) stage(jc + 2);   // refill it asynchronously
    }

    // epilogue
    lsum0 += __shfl_xor_sync(0xffffffffu, lsum0, 1);
    lsum0 += __shfl_xor_sync(0xffffffffu, lsum0, 2);
    lsum1 += __shfl_xor_sync(0xffffffffu, lsum1, 1);
    lsum1 += __shfl_xor_sync(0xffffffffu, lsum1, 2);
    float inv0 = 1.f / lsum0;
    float inv1 = 1.f / lsum1;

    const int ir0 = m0 + lq;
    const int ir1 = ir0 + 8;
    if (ir0 < NTOK) {
        __half* base = g_o + ((size_t)b * NTOK + ir0) * CDIM + h * HD;
        #pragma unroll
        for (int nt = 0; nt < 4; nt++)
            *(__half2*)(base + nt * 8 + 2 * lr) =
                __floats2half2_rn(o[nt][0] * inv0, o[nt][1] * inv0);
    }
    if (ir1 < NTOK) {
        __half* base = g_o + ((size_t)b * NTOK + ir1) * CDIM + h * HD;
        #pragma unroll
        for (int nt = 0; nt < 4; nt++)
            *(__half2*)(base + nt * 8 + 2 * lr) =
                __floats2half2_rn(o[nt][2] * inv1, o[nt][3] * inv1);
    }
}

// ---------------------------------------------------------------------------
// Launch
// ---------------------------------------------------------------------------
extern "C" void kernel_launch(void* const* d_in, const int* in_sizes, int n_in,
                              void* d_out, int out_size)
{
    const float* x      = (const float*)d_in[0];
    const float* mask   = (const float*)d_in[1];
    const float* qkv_w  = (const float*)d_in[2];
    const float* qkv_b  = (const float*)d_in[3];
    const float* proj_w = (const float*)d_in[4];
    const float* proj_b = (const float*)d_in[5];
    const float* bt     = (const float*)d_in[6];
    const int*   rpi    = (const int*)d_in[7];
    float* out = (float*)d_out;

    cudaFuncSetAttribute(attn_mma_kernel,
                         cudaFuncAttributeMaxDynamicSharedMemorySize,
                         ATTN_SMEM_BYTES);

    round_x_kernel<<<MROWS * CDIM / 4 / 256, 256>>>(x);
    round_wt_kernel<<<(3 * CDIM * CDIM + CDIM * CDIM) / 256, 256>>>(qkv_w, proj_w);
    bm_combine_kernel<<<dim3((NN + 255) / 256, NWIN, NHEAD), 256>>>(mask, bt, rpi);
    gemm_tc_kernel<0><<<dim3(9, 686), 256>>>(qkv_b, nullptr);
    attn_mma_kernel<<<dim3(48, NWIN, 3), 256, ATTN_SMEM_BYTES>>>();
    gemm_tc_kernel<1><<<dim3(3, 686), 256>>>(proj_b, out);
}

// round 17
// speedup vs baseline: 4.6606x; 1.0647x over previous
#include <cuda_runtime.h>
#include <cuda_fp16.h>
#include <cstdint>

// Problem constants
#define BATCH 512
#define NTOK  343
#define NP    384
#define CDIM  192
#define NHEAD 6
#define HD    32
#define NWIN  64
#define NN    (NTOK * NTOK)
#define BMP   384                  // g_bm row pitch (halves)
#define SCALE 0.17677669529663687f
#define LOG2E 1.4426950408889634f
#define QSC   (SCALE * LOG2E)      // folded q scale
#define SH    14.4269504f          // 10 * log2e (softmax shift, exact fold of old ESHIFT)
#define MROWS (BATCH * NTOK)       // 175616

// ---------------------------------------------------------------------------
// Scratch (device globals: allocation-free, zero-init)
// ---------------------------------------------------------------------------
__device__ __half g_q[BATCH * NHEAD * NTOK * HD];     // pre-scaled by SCALE*log2e
__device__ __half g_k[BATCH * NHEAD * NTOK * HD];
__device__ __half g_vt[BATCH * NHEAD * HD * NP];      // transposed, pads zero
__device__ __half g_o[BATCH * NTOK * CDIM];
__device__ __half g_bm[NWIN * NHEAD * NP * BMP];      // (bias+mask)*log2e; pads = -60000
__device__ __half g_xh[MROWS * CDIM];                 // x in half
__device__ __half g_wt[3 * CDIM * CDIM + CDIM * CDIM]; // qkv_w^T | proj_w^T

__device__ __forceinline__ void cpa16(void* smem_dst, const void* gmem_src) {
    uint32_t d = (uint32_t)__cvta_generic_to_shared(smem_dst);
    asm volatile("cp.async.cg.shared.global [%0], [%1], 16;" :: "r"(d), "l"(gmem_src));
}
__device__ __forceinline__ void cpa16z(void* smem_dst, const void* gmem_src, int sz) {
    uint32_t d = (uint32_t)__cvta_generic_to_shared(smem_dst);
    asm volatile("cp.async.cg.shared.global [%0], [%1], 16, %2;"
                 :: "r"(d), "l"(gmem_src), "r"(sz));
}
__device__ __forceinline__ void ldsm4(uint32_t r[4], const void* p) {
    uint32_t a = (uint32_t)__cvta_generic_to_shared(p);
    asm volatile("ldmatrix.sync.aligned.m8n8.x4.shared.b16 {%0,%1,%2,%3}, [%4];"
                 : "=r"(r[0]), "=r"(r[1]), "=r"(r[2]), "=r"(r[3]) : "r"(a));
}
__device__ __forceinline__ float ex2(float x) {
    float r;
    asm("ex2.approx.f32 %0, %1;" : "=f"(r) : "f"(x));
    return r;
}
__device__ __forceinline__ uint32_t packh2(float a, float b) {
    __half2 h = __floats2half2_rn(a, b);
    return *(uint32_t*)&h;
}

// fp16 MMA m16n8k16, fp32 accum (fragment layout validated R10).
__device__ __forceinline__ void mma_f16(float c[4], const uint32_t a[4],
                                        uint32_t b0, uint32_t b1) {
    asm volatile(
        "mma.sync.aligned.m16n8k16.row.col.f32.f16.f16.f32 "
        "{%0,%1,%2,%3}, {%4,%5,%6,%7}, {%8,%9}, {%0,%1,%2,%3};"
        : "+f"(c[0]), "+f"(c[1]), "+f"(c[2]), "+f"(c[3])
        : "r"(a[0]), "r"(a[1]), "r"(a[2]), "r"(a[3]), "r"(b0), "r"(b1));
}

// ---------------------------------------------------------------------------
// Prepass kernels
// ---------------------------------------------------------------------------
__global__ void round_x_kernel(const float* __restrict__ x)
{
    size_t i = (size_t)blockIdx.x * 256 + threadIdx.x;
    float4 v = ((const float4*)x)[i];
    __half2* dst = (__half2*)g_xh;
    dst[2 * i]     = __floats2half2_rn(v.x, v.y);
    dst[2 * i + 1] = __floats2half2_rn(v.z, v.w);
}
__global__ void round_wt_kernel(const float* __restrict__ qkv_w,
                                const float* __restrict__ proj_w)
{
    int idx = blockIdx.x * 256 + threadIdx.x;
    const int nq = 3 * CDIM * CDIM;
    float v;
    if (idx < nq) {
        int c = idx / CDIM, k = idx - c * CDIM;
        v = qkv_w[k * (3 * CDIM) + c];
    } else {
        int i2 = idx - nq;
        int c = i2 / CDIM, k = i2 - c * CDIM;
        v = proj_w[k * CDIM + c];
    }
    g_wt[idx] = __float2half_rn(v);
}
// bias+mask combined, scaled by log2e; ALL pad rows/cols = -60000 so that
// exp2(s + bm - SH) is exactly 0 out of range (no predicates needed downstream).
__global__ void bm_combine_kernel(const float* __restrict__ mask,
                                  const float* __restrict__ bt,
                                  const int* __restrict__ rpi)
{
    int idx = blockIdx.x * 256 + threadIdx.x;       // over NP*BMP = 147456
    int i = idx / BMP, j = idx - i * BMP;
    int w = blockIdx.y;
    int h = blockIdx.z;
    __half out;
    if (i < NTOK && j < NTOK) {
        int ij = i * NTOK + j;
        float v = (bt[rpi[ij] * NHEAD + h] + mask[(size_t)w * NN + ij]) * LOG2E;
        out = __float2half_rn(v);
    } else {
        out = __float2half_rn(-60000.0f);
    }
    g_bm[((size_t)(w * NHEAD + h) * NP + i) * BMP + j] = out;
}

// ---------------------------------------------------------------------------
// GEMM: fp16 mma, CTA 256x64, warp 64x32, K-slab 32, 3-stage cp.async,
// ldmatrix fragment loads. (q epilogue scale now includes log2e)
// ---------------------------------------------------------------------------
#define AS_P 40
#define WS_P 40
#define AS_SZ (256 * AS_P)
#define WS_SZ (64 * WS_P)

template <int MODE>
__global__ void __launch_bounds__(256, 2)
gemm_tc_kernel(const float* __restrict__ bias, float* __restrict__ Cout)
{
    const __half* A = (MODE == 0) ? g_xh : g_o;
    const __half* W = (MODE == 0) ? g_wt : (g_wt + 3 * CDIM * CDIM);

    __shared__ __align__(16) __half As[3 * AS_SZ];
    __shared__ __align__(16) __half Ws[3 * WS_SZ];

    const int tid  = threadIdx.x;
    const int w    = tid >> 5;
    const int lane = tid & 31;
    const int lq   = lane >> 2;
    const int lr   = lane & 3;
    const int wm   = w >> 1;
    const int wn   = w & 1;
    const int row0 = blockIdx.y * 256;
    const int c0   = blockIdx.x * 64;

    const int arq = tid >> 2;
    const int aq  = tid & 3;
    const int wcq = tid >> 2;
    const int wq  = tid & 3;

    const int lm_row16 = lane & 15;
    const int lm_khi   = (lane >> 4) << 3;
    const int lm_brow  = ((lane >> 4) << 3) + (lane & 7);
    const int lm_bk    = ((lane >> 3) & 1) << 3;

    float acc[4][4][4];
    #pragma unroll
    for (int mi = 0; mi < 4; mi++)
        #pragma unroll
        for (int ni = 0; ni < 4; ni++)
            #pragma unroll
            for (int r = 0; r < 4; r++) acc[mi][ni][r] = 0.f;

    auto stage = [&](int kb) {
        const int buf = kb % 3;
        const int k0 = kb * 32;
        __half* An = &As[buf * AS_SZ];
        __half* Wn = &Ws[buf * WS_SZ];
        #pragma unroll
        for (int f = 0; f < 4; f++)
            cpa16(&An[(f * 64 + arq) * AS_P + aq * 8],
                  A + (size_t)(row0 + f * 64 + arq) * CDIM + k0 + aq * 8);
        cpa16(&Wn[wcq * WS_P + wq * 8],
              W + (size_t)(c0 + wcq) * CDIM + k0 + wq * 8);
        asm volatile("cp.async.commit_group;" ::: "memory");
    };

    stage(0);
    stage(1);

    for (int kb = 0; kb < 6; kb++) {
        if (kb < 5) asm volatile("cp.async.wait_group 1;" ::: "memory");
        else        asm volatile("cp.async.wait_group 0;" ::: "memory");
        __syncthreads();
        if (kb + 2 < 6) stage(kb + 2);

        const __half* Ab = &As[(kb % 3) * AS_SZ];
        const __half* Wb = &Ws[(kb % 3) * WS_SZ];
        #pragma unroll
        for (int ks = 0; ks < 2; ks++) {
            const int kc = ks * 16;
            uint32_t bf[2][4];
            #pragma unroll
            for (int np = 0; np < 2; np++)
                ldsm4(bf[np], &Wb[(wn * 32 + np * 16 + lm_brow) * WS_P + kc + lm_bk]);
            #pragma unroll
            for (int mi = 0; mi < 4; mi++) {
                uint32_t af[4];
                ldsm4(af, &Ab[(wm * 64 + mi * 16 + lm_row16) * AS_P + kc + lm_khi]);
                mma_f16(acc[mi][0], af, bf[0][0], bf[0][1]);
                mma_f16(acc[mi][1], af, bf[0][2], bf[0][3]);
                mma_f16(acc[mi][2], af, bf[1][0], bf[1][1]);
                mma_f16(acc[mi][3], af, bf[1][2], bf[1][3]);
            }
        }
    }

    // epilogue
    #pragma unroll
    for (int mi = 0; mi < 4; mi++) {
        int rlo = row0 + wm * 64 + mi * 16 + lq;
        int rhi = rlo + 8;
        int blo = rlo / NTOK, nlo = rlo - blo * NTOK;
        int bhi = rhi / NTOK, nhi = rhi - bhi * NTOK;
        #pragma unroll
        for (int ni = 0; ni < 4; ni++) {
            int c = c0 + wn * 32 + ni * 8 + 2 * lr;
            float b0 = bias[c], b1 = bias[c + 1];
            if (MODE == 0) {
                int s   = c / CDIM;
                int rem = c - s * CDIM;
                int hh  = rem >> 5;
                int dd  = rem & 31;
                if (s == 2) {
                    __half* vlo = g_vt + (size_t)(blo * NHEAD + hh) * HD * NP;
                    __half* vhi = g_vt + (size_t)(bhi * NHEAD + hh) * HD * NP;
                    vlo[(size_t)dd * NP + nlo]       = __float2half_rn(acc[mi][ni][0] + b0);
                    vlo[(size_t)(dd + 1) * NP + nlo] = __float2half_rn(acc[mi][ni][1] + b1);
                    vhi[(size_t)dd * NP + nhi]       = __float2half_rn(acc[mi][ni][2] + b0);
                    vhi[(size_t)(dd + 1) * NP + nhi] = __float2half_rn(acc[mi][ni][3] + b1);
                } else {
                    float sc = (s == 0) ? QSC : 1.f;   // q: SCALE * log2e folded
                    __half* dst = (s == 0) ? g_q : g_k;
                    *(__half2*)&dst[((size_t)(blo * NHEAD + hh) * NTOK + nlo) * HD + dd] =
                        __floats2half2_rn((acc[mi][ni][0] + b0) * sc, (acc[mi][ni][1] + b1) * sc);
                    *(__half2*)&dst[((size_t)(bhi * NHEAD + hh) * NTOK + nhi) * HD + dd] =
                        __floats2half2_rn((acc[mi][ni][2] + b0) * sc, (acc[mi][ni][3] + b1) * sc);
                }
            } else {
                float2 vl, vh;
                vl.x = acc[mi][ni][0] + b0; vl.y = acc[mi][ni][1] + b1;
                vh.x = acc[mi][ni][2] + b0; vh.y = acc[mi][ni][3] + b1;
                *(float2*)&Cout[(size_t)rlo * CDIM + c] = vl;
                *(float2*)&Cout[(size_t)rhi * CDIM + c] = vh;
            }
        }
    }
}

// ---------------------------------------------------------------------------
// Attention: fp16 mma, double-buffered cp.async (K, VT, BM), ldmatrix frags,
// P kept in REGISTERS (softmax C-frags == PV A-frags), ex2-based softmax with
// zero predicates (OOB handled by -60000 pads in g_bm).
// smem 55 KB -> 3 CTAs/SM. Grid (48, NWIN, 3).
// ---------------------------------------------------------------------------
#define KS_P 40
#define VS_P 72
#define BM_P 72
#define KS_SZ (64 * KS_P)      // 2560
#define VS_SZ (32 * VS_P)      // 2304
#define BM_SZ (128 * BM_P)     // 9216
#define OFF_KS 0
#define OFF_VS (2 * KS_SZ)                 // 5120
#define OFF_BM (OFF_VS + 2 * VS_SZ)        // 9728
#define ATTN_SMEM_HALVES (OFF_BM + 2 * BM_SZ)   // 28160
#define ATTN_SMEM_BYTES  (ATTN_SMEM_HALVES * 2) // 56320

__global__ void __launch_bounds__(256, 3)
attn_mma_kernel()
{
    const int bg  = blockIdx.x & 7;
    const int h   = blockIdx.x >> 3;
    const int wi  = blockIdx.y;
    const int mt  = blockIdx.z;
    const int b   = wi + NWIN * bg;
    const int tid = threadIdx.x;
    const int w   = tid >> 5;
    const int lane = tid & 31;
    const int lq  = lane >> 2;
    const int lr  = lane & 3;

    extern __shared__ __half smh[];

    const int i0 = mt * 128;
    const int m0 = i0 + w * 16;
    const size_t bh = (size_t)(b * NHEAD + h);

    const __half* kgh = g_k + bh * NTOK * HD;
    const __half* vg  = g_vt + bh * HD * NP;
    const __half* bmrow = g_bm + ((size_t)(wi * NHEAD + h) * NP + i0) * BMP;

    const int lm_row16 = lane & 15;
    const int lm_khi   = (lane >> 4) << 3;
    const int lm_brow  = ((lane >> 4) << 3) + (lane & 7);
    const int lm_bk    = ((lane >> 3) & 1) << 3;

    // async stage of chunk jc into buffer jc&1 (K, VT, BM), one commit group
    auto stage = [&](int jc) {
        const int buf = jc & 1;
        const int j0 = jc * 64;
        {   // K: 64 j-rows x 32 d: 256 thr = 64 rows x 4 quads
            int jl = tid >> 2, q = tid & 3;
            int j = j0 + jl;
            const __half* src = kgh + (size_t)(j < NTOK ? j : 0) * HD + q * 8;
            cpa16z(&smh[OFF_KS + buf * KS_SZ + jl * KS_P + q * 8], src,
                   (j < NTOK) ? 16 : 0);
        }
        {   // VT: 32 d-rows x 64 j: 256 thr = 32 rows x 8 quads
            int d = tid >> 3, q = tid & 7;
            cpa16(&smh[OFF_VS + buf * VS_SZ + d * VS_P + q * 8],
                  vg + (size_t)d * NP + j0 + q * 8);
        }
        #pragma unroll
        for (int f = 0; f < 4; f++) {   // BM: 128 i-rows x 64 j: 1024 = 128 x 8
            int idx = f * 256 + tid;
            int r = idx >> 3, q = idx & 7;
            cpa16(&smh[OFF_BM + buf * BM_SZ + r * BM_P + q * 8],
                  bmrow + (size_t)r * BMP + j0 + q * 8);
        }
        asm volatile("cp.async.commit_group;" ::: "memory");
    };

    // --- load Q fragments (stage via BM region, pitch 40; before any cp.async)
    uint32_t qf[2][4];
    {
        __half* Qs = smh + OFF_BM;
        const uint4* qg = (const uint4*)(g_q + bh * NTOK * HD);
        for (int idx = tid; idx < 128 * 4; idx += 256) {
            int r = idx >> 2, q = idx & 3;
            int i = i0 + r;
            uint4 v = (i < NTOK) ? qg[i * 4 + q] : make_uint4(0, 0, 0, 0);
            *(uint4*)&Qs[r * KS_P + q * 8] = v;
        }
        __syncthreads();
        #pragma unroll
        for (int ks = 0; ks < 2; ks++)
            ldsm4(qf[ks], &Qs[(w * 16 + lm_row16) * KS_P + ks * 16 + lm_khi]);
        __syncthreads();   // done with Qs before BM staging overwrites it
    }

    float o[4][4];
    #pragma unroll
    for (int nt = 0; nt < 4; nt++)
        #pragma unroll
        for (int r = 0; r < 4; r++) o[nt][r] = 0.f;
    float lsum0 = 0.f, lsum1 = 0.f;

    stage(0);
    stage(1);

    for (int jc = 0; jc < 6; jc++) {
        if (jc < 5) asm volatile("cp.async.wait_group 1;" ::: "memory");
        else        asm volatile("cp.async.wait_group 0;" ::: "memory");
        __syncthreads();

        const int buf = jc & 1;
        const __half* Ks = smh + OFF_KS + buf * KS_SZ;
        const __half* Vs = smh + OFF_VS + buf * VS_SZ;
        const __half* Bm = smh + OFF_BM + buf * BM_SZ;
        const int rb0 = w * 16 + lq;

        // S + softmax; P packed directly into PV A-operand fragments
        uint32_t pa[4][4];
        #pragma unroll
        for (int ntp = 0; ntp < 4; ntp++) {
            float s0[4] = {0.f, 0.f, 0.f, 0.f};
            float s1[4] = {0.f, 0.f, 0.f, 0.f};
            #pragma unroll
            for (int ks = 0; ks < 2; ks++) {
                uint32_t bb[4];
                ldsm4(bb, &Ks[(ntp * 16 + lm_brow) * KS_P + ks * 16 + lm_bk]);
                mma_f16(s0, qf[ks], bb[0], bb[1]);
                mma_f16(s1, qf[ks], bb[2], bb[3]);
            }
            const int cl = ntp * 16 + 2 * lr;
            float2 bml0 = __half22float2(*(const __half2*)&Bm[rb0 * BM_P + cl]);
            float2 bmh0 = __half22float2(*(const __half2*)&Bm[(rb0 + 8) * BM_P + cl]);
            float2 bml1 = __half22float2(*(const __half2*)&Bm[rb0 * BM_P + cl + 8]);
            float2 bmh1 = __half22float2(*(const __half2*)&Bm[(rb0 + 8) * BM_P + cl + 8]);
            float p00 = ex2(s0[0] + bml0.x - SH);
            float p01 = ex2(s0[1] + bml0.y - SH);
            float p10 = ex2(s0[2] + bmh0.x - SH);
            float p11 = ex2(s0[3] + bmh0.y - SH);
            float q00 = ex2(s1[0] + bml1.x - SH);
            float q01 = ex2(s1[1] + bml1.y - SH);
            float q10 = ex2(s1[2] + bmh1.x - SH);
            float q11 = ex2(s1[3] + bmh1.y - SH);
            lsum0 += (p00 + p01) + (q00 + q01);
            lsum1 += (p10 + p11) + (q10 + q11);
            pa[ntp][0] = packh2(p00, p01);
            pa[ntp][1] = packh2(p10, p11);
            pa[ntp][2] = packh2(q00, q01);
            pa[ntp][3] = packh2(q10, q11);
        }

        // O += P * V  (P from registers; V via ldmatrix)
        #pragma unroll
        for (int ks = 0; ks < 4; ks++) {
            const int kc = ks * 16;
            uint32_t vb0[4], vb1[4];
            ldsm4(vb0, &Vs[lm_brow * VS_P + kc + lm_bk]);          // nt 0,1
            ldsm4(vb1, &Vs[(16 + lm_brow) * VS_P + kc + lm_bk]);   // nt 2,3
            mma_f16(o[0], pa[ks], vb0[0], vb0[1]);
            mma_f16(o[1], pa[ks], vb0[2], vb0[3]);
            mma_f16(o[2], pa[ks], vb1[0], vb1[1]);
            mma_f16(o[3], pa[ks], vb1[2], vb1[3]);
        }

        __syncthreads();                 // all warps done with buffer jc&1
        if (jc + 2 < 6) stage(jc + 2);   // refill asynchronously
    }

    // epilogue
    lsum0 += __shfl_xor_sync(0xffffffffu, lsum0, 1);
    lsum0 += __shfl_xor_sync(0xffffffffu, lsum0, 2);
    lsum1 += __shfl_xor_sync(0xffffffffu, lsum1, 1);
    lsum1 += __shfl_xor_sync(0xffffffffu, lsum1, 2);
    float inv0 = 1.f / lsum0;
    float inv1 = 1.f / lsum1;

    const int ir0 = m0 + lq;
    const int ir1 = ir0 + 8;
    if (ir0 < NTOK) {
        __half* base = g_o + ((size_t)b * NTOK + ir0) * CDIM + h * HD;
        #pragma unroll
        for (int nt = 0; nt < 4; nt++)
            *(__half2*)(base + nt * 8 + 2 * lr) =
                __floats2half2_rn(o[nt][0] * inv0, o[nt][1] * inv0);
    }
    if (ir1 < NTOK) {
        __half* base = g_o + ((size_t)b * NTOK + ir1) * CDIM + h * HD;
        #pragma unroll
        for (int nt = 0; nt < 4; nt++)
            *(__half2*)(base + nt * 8 + 2 * lr) =
                __floats2half2_rn(o[nt][2] * inv1, o[nt][3] * inv1);
    }
}

// ---------------------------------------------------------------------------
// Launch
// ---------------------------------------------------------------------------
extern "C" void kernel_launch(void* const* d_in, const int* in_sizes, int n_in,
                              void* d_out, int out_size)
{
    const float* x      = (const float*)d_in[0];
    const float* mask   = (const float*)d_in[1];
    const float* qkv_w  = (const float*)d_in[2];
    const float* qkv_b  = (const float*)d_in[3];
    const float* proj_w = (const float*)d_in[4];
    const float* proj_b = (const float*)d_in[5];
    const float* bt     = (const float*)d_in[6];
    const int*   rpi    = (const int*)d_in[7];
    float* out = (float*)d_out;

    cudaFuncSetAttribute(attn_mma_kernel,
                         cudaFuncAttributeMaxDynamicSharedMemorySize,
                         ATTN_SMEM_BYTES);

    round_x_kernel<<<MROWS * CDIM / 4 / 256, 256>>>(x);
    round_wt_kernel<<<(3 * CDIM * CDIM + CDIM * CDIM) / 256, 256>>>(qkv_w, proj_w);
    bm_combine_kernel<<<dim3(NP * BMP / 256, NWIN, NHEAD), 256>>>(mask, bt, rpi);
    gemm_tc_kernel<0><<<dim3(9, 686), 256>>>(qkv_b, nullptr);
    attn_mma_kernel<<<dim3(48, NWIN, 3), 256, ATTN_SMEM_BYTES>>>();
    gemm_tc_kernel<1><<<dim3(3, 686), 256>>>(proj_b, out);
}